// round 1
// baseline (speedup 1.0000x reference)
#include <cuda_runtime.h>
#include <cstdint>

// Problem constants
#define NN      16384      // N = NE*B
#define NE_     1024
#define BB      16
#define KK      64
#define TX_     768
#define OM_     511
#define DD      512
#define SLOPE_  0.3f

// -------------------- scratch (device globals; no allocs allowed) ----------
__device__ float g_NDL   [NE_ * 1536];      // [nameL | descL], row stride 1536
__device__ float g_NDPART[NE_ * OM_];       // fused name+desc part, stride 511
__device__ float g_OMICL [NN * OM_];        // act(x@omicW+b), stride 511
__device__ float g_CROSSC[NN * DD];         // cross_c = [cross_x | ko], later reused as Z2
__device__ float g_M     [NN * DD];         // gconv message buffer
__device__ float g_AGG   [NN * DD];         // gconv aggregate
__device__ float g_Z     [NN * DD];         // z
__device__ float g_PREC  [NN * DD];         // pre_c = [pre_x | ko]
__device__ float g_KO    [NN];              // ko feature column

// -------------------- generic tiled SGEMM: C = op(A @ W [+bias]) ------------
// A: [M,K] row-major stride lda; W: [K,Nc] row-major stride Nc; C stride ldc.
// flags: 1 = leaky-relu, 2 = accumulate into C, 4 = add gat[(row&1023)*511+col]
__global__ void __launch_bounds__(256, 2)
sgemm128(const float* __restrict__ A, const float* __restrict__ W,
         const float* __restrict__ bias, const float* __restrict__ gat,
         float* __restrict__ C,
         int M, int K, int Nc, int lda, int ldc, int flags)
{
    __shared__ float As[8][128];
    __shared__ float Bs[8][128];

    const int bm = blockIdx.y * 128;
    const int bn = blockIdx.x * 128;
    const int tid = threadIdx.x;
    const int tx = tid & 15;   // N-dir
    const int ty = tid >> 4;   // M-dir

    float acc[8][8];
#pragma unroll
    for (int i = 0; i < 8; i++)
#pragma unroll
        for (int j = 0; j < 8; j++) acc[i][j] = 0.f;

    for (int k0 = 0; k0 < K; k0 += 8) {
        // load A tile 128x8 (transposed into As[k][m])
        {
            int r = tid >> 1;
            int c = (tid & 1) * 4;
            int gr = bm + r;
#pragma unroll
            for (int i = 0; i < 4; i++) {
                int gc = k0 + c + i;
                As[c + i][r] = (gr < M && gc < K) ? A[(size_t)gr * lda + gc] : 0.f;
            }
        }
        // load W tile 8x128
        {
            int r = tid >> 5;
            int c = (tid & 31) * 4;
            int gr = k0 + r;
#pragma unroll
            for (int i = 0; i < 4; i++) {
                int gc = bn + c + i;
                Bs[r][c + i] = (gr < K && gc < Nc) ? W[(size_t)gr * Nc + gc] : 0.f;
            }
        }
        __syncthreads();

#pragma unroll
        for (int kk = 0; kk < 8; kk++) {
            float4 a0 = *(const float4*)&As[kk][ty * 8];
            float4 a1 = *(const float4*)&As[kk][ty * 8 + 4];
            float4 b0 = *(const float4*)&Bs[kk][tx * 8];
            float4 b1 = *(const float4*)&Bs[kk][tx * 8 + 4];
            float a[8] = {a0.x, a0.y, a0.z, a0.w, a1.x, a1.y, a1.z, a1.w};
            float b[8] = {b0.x, b0.y, b0.z, b0.w, b1.x, b1.y, b1.z, b1.w};
#pragma unroll
            for (int i = 0; i < 8; i++)
#pragma unroll
                for (int j = 0; j < 8; j++)
                    acc[i][j] = fmaf(a[i], b[j], acc[i][j]);
        }
        __syncthreads();
    }

#pragma unroll
    for (int i = 0; i < 8; i++) {
        int row = bm + ty * 8 + i;
        if (row >= M) continue;
#pragma unroll
        for (int j = 0; j < 8; j++) {
            int col = bn + tx * 8 + j;
            if (col >= Nc) continue;
            float v = acc[i][j];
            if (bias) v += bias[col];
            if (flags & 4) v += gat[(size_t)(row & (NE_ - 1)) * OM_ + col];
            if (flags & 1) v = v > 0.f ? v : SLOPE_ * v;
            size_t ci = (size_t)row * ldc + col;
            if (flags & 2) v += C[ci];
            C[ci] = v;
        }
    }
}

// -------------------- misc elementwise kernels ------------------------------
__global__ void zero_f(float* __restrict__ p, int n)
{
    int i = blockIdx.x * blockDim.x + threadIdx.x;
    if (i < n) p[i] = 0.f;
}

__global__ void set_ko(const int* __restrict__ bkm, float* __restrict__ ko)
{
    int i = blockIdx.x * blockDim.x + threadIdx.x;
    if (i < BB * KK) {
        int b = i >> 6;            // /K
        int ent = bkm[i];
        ko[b * NE_ + ent] = 1.0f;
    }
}

// PREC = [pre_x | ko]; also write CROSSC column 511 = ko
__global__ void pack_prec(const float* __restrict__ pre_x, const float* __restrict__ ko,
                          float* __restrict__ prec, float* __restrict__ crossc)
{
    int i = blockIdx.x * blockDim.x + threadIdx.x;
    if (i >= NN * DD) return;
    int r = i >> 9;
    int c = i & 511;
    float kv = ko[r];
    prec[i] = (c < OM_) ? pre_x[(size_t)r * OM_ + c] : kv;
    if (c == OM_) crossc[i] = kv;
}

// AGG = M + bias (column-broadcast over 512)
__global__ void add_bias512(const float* __restrict__ src, const float* __restrict__ bias,
                            float* __restrict__ dst, int total4)
{
    int i = blockIdx.x * blockDim.x + threadIdx.x;
    if (i >= total4) return;
    float4 v = ((const float4*)src)[i];
    float4 b = ((const float4*)bias)[i & 127];
    v.x += b.x; v.y += b.y; v.z += b.z; v.w += b.w;
    ((float4*)dst)[i] = v;
}

// Z = leaky(AGG) + x_c (x for cols<511, ko for col 511)
__global__ void z_final(const float* __restrict__ agg, const float* __restrict__ x,
                        const float* __restrict__ ko, float* __restrict__ z)
{
    int i = blockIdx.x * blockDim.x + threadIdx.x;
    if (i >= NN * DD) return;
    int r = i >> 9;
    int c = i & 511;
    float v = agg[i];
    v = v > 0.f ? v : SLOPE_ * v;
    v += (c < OM_) ? x[(size_t)r * OM_ + c] : ko[r];
    z[i] = v;
}

__global__ void leaky_k(const float* __restrict__ a, float* __restrict__ o, int total4)
{
    int i = blockIdx.x * blockDim.x + threadIdx.x;
    if (i >= total4) return;
    float4 v = ((const float4*)a)[i];
    v.x = v.x > 0.f ? v.x : SLOPE_ * v.x;
    v.y = v.y > 0.f ? v.y : SLOPE_ * v.y;
    v.z = v.z > 0.f ? v.z : SLOPE_ * v.z;
    v.w = v.w > 0.f ? v.w : SLOPE_ * v.w;
    ((float4*)o)[i] = v;
}

// segment-sum: agg[dst] += m[src] over edges. 128 threads = 128 float4 cols.
__global__ void edge_scatter(const int* __restrict__ ei, int E,
                             const float* __restrict__ m, float* __restrict__ agg)
{
    const int EPB = 8;
    int t = threadIdx.x;
    int e0 = blockIdx.x * EPB;
#pragma unroll
    for (int i = 0; i < EPB; i++) {
        int e = e0 + i;
        if (e >= E) return;
        int src = ei[e];
        int dst = ei[E + e];
        float4 v = ((const float4*)(m + (size_t)src * DD))[t];
        float* o = agg + (size_t)dst * DD + t * 4;
        atomicAdd(o + 0, v.x);
        atomicAdd(o + 1, v.y);
        atomicAdd(o + 2, v.z);
        atomicAdd(o + 3, v.w);
    }
}

// -------------------- gated readout: one block per batch element ------------
__global__ void readout_kernel(const float* __restrict__ Z2, const int* __restrict__ bkm,
                               const float* __restrict__ W1, const float* __restrict__ b1,
                               const float* __restrict__ W2, const float* __restrict__ b2,
                               const float* __restrict__ regW, const float* __restrict__ regb,
                               float* __restrict__ out)
{
    int b = blockIdx.x;
    int tid = threadIdx.x;   // 256
    __shared__ float zrow[DD];
    __shared__ float red[256];
    __shared__ float sc[KK];

    for (int k = 0; k < KK; k++) {
        size_t row = (size_t)bkm[b * KK + k] + (size_t)b * NE_;
        for (int c = tid; c < DD; c += 256) zrow[c] = Z2[row * DD + c];
        __syncthreads();
        float part = 0.f;
        for (int j = tid; j < DD; j += 256) {
            float h = b1[j];
            for (int d = 0; d < DD; d++) h = fmaf(zrow[d], W1[d * DD + j], h);
            part = fmaf(tanhf(h), W2[j], part);
        }
        red[tid] = part;
        __syncthreads();
        for (int s = 128; s > 0; s >>= 1) {
            if (tid < s) red[tid] += red[tid + s];
            __syncthreads();
        }
        if (tid == 0) sc[k] = red[0] + b2[0];
        __syncthreads();
    }

    // softmax over K
    __shared__ float wsum;
    if (tid == 0) {
        float mx = sc[0];
        for (int k = 1; k < KK; k++) mx = fmaxf(mx, sc[k]);
        float s = 0.f;
        for (int k = 0; k < KK; k++) { sc[k] = expf(sc[k] - mx); s += sc[k]; }
        wsum = s;
    }
    __syncthreads();

    // weighted readout + final regression dot
    int c0 = tid, c1 = tid + 256;
    float ro0 = 0.f, ro1 = 0.f;
    for (int k = 0; k < KK; k++) {
        size_t row = (size_t)bkm[b * KK + k] + (size_t)b * NE_;
        float w = sc[k];
        ro0 = fmaf(w, Z2[row * DD + c0], ro0);
        ro1 = fmaf(w, Z2[row * DD + c1], ro1);
    }
    float inv = 1.f / wsum;
    float part = ro0 * inv * regW[c0] + ro1 * inv * regW[c1];
    red[tid] = part;
    __syncthreads();
    for (int s = 128; s > 0; s >>= 1) {
        if (tid < s) red[tid] += red[tid + s];
        __syncthreads();
    }
    if (tid == 0) out[b] = red[0] + regb[0];
}

// -------------------- host side ---------------------------------------------
static inline dim3 gemm_grid(int M, int Nc)
{
    return dim3((Nc + 127) / 128, (M + 127) / 128);
}

extern "C" void kernel_launch(void* const* d_in, const int* in_sizes, int n_in,
                              void* d_out, int out_size)
{
    // Logical input order follows the reference dict; num_entity (idx 5) and
    // batch_size (idx 8) are python-int scalars that may or may not appear
    // as size-1 inputs. Resolve the physical index for both possibilities.
    int map_[31];
    {
        int p = 0;
        for (int l = 0; l < 31; l++) {
            if (l == 5 || l == 8) {
                // Scalar slot: present only if the next physical input has 1 elem
                // AND we still have enough inputs to be the "with scalars" layout.
                bool present = (n_in >= 30 + ((l == 5) ? 1 : 0));
                // more robust: layout w/ scalars has n_in==31
                present = (n_in == 31);
                if (present && p < n_in && in_sizes[p] == 1) map_[l] = p++;
                else map_[l] = -1;
            } else {
                map_[l] = p++;
            }
        }
    }
    auto F = [&](int l) -> const float* { return (const float*)d_in[map_[l]]; };
    auto I = [&](int l) -> const int*   { return (const int*)d_in[map_[l]]; };

    const float* x        = F(0);
    const float* pre_x    = F(1);
    const int*   edge_ei  = I(2);   // [2, 262144]
    const int*   int_ei   = I(3);   // [2, 131072]
    const float* name_emb = F(6);
    const float* desc_emb = F(7);
    const int*   bkm      = I(9);   // [B,K] entity ids
    const float* name_W = F(11), *name_b = F(12);
    const float* desc_W = F(13), *desc_b = F(14);
    const float* omic_W = F(15), *omic_b = F(16);
    const float* fus_W  = F(17), *fus_b  = F(18);
    const float* pre_W  = F(19), *pre_b  = F(20);
    const float* ienc_W = F(21), *ienc_b = F(22);
    const float* enc_W  = F(23), *enc_b  = F(24);
    const float* gate_W1 = F(25), *gate_b1 = F(26);
    const float* gate_W2 = F(27), *gate_b2 = F(28);
    const float* reg_W   = F(29), *reg_b   = F(30);
    float* out = (float*)d_out;

    const int E_full = in_sizes[map_[2]] / 2;   // 262144
    const int E_int  = in_sizes[map_[3]] / 2;   // 131072

    float *pNDL, *pNDP, *pOMI, *pCRS, *pM, *pAGG, *pZ, *pPRE, *pKO;
    cudaGetSymbolAddress((void**)&pNDL, g_NDL);
    cudaGetSymbolAddress((void**)&pNDP, g_NDPART);
    cudaGetSymbolAddress((void**)&pOMI, g_OMICL);
    cudaGetSymbolAddress((void**)&pCRS, g_CROSSC);
    cudaGetSymbolAddress((void**)&pM,   g_M);
    cudaGetSymbolAddress((void**)&pAGG, g_AGG);
    cudaGetSymbolAddress((void**)&pZ,   g_Z);
    cudaGetSymbolAddress((void**)&pPRE, g_PREC);
    cudaGetSymbolAddress((void**)&pKO,  g_KO);

    const int total  = NN * DD;          // 8388608
    const int total4 = total / 4;        // 2097152
    const int ew_blk = (total + 255) / 256;
    const int v4_blk = (total4 + 255) / 256;

    // 1) KO feature column
    zero_f<<<(NN + 255) / 256, 256>>>(pKO, NN);
    set_ko<<<(BB * KK + 255) / 256, 256>>>(bkm, pKO);

    // 2) nameL / descL / omicL (activated linears); name/desc only on NE rows
    sgemm128<<<gemm_grid(NE_, TX_), 256>>>(name_emb, name_W, name_b, nullptr,
                                           pNDL, NE_, TX_, TX_, TX_, 1536, 1);
    sgemm128<<<gemm_grid(NE_, TX_), 256>>>(desc_emb, desc_W, desc_b, nullptr,
                                           pNDL + TX_, NE_, TX_, TX_, TX_, 1536, 1);
    sgemm128<<<gemm_grid(NN, OM_), 256>>>(x, omic_W, omic_b, nullptr,
                                          pOMI, NN, OM_, OM_, OM_, OM_, 1);

    // 3) ndpart = [nameL|descL] @ fus_W[0:1536] + fus_b   (NE rows only)
    sgemm128<<<gemm_grid(NE_, OM_), 256>>>(pNDL, fus_W, fus_b, nullptr,
                                           pNDP, NE_, 1536, OM_, 1536, OM_, 0);

    // 4) pack PREC = [pre_x|ko] and CROSSC[:,511] = ko
    pack_prec<<<ew_blk, 256>>>(pre_x, pKO, pPRE, pCRS);

    // 5) cross_x = omicL @ fus_W[1536:] + ndpart[row % NE]  -> CROSSC[:,0:511]
    sgemm128<<<gemm_grid(NN, OM_), 256>>>(pOMI, fus_W + (size_t)1536 * OM_, nullptr,
                                          pNDP, pCRS, NN, OM_, OM_, OM_, DD, 4);

    // 6) gconv(ienc): M = CROSSC @ ienc_W ; AGG = M + b ; scatter ; Z = act + x_c
    sgemm128<<<gemm_grid(NN, DD), 256>>>(pCRS, ienc_W, nullptr, nullptr,
                                         pM, NN, DD, DD, DD, DD, 0);
    add_bias512<<<v4_blk, 256>>>(pM, ienc_b, pAGG, total4);
    edge_scatter<<<(E_int + 7) / 8, 128>>>(int_ei, E_int, pM, pAGG);
    z_final<<<ew_blk, 256>>>(pAGG, x, pKO, pZ);

    // 7) Z += PREC @ pre_W + pre_b
    sgemm128<<<gemm_grid(NN, DD), 256>>>(pPRE, pre_W, pre_b, nullptr,
                                         pZ, NN, DD, DD, DD, DD, 2);

    // 8) gconv(enc): M = Z @ enc_W ; AGG = M + b ; scatter ; Z2 = act  (Z2 reuses CROSSC)
    sgemm128<<<gemm_grid(NN, DD), 256>>>(pZ, enc_W, nullptr, nullptr,
                                         pM, NN, DD, DD, DD, DD, 0);
    add_bias512<<<v4_blk, 256>>>(pM, enc_b, pAGG, total4);
    edge_scatter<<<(E_full + 7) / 8, 128>>>(edge_ei, E_full, pM, pAGG);
    leaky_k<<<v4_blk, 256>>>(pAGG, pCRS, total4);

    // 9) gated readout -> out[B]
    readout_kernel<<<BB, 256>>>(pCRS, bkm, gate_W1, gate_b1, gate_W2, gate_b2,
                                reg_W, reg_b, out);

    (void)out_size;
    (void)n_in;
}

// round 2
// speedup vs baseline: 2.1370x; 2.1370x over previous
#include <cuda_runtime.h>
#include <cstdint>

// Problem constants
#define NN      16384      // N = NE*B
#define NE_     1024
#define BB      16
#define KK      64
#define TX_     768
#define OM_     511
#define DD      512
#define SLOPE_  0.3f

// -------------------- scratch (device globals; no allocs allowed) ----------
__device__ float g_NDL   [NE_ * 1536];      // [nameL | descL]; later reused: ZK | H
__device__ float g_NDPART[NE_ * OM_];       // fused name+desc part, stride 511
__device__ float g_OMICL [NN * OM_];        // act(x@omicW+b), stride 511
__device__ float g_CROSSC[NN * DD];         // cross_c = [cross_x | ko], later reused as Z2
__device__ float g_M     [NN * DD];         // gconv message buffer
__device__ float g_AGG   [NN * DD];         // gconv aggregate
__device__ float g_Z     [NN * DD];         // z
__device__ float g_PREC  [NN * DD];         // pre_c = [pre_x | ko]
__device__ float g_KO    [NN];              // ko feature column
__device__ float g_SC    [BB * KK];         // gate scores

// ============================================================================
// Big GEMM: 128x128x16 tiles, double-buffered, 256 threads, 8x8 micro-tile.
// C = op(A @ W); A [M,K] stride lda, W [K,Nc] stride Nc, C stride ldc.
// flags: 1 leaky-relu, 2 accumulate into C, 4 add gat[(row&1023)*511+col],
//        8 dual-output: C = v (raw), C2 = v + bias  (bias NOT applied to C)
// ============================================================================
#define BM 128
#define BN 128
#define BKQ 16
#define PAD 4

__global__ void __launch_bounds__(256, 2)
sgemm_db(const float* __restrict__ A, const float* __restrict__ W,
         const float* __restrict__ bias, const float* __restrict__ gat,
         float* __restrict__ C, float* __restrict__ C2,
         int M, int K, int Nc, int lda, int ldc, int flags)
{
    __shared__ float As[2][BKQ][BM + PAD];
    __shared__ float Bs[2][BKQ][BN + PAD];

    const int bm = blockIdx.y * BM;
    const int bn = blockIdx.x * BN;
    const int tid = threadIdx.x;
    const int tx = tid & 15;      // N-dir (8 cols each)
    const int ty = tid >> 4;      // M-dir (8 rows each)

    // global load mapping
    const int ac = tid & 15;      // A col within k-tile
    const int ar = tid >> 4;      // A base row (rows ar + i*16)
    const int bc = tid & 127;     // B col
    const int br = tid >> 7;      // B base row (rows br + i*2)

    float acc[8][8];
#pragma unroll
    for (int i = 0; i < 8; i++)
#pragma unroll
        for (int j = 0; j < 8; j++) acc[i][j] = 0.f;

    const int nt = (K + BKQ - 1) / BKQ;
    float ldga[8], ldgb[8];

    // prologue: load tile 0
    {
#pragma unroll
        for (int i = 0; i < 8; i++) {
            int c = ac;
            ldga[i] = (c < K) ? A[(size_t)(bm + ar + i * 16) * lda + c] : 0.f;
        }
#pragma unroll
        for (int i = 0; i < 8; i++) {
            int r = br + i * 2, c = bn + bc;
            ldgb[i] = (r < K && c < Nc) ? W[(size_t)r * Nc + c] : 0.f;
        }
#pragma unroll
        for (int i = 0; i < 8; i++) As[0][ac][ar + i * 16] = ldga[i];
#pragma unroll
        for (int i = 0; i < 8; i++) Bs[0][br + i * 2][bc] = ldgb[i];
    }
    __syncthreads();

    for (int kt = 0; kt < nt; kt++) {
        const int k0n = (kt + 1) * BKQ;
        const bool more = (kt + 1 < nt);
        if (more) {
#pragma unroll
            for (int i = 0; i < 8; i++) {
                int c = k0n + ac;
                ldga[i] = (c < K) ? A[(size_t)(bm + ar + i * 16) * lda + c] : 0.f;
            }
#pragma unroll
            for (int i = 0; i < 8; i++) {
                int r = k0n + br + i * 2, c = bn + bc;
                ldgb[i] = (r < K && c < Nc) ? W[(size_t)r * Nc + c] : 0.f;
            }
        }
        const int cur = kt & 1;
#pragma unroll
        for (int kk = 0; kk < BKQ; kk++) {
            float regA[8], regB[8];
            *(float4*)&regA[0] = *(const float4*)&As[cur][kk][ty * 8];
            *(float4*)&regA[4] = *(const float4*)&As[cur][kk][ty * 8 + 4];
            *(float4*)&regB[0] = *(const float4*)&Bs[cur][kk][tx * 8];
            *(float4*)&regB[4] = *(const float4*)&Bs[cur][kk][tx * 8 + 4];
#pragma unroll
            for (int i = 0; i < 8; i++)
#pragma unroll
                for (int j = 0; j < 8; j++)
                    acc[i][j] = fmaf(regA[i], regB[j], acc[i][j]);
        }
        if (more) {
            const int nx = cur ^ 1;
#pragma unroll
            for (int i = 0; i < 8; i++) As[nx][ac][ar + i * 16] = ldga[i];
#pragma unroll
            for (int i = 0; i < 8; i++) Bs[nx][br + i * 2][bc] = ldgb[i];
        }
        __syncthreads();
    }

    // epilogue (M is always a multiple of 128 here)
#pragma unroll
    for (int i = 0; i < 8; i++) {
        const int row = bm + ty * 8 + i;
#pragma unroll
        for (int j = 0; j < 8; j++) {
            const int col = bn + tx * 8 + j;
            if (col >= Nc) continue;
            float v = acc[i][j];
            if (flags & 4) v += gat[(size_t)(row & (NE_ - 1)) * OM_ + col];
            const size_t ci = (size_t)row * ldc + col;
            if (flags & 8) {
                C[ci]  = v;
                C2[ci] = v + bias[col];
            } else {
                if (bias) v += bias[col];
                if (flags & 1) v = v > 0.f ? v : SLOPE_ * v;
                if (flags & 2) v += C[ci];
                C[ci] = v;
            }
        }
    }
}

// ============================================================================
// Small GEMM: 64x64x16 tiles, 128 threads, 4x8 micro-tile (for small M/N).
// flags: 1 leaky-relu (bias applied if non-null)
// ============================================================================
__global__ void __launch_bounds__(128, 4)
sgemm64(const float* __restrict__ A, const float* __restrict__ W,
        const float* __restrict__ bias, float* __restrict__ C,
        int M, int K, int Nc, int lda, int ldc, int flags)
{
    __shared__ float As[2][BKQ][64 + PAD];
    __shared__ float Bs[2][BKQ][64 + PAD];

    const int bm = blockIdx.y * 64;
    const int bn = blockIdx.x * 64;
    const int tid = threadIdx.x;
    const int tx = tid & 7;       // 8 threads * 8 cols
    const int ty = tid >> 3;      // 16 threads * 4 rows

    const int ac = tid & 15;
    const int ar = tid >> 4;      // rows ar + i*8
    const int bc = tid & 63;
    const int br = tid >> 6;      // rows br + i*2

    float acc[4][8];
#pragma unroll
    for (int i = 0; i < 4; i++)
#pragma unroll
        for (int j = 0; j < 8; j++) acc[i][j] = 0.f;

    const int nt = (K + BKQ - 1) / BKQ;
    float ldga[8], ldgb[8];

    {
#pragma unroll
        for (int i = 0; i < 8; i++) {
            int c = ac;
            ldga[i] = (c < K) ? A[(size_t)(bm + ar + i * 8) * lda + c] : 0.f;
        }
#pragma unroll
        for (int i = 0; i < 8; i++) {
            int r = br + i * 2, c = bn + bc;
            ldgb[i] = (r < K && c < Nc) ? W[(size_t)r * Nc + c] : 0.f;
        }
#pragma unroll
        for (int i = 0; i < 8; i++) As[0][ac][ar + i * 8] = ldga[i];
#pragma unroll
        for (int i = 0; i < 8; i++) Bs[0][br + i * 2][bc] = ldgb[i];
    }
    __syncthreads();

    for (int kt = 0; kt < nt; kt++) {
        const int k0n = (kt + 1) * BKQ;
        const bool more = (kt + 1 < nt);
        if (more) {
#pragma unroll
            for (int i = 0; i < 8; i++) {
                int c = k0n + ac;
                ldga[i] = (c < K) ? A[(size_t)(bm + ar + i * 8) * lda + c] : 0.f;
            }
#pragma unroll
            for (int i = 0; i < 8; i++) {
                int r = k0n + br + i * 2, c = bn + bc;
                ldgb[i] = (r < K && c < Nc) ? W[(size_t)r * Nc + c] : 0.f;
            }
        }
        const int cur = kt & 1;
#pragma unroll
        for (int kk = 0; kk < BKQ; kk++) {
            float regA[4], regB[8];
            *(float4*)&regA[0] = *(const float4*)&As[cur][kk][ty * 4];
            *(float4*)&regB[0] = *(const float4*)&Bs[cur][kk][tx * 8];
            *(float4*)&regB[4] = *(const float4*)&Bs[cur][kk][tx * 8 + 4];
#pragma unroll
            for (int i = 0; i < 4; i++)
#pragma unroll
                for (int j = 0; j < 8; j++)
                    acc[i][j] = fmaf(regA[i], regB[j], acc[i][j]);
        }
        if (more) {
            const int nx = cur ^ 1;
#pragma unroll
            for (int i = 0; i < 8; i++) As[nx][ac][ar + i * 8] = ldga[i];
#pragma unroll
            for (int i = 0; i < 8; i++) Bs[nx][br + i * 2][bc] = ldgb[i];
        }
        __syncthreads();
    }

#pragma unroll
    for (int i = 0; i < 4; i++) {
        const int row = bm + ty * 4 + i;
#pragma unroll
        for (int j = 0; j < 8; j++) {
            const int col = bn + tx * 8 + j;
            if (col >= Nc) continue;
            float v = acc[i][j];
            if (bias) v += bias[col];
            if (flags & 1) v = v > 0.f ? v : SLOPE_ * v;
            C[(size_t)row * ldc + col] = v;
        }
    }
}

// -------------------- misc elementwise kernels ------------------------------
__global__ void zero_f(float* __restrict__ p, int n)
{
    int i = blockIdx.x * blockDim.x + threadIdx.x;
    if (i < n) p[i] = 0.f;
}

__global__ void set_ko(const int* __restrict__ bkm, float* __restrict__ ko)
{
    int i = blockIdx.x * blockDim.x + threadIdx.x;
    if (i < BB * KK) {
        int b = i >> 6;
        int ent = bkm[i];
        ko[b * NE_ + ent] = 1.0f;
    }
}

// PREC = [pre_x | ko]; also write CROSSC column 511 = ko
__global__ void pack_prec(const float* __restrict__ pre_x, const float* __restrict__ ko,
                          float* __restrict__ prec, float* __restrict__ crossc)
{
    int i = blockIdx.x * blockDim.x + threadIdx.x;
    if (i >= NN * DD) return;
    int r = i >> 9;
    int c = i & 511;
    float kv = ko[r];
    prec[i] = (c < OM_) ? pre_x[(size_t)r * OM_ + c] : kv;
    if (c == OM_) crossc[i] = kv;
}

// Z = leaky(AGG) + x_c (x for cols<511, ko for col 511)
__global__ void z_final(const float* __restrict__ agg, const float* __restrict__ x,
                        const float* __restrict__ ko, float* __restrict__ z)
{
    int i = blockIdx.x * blockDim.x + threadIdx.x;
    if (i >= NN * DD) return;
    int r = i >> 9;
    int c = i & 511;
    float v = agg[i];
    v = v > 0.f ? v : SLOPE_ * v;
    v += (c < OM_) ? x[(size_t)r * OM_ + c] : ko[r];
    z[i] = v;
}

__global__ void leaky_k(const float* __restrict__ a, float* __restrict__ o, int total4)
{
    int i = blockIdx.x * blockDim.x + threadIdx.x;
    if (i >= total4) return;
    float4 v = ((const float4*)a)[i];
    v.x = v.x > 0.f ? v.x : SLOPE_ * v.x;
    v.y = v.y > 0.f ? v.y : SLOPE_ * v.y;
    v.z = v.z > 0.f ? v.z : SLOPE_ * v.z;
    v.w = v.w > 0.f ? v.w : SLOPE_ * v.w;
    ((float4*)o)[i] = v;
}

// segment-sum: agg[dst] += m[src] over edges. 128 threads = 128 float4 cols.
__global__ void edge_scatter(const int* __restrict__ ei, int E,
                             const float* __restrict__ m, float* __restrict__ agg)
{
    const int EPB = 8;
    int t = threadIdx.x;
    int e0 = blockIdx.x * EPB;
#pragma unroll
    for (int i = 0; i < EPB; i++) {
        int e = e0 + i;
        if (e >= E) return;
        int src = ei[e];
        int dst = ei[E + e];
        float4 v = ((const float4*)(m + (size_t)src * DD))[t];
        float* o = agg + (size_t)dst * DD + t * 4;
        atomicAdd(o + 0, v.x);
        atomicAdd(o + 1, v.y);
        atomicAdd(o + 2, v.z);
        atomicAdd(o + 3, v.w);
    }
}

// -------------------- readout path -------------------------------------------
// gather zk rows into contiguous ZK [B*K, 512]
__global__ void gather_zk(const float* __restrict__ Z2, const int* __restrict__ bkm,
                          float* __restrict__ ZK)
{
    int i = blockIdx.x * blockDim.x + threadIdx.x;   // over 1024*128 float4
    if (i >= BB * KK * 128) return;
    int row = i >> 7, c4 = i & 127;
    int b = row >> 6;
    size_t src = (size_t)bkm[row] + (size_t)b * NE_;
    ((float4*)ZK)[(size_t)row * 128 + c4] = ((const float4*)Z2)[src * 128 + c4];
}

// sc[row] = sum_j tanh(H[row,j]) * W2[j] + b2
__global__ void tanh_dot(const float* __restrict__ H, const float* __restrict__ W2,
                         const float* __restrict__ b2, float* __restrict__ sc)
{
    int row = blockIdx.x;
    int tid = threadIdx.x;   // 128
    __shared__ float red[128];
    float p = 0.f;
    for (int j = tid; j < DD; j += 128)
        p = fmaf(tanhf(H[(size_t)row * DD + j]), W2[j], p);
    red[tid] = p;
    __syncthreads();
    for (int s = 64; s > 0; s >>= 1) {
        if (tid < s) red[tid] += red[tid + s];
        __syncthreads();
    }
    if (tid == 0) sc[row] = red[0] + b2[0];
}

// per-batch softmax over K, weighted readout, regression dot
__global__ void readout2(const float* __restrict__ ZK, const float* __restrict__ sc,
                         const float* __restrict__ regW, const float* __restrict__ regb,
                         float* __restrict__ out)
{
    int b = blockIdx.x;
    int tid = threadIdx.x;   // 256
    __shared__ float w[KK];
    __shared__ float red[256];
    __shared__ float sm;
    if (tid < KK) w[tid] = sc[b * KK + tid];
    __syncthreads();
    if (tid == 0) {
        float m = w[0];
        for (int k = 1; k < KK; k++) m = fmaxf(m, w[k]);
        float s = 0.f;
        for (int k = 0; k < KK; k++) { w[k] = expf(w[k] - m); s += w[k]; }
        sm = s;
    }
    __syncthreads();
    int c0 = tid, c1 = tid + 256;
    float r0 = 0.f, r1 = 0.f;
    for (int k = 0; k < KK; k++) {
        const float* z = ZK + ((size_t)b * KK + k) * DD;
        float wk = w[k];
        r0 = fmaf(wk, z[c0], r0);
        r1 = fmaf(wk, z[c1], r1);
    }
    float part = (r0 * regW[c0] + r1 * regW[c1]) / sm;
    red[tid] = part;
    __syncthreads();
    for (int s = 128; s > 0; s >>= 1) {
        if (tid < s) red[tid] += red[tid + s];
        __syncthreads();
    }
    if (tid == 0) out[b] = red[0] + regb[0];
}

// -------------------- host side ---------------------------------------------
static inline dim3 grid128(int M, int Nc) { return dim3((Nc + 127) / 128, (M + 127) / 128); }
static inline dim3 grid64(int M, int Nc)  { return dim3((Nc + 63) / 64, (M + 63) / 64); }

extern "C" void kernel_launch(void* const* d_in, const int* in_sizes, int n_in,
                              void* d_out, int out_size)
{
    int map_[31];
    {
        int p = 0;
        for (int l = 0; l < 31; l++) {
            if (l == 5 || l == 8) {
                bool present = (n_in == 31);
                if (present && p < n_in && in_sizes[p] == 1) map_[l] = p++;
                else map_[l] = -1;
            } else {
                map_[l] = p++;
            }
        }
    }
    auto F = [&](int l) -> const float* { return (const float*)d_in[map_[l]]; };
    auto I = [&](int l) -> const int*   { return (const int*)d_in[map_[l]]; };

    const float* x        = F(0);
    const float* pre_x    = F(1);
    const int*   edge_ei  = I(2);
    const int*   int_ei   = I(3);
    const float* name_emb = F(6);
    const float* desc_emb = F(7);
    const int*   bkm      = I(9);
    const float* name_W = F(11), *name_b = F(12);
    const float* desc_W = F(13), *desc_b = F(14);
    const float* omic_W = F(15), *omic_b = F(16);
    const float* fus_W  = F(17), *fus_b  = F(18);
    const float* pre_W  = F(19), *pre_b  = F(20);
    const float* ienc_W = F(21), *ienc_b = F(22);
    const float* enc_W  = F(23), *enc_b  = F(24);
    const float* gate_W1 = F(25), *gate_b1 = F(26);
    const float* gate_W2 = F(27), *gate_b2 = F(28);
    const float* reg_W   = F(29), *reg_b   = F(30);
    float* out = (float*)d_out;

    const int E_full = in_sizes[map_[2]] / 2;
    const int E_int  = in_sizes[map_[3]] / 2;

    float *pNDL, *pNDP, *pOMI, *pCRS, *pM, *pAGG, *pZ, *pPRE, *pKO, *pSC;
    cudaGetSymbolAddress((void**)&pNDL, g_NDL);
    cudaGetSymbolAddress((void**)&pNDP, g_NDPART);
    cudaGetSymbolAddress((void**)&pOMI, g_OMICL);
    cudaGetSymbolAddress((void**)&pCRS, g_CROSSC);
    cudaGetSymbolAddress((void**)&pM,   g_M);
    cudaGetSymbolAddress((void**)&pAGG, g_AGG);
    cudaGetSymbolAddress((void**)&pZ,   g_Z);
    cudaGetSymbolAddress((void**)&pPRE, g_PREC);
    cudaGetSymbolAddress((void**)&pKO,  g_KO);
    cudaGetSymbolAddress((void**)&pSC,  g_SC);

    const int total  = NN * DD;
    const int total4 = total / 4;
    const int ew_blk = (total + 255) / 256;
    const int v4_blk = (total4 + 255) / 256;

    // 1) KO feature column
    zero_f<<<(NN + 255) / 256, 256>>>(pKO, NN);
    set_ko<<<(BB * KK + 255) / 256, 256>>>(bkm, pKO);

    // 2) name/desc linears on NE rows only (64-tile for SM fill); omic on big tile
    sgemm64<<<grid64(NE_, TX_), 128>>>(name_emb, name_W, name_b, pNDL,
                                       NE_, TX_, TX_, TX_, 1536, 1);
    sgemm64<<<grid64(NE_, TX_), 128>>>(desc_emb, desc_W, desc_b, pNDL + TX_,
                                       NE_, TX_, TX_, TX_, 1536, 1);
    sgemm_db<<<grid128(NN, OM_), 256>>>(x, omic_W, omic_b, nullptr,
                                        pOMI, nullptr, NN, OM_, OM_, OM_, OM_, 1);

    // 3) ndpart = [nameL|descL] @ fus_W[0:1536] + fus_b   (NE rows only)
    sgemm64<<<grid64(NE_, OM_), 128>>>(pNDL, fus_W, fus_b, pNDP,
                                       NE_, 1536, OM_, 1536, OM_, 0);

    // 4) pack PREC = [pre_x|ko] and CROSSC[:,511] = ko
    pack_prec<<<ew_blk, 256>>>(pre_x, pKO, pPRE, pCRS);

    // 5) cross_x = omicL @ fus_W[1536:] + ndpart[row % NE]  -> CROSSC[:,0:511]
    sgemm_db<<<grid128(NN, OM_), 256>>>(pOMI, fus_W + (size_t)1536 * OM_, nullptr,
                                        pNDP, pCRS, nullptr, NN, OM_, OM_, OM_, DD, 4);

    // 6) gconv(ienc): M = CROSSC @ ienc_W (raw), AGG = M + b ; scatter ; Z = act + x_c
    sgemm_db<<<grid128(NN, DD), 256>>>(pCRS, ienc_W, ienc_b, nullptr,
                                       pM, pAGG, NN, DD, DD, DD, DD, 8);
    edge_scatter<<<(E_int + 7) / 8, 128>>>(int_ei, E_int, pM, pAGG);
    z_final<<<ew_blk, 256>>>(pAGG, x, pKO, pZ);

    // 7) Z += PREC @ pre_W + pre_b
    sgemm_db<<<grid128(NN, DD), 256>>>(pPRE, pre_W, pre_b, nullptr,
                                       pZ, nullptr, NN, DD, DD, DD, DD, 2);

    // 8) gconv(enc): M = Z @ enc_W (raw), AGG = M + b ; scatter ; Z2 = act
    sgemm_db<<<grid128(NN, DD), 256>>>(pZ, enc_W, enc_b, nullptr,
                                       pM, pAGG, NN, DD, DD, DD, DD, 8);
    edge_scatter<<<(E_full + 7) / 8, 128>>>(edge_ei, E_full, pM, pAGG);
    leaky_k<<<v4_blk, 256>>>(pAGG, pCRS, total4);   // Z2 in pCRS

    // 9) readout: gather zk, H = zk@W1+b1 (GEMM), tanh·W2 reduce, softmax+reg
    float* pZK = pNDL;                 // 1024*512 (NDL is free now)
    float* pH  = pNDL + NE_ * DD;      // 1024*512
    gather_zk<<<(BB * KK * 128 + 255) / 256, 256>>>(pCRS, bkm, pZK);
    sgemm64<<<grid64(BB * KK, DD), 128>>>(pZK, gate_W1, gate_b1, pH,
                                          BB * KK, DD, DD, DD, DD, 0);
    tanh_dot<<<BB * KK, 128>>>(pH, gate_W2, gate_b2, pSC);
    readout2<<<BB, 256>>>(pZK, pSC, reg_W, reg_b, out);

    (void)out_size;
    (void)n_in;
}

// round 4
// speedup vs baseline: 4.3839x; 2.0515x over previous
#include <cuda_runtime.h>
#include <cuda_bf16.h>
#include <cstdint>

#define NN      16384
#define NE_     1024
#define BB      16
#define KK      64
#define TX_     768
#define OM_     511
#define DD      512
#define SLOPE_  0.3f

// ------------------------- helpers ------------------------------------------
__device__ __forceinline__ uint32_t smem_to_u32(const void* p) {
    uint32_t a;
    asm("{ .reg .u64 t; cvta.to.shared.u64 t, %1; cvt.u32.u64 %0, t; }"
        : "=r"(a) : "l"(p));
    return a;
}

#define CP_ASYNC16(saddr, gptr) \
    asm volatile("cp.async.cg.shared.global [%0], [%1], 16;" \
                 :: "r"(saddr), "l"(gptr) : "memory")

#define LDMX4(r0, r1, r2, r3, addr) \
    asm volatile("ldmatrix.sync.aligned.m8n8.x4.shared.b16 {%0,%1,%2,%3}, [%4];" \
                 : "=r"(r0), "=r"(r1), "=r"(r2), "=r"(r3) : "r"(addr))

#define MMA16816(c, a, b) \
    asm volatile("mma.sync.aligned.m16n8k16.row.col.f32.bf16.bf16.f32 " \
                 "{%0,%1,%2,%3},{%4,%5,%6,%7},{%8,%9},{%0,%1,%2,%3};" \
                 : "+f"((c)[0]), "+f"((c)[1]), "+f"((c)[2]), "+f"((c)[3]) \
                 : "r"((a)[0]), "r"((a)[1]), "r"((a)[2]), "r"((a)[3]), \
                   "r"((b)[0]), "r"((b)[1]))

// ------------------------- scratch (device globals) -------------------------
__device__ __nv_bfloat16 g_AH[NN * DD];        // split A (hi)
__device__ __nv_bfloat16 g_AL[NN * DD];        // split A (lo)
__device__ __nv_bfloat16 g_PH[NN * DD];        // PREC split (hi)
__device__ __nv_bfloat16 g_PL[NN * DD];        // PREC split (lo)
__device__ __nv_bfloat16 g_WH[1536 * 1536];    // W^T split (hi)
__device__ __nv_bfloat16 g_WL[1536 * 1536];    // W^T split (lo)
__device__ float g_NDL   [NE_ * 1536];         // [nameL|descL]; later ZK | H
__device__ float g_NDPART[NE_ * DD];           // fused name+desc part (stride 512)
__device__ float g_OMICL [NN * DD];            // act(x@omicW+b) (stride 512)
__device__ float g_CROSSC[NN * DD];            // cross_c; later Z2
__device__ float g_M     [NN * DD];            // gconv message buffer
__device__ float g_Z     [NN * DD];            // z
__device__ float g_KO    [NN];
__device__ float g_SC    [BB * KK];
__device__ int   g_CNT[NN];
__device__ int   g_OFF[NN];
__device__ int   g_CUR[NN];
__device__ int   g_SRT[262144];

// ============================================================================
// HMMA split-bf16 GEMM.  C[M,Nc] = epilogue(A @ B^T), fp32 accumulate.
// A split: Ah/Al [M, lda_b] bf16 (K padded to lda_b, zeros)
// B split: Bh/Bl [Npad, ldb_b] bf16 (K-major = W^T, zero padded)
// Computes Ah*Bh + Ah*Bl + Al*Bh (drops Al*Bl, ~2^-18).
// flags: 1 leaky, 2 accumulate (+Cin), 4 add gat[(row&1023)*512+col]
// CTA: 128x128 tile, BK=32, 256 threads, 8 warps each 64x32.
// smem per stage: 4 matrices x 128 rows x 40 bf16 (stride-40 pad) = 40KB.
// ============================================================================
__global__ void __launch_bounds__(256, 1)
hgemm(const __nv_bfloat16* __restrict__ Ah, const __nv_bfloat16* __restrict__ Al,
      const __nv_bfloat16* __restrict__ Bh, const __nv_bfloat16* __restrict__ Bl,
      const float* __restrict__ bias, const float* __restrict__ gat,
      const float* __restrict__ Cin, float* __restrict__ C,
      int lda_b, int ldb_b, int nchunks, int Nc, int ldc, int flags)
{
    extern __shared__ char smem[];
    const uint32_t sb = smem_to_u32(smem);
    const int tid  = threadIdx.x;
    const int lane = tid & 31;
    const int wid  = tid >> 5;
    const int wm   = (wid >> 2) * 64;   // warp m-offset (0/64)
    const int wn   = (wid & 3) * 32;    // warp n-offset (0/32/64/96)
    const int bm   = blockIdx.y * 128;
    const int bn   = blockIdx.x * 128;

    float acc[4][4][4];
#pragma unroll
    for (int i = 0; i < 4; i++)
#pragma unroll
        for (int j = 0; j < 4; j++)
#pragma unroll
            for (int q = 0; q < 4; q++) acc[i][j][q] = 0.f;

    // ---- async stage loader: 4 matrices, 128x32 bf16 each, stride 40 ----
    auto load_stage = [&](int st, int k0) {
        const uint32_t base = sb + st * 40960;
#pragma unroll
        for (int i = 0; i < 2; i++) {
            const int idx = tid + i * 256;      // 0..511
            const int row = idx >> 2;
            const int c16 = idx & 3;
            const uint32_t so = base + row * 80 + c16 * 16;
            const size_t ga = (size_t)(bm + row) * lda_b + k0 + c16 * 8;
            const size_t gb = (size_t)(bn + row) * ldb_b + k0 + c16 * 8;
            CP_ASYNC16(so,          Ah + ga);
            CP_ASYNC16(so + 10240,  Al + ga);
            CP_ASYNC16(so + 20480,  Bh + gb);
            CP_ASYNC16(so + 30720,  Bl + gb);
        }
        asm volatile("cp.async.commit_group;" ::: "memory");
    };

    // ---- per-chunk compute ----
    auto compute = [&](int st) {
        const uint32_t base = sb + st * 40960;
        const int arow = lane & 15;
        const int asub = (lane >> 4) * 8;
        const int brow = (lane & 7) + (lane >> 4) * 8;
        const int bsub = ((lane >> 3) & 1) * 8;
#pragma unroll
        for (int ks = 0; ks < 2; ks++) {
            const int kb = ks * 16;
            const uint32_t a0 = base + ((wm + arow) * 40 + kb + asub) * 2;
            const uint32_t b0 = base + 20480 + ((wn + brow) * 40 + kb + bsub) * 2;

            uint32_t ah[4][4], al_[4][4], bh[4][2], bl_[4][2];
#pragma unroll
            for (int mt = 0; mt < 4; mt++)
                LDMX4(ah[mt][0], ah[mt][1], ah[mt][2], ah[mt][3], a0 + mt * 16 * 80);
#pragma unroll
            for (int p = 0; p < 2; p++)
                LDMX4(bh[2*p][0], bh[2*p][1], bh[2*p+1][0], bh[2*p+1][1],
                      b0 + p * 16 * 80);
#pragma unroll
            for (int mt = 0; mt < 4; mt++)
#pragma unroll
                for (int nt = 0; nt < 4; nt++)
                    MMA16816(acc[mt][nt], ah[mt], bh[nt]);

#pragma unroll
            for (int p = 0; p < 2; p++)
                LDMX4(bl_[2*p][0], bl_[2*p][1], bl_[2*p+1][0], bl_[2*p+1][1],
                      b0 + 10240 + p * 16 * 80);
#pragma unroll
            for (int mt = 0; mt < 4; mt++)
#pragma unroll
                for (int nt = 0; nt < 4; nt++)
                    MMA16816(acc[mt][nt], ah[mt], bl_[nt]);

#pragma unroll
            for (int mt = 0; mt < 4; mt++)
                LDMX4(al_[mt][0], al_[mt][1], al_[mt][2], al_[mt][3],
                      a0 + 10240 + mt * 16 * 80);
#pragma unroll
            for (int mt = 0; mt < 4; mt++)
#pragma unroll
                for (int nt = 0; nt < 4; nt++)
                    MMA16816(acc[mt][nt], al_[mt], bh[nt]);
        }
    };

    // ---- pipelined main loop ----
    load_stage(0, 0);
    for (int c = 0; c < nchunks; c++) {
        if (c + 1 < nchunks) {
            load_stage((c + 1) & 1, (c + 1) * 32);
            asm volatile("cp.async.wait_group 1;" ::: "memory");
        } else {
            asm volatile("cp.async.wait_group 0;" ::: "memory");
        }
        __syncthreads();
        compute(c & 1);
        __syncthreads();
    }

    // ---- epilogue ----
    const int er = lane >> 2;
    const int ec = (lane & 3) * 2;
#pragma unroll
    for (int mt = 0; mt < 4; mt++) {
#pragma unroll
        for (int h = 0; h < 2; h++) {
            const int row = bm + wm + mt * 16 + er + h * 8;
            const size_t crow = (size_t)row * ldc;
            const size_t grow = (size_t)(row & (NE_ - 1)) * 512;
#pragma unroll
            for (int nt = 0; nt < 4; nt++) {
                const int col = bn + wn + nt * 8 + ec;
                float v0 = acc[mt][nt][h * 2 + 0];
                float v1 = acc[mt][nt][h * 2 + 1];
                if (col + 1 < Nc) {
                    if (bias)      { v0 += bias[col];       v1 += bias[col + 1]; }
                    if (flags & 4) { v0 += gat[grow + col]; v1 += gat[grow + col + 1]; }
                    if (flags & 1) {
                        v0 = v0 > 0.f ? v0 : SLOPE_ * v0;
                        v1 = v1 > 0.f ? v1 : SLOPE_ * v1;
                    }
                    if (flags & 2) {
                        float2 ci = *reinterpret_cast<const float2*>(Cin + crow + col);
                        v0 += ci.x; v1 += ci.y;
                    }
                    *reinterpret_cast<float2*>(C + crow + col) = make_float2(v0, v1);
                } else {
                    float vv[2] = {v0, v1};
#pragma unroll
                    for (int q = 0; q < 2; q++) {
                        const int cq = col + q;
                        if (cq >= Nc) continue;
                        float v = vv[q];
                        if (bias)      v += bias[cq];
                        if (flags & 4) v += gat[grow + cq];
                        if (flags & 1) v = v > 0.f ? v : SLOPE_ * v;
                        if (flags & 2) v += Cin[crow + cq];
                        C[crow + cq] = v;
                    }
                }
            }
        }
    }
}

// ------------------------- conversion kernels -------------------------------
__global__ void cvt_splitA(const float* __restrict__ A, int M, int K, int lda, int ldo,
                           __nv_bfloat16* __restrict__ Ah, __nv_bfloat16* __restrict__ Al)
{
    int i = blockIdx.x * blockDim.x + threadIdx.x;
    int half = ldo >> 1;
    int r = i / half;
    if (r >= M) return;
    int c2 = (i - r * half) * 2;
    float v0 = (c2 < K)     ? A[(size_t)r * lda + c2]     : 0.f;
    float v1 = (c2 + 1 < K) ? A[(size_t)r * lda + c2 + 1] : 0.f;
    __nv_bfloat16 h0 = __float2bfloat16(v0), h1 = __float2bfloat16(v1);
    __nv_bfloat16 l0 = __float2bfloat16(v0 - __bfloat162float(h0));
    __nv_bfloat16 l1 = __float2bfloat16(v1 - __bfloat162float(h1));
    __nv_bfloat162 hh; hh.x = h0; hh.y = h1;
    __nv_bfloat162 ll; ll.x = l0; ll.y = l1;
    *reinterpret_cast<__nv_bfloat162*>(Ah + (size_t)r * ldo + c2) = hh;
    *reinterpret_cast<__nv_bfloat162*>(Al + (size_t)r * ldo + c2) = ll;
}

// W [K,N] (stride ldw) -> W^T split bf16 [Npad, ldo] (zero padded)
__global__ void cvt_splitWt(const float* __restrict__ W, int K, int N, int ldw,
                            int ldo, int Npad,
                            __nv_bfloat16* __restrict__ Wh, __nv_bfloat16* __restrict__ Wl)
{
    int i = blockIdx.x * blockDim.x + threadIdx.x;
    int n = i / ldo;
    if (n >= Npad) return;
    int k = i - n * ldo;
    float v = (n < N && k < K) ? W[(size_t)k * ldw + n] : 0.f;
    __nv_bfloat16 h = __float2bfloat16(v);
    __nv_bfloat16 l = __float2bfloat16(v - __bfloat162float(h));
    Wh[(size_t)n * ldo + k] = h;
    Wl[(size_t)n * ldo + k] = l;
}

// PREC = [pre_x | ko] directly to split bf16; also CROSSC[:,511] = ko
__global__ void pack_prec_bf(const float* __restrict__ pre_x, const float* __restrict__ ko,
                             __nv_bfloat16* __restrict__ Ph, __nv_bfloat16* __restrict__ Pl,
                             float* __restrict__ crossc)
{
    int i = blockIdx.x * blockDim.x + threadIdx.x;   // NN * 256
    if (i >= NN * 256) return;
    int r = i >> 8;
    int c2 = (i & 255) * 2;
    float kv = ko[r];
    float v0 = (c2 < OM_)     ? pre_x[(size_t)r * OM_ + c2]     : kv;
    float v1 = (c2 + 1 < OM_) ? pre_x[(size_t)r * OM_ + c2 + 1] : kv;
    __nv_bfloat16 h0 = __float2bfloat16(v0), h1 = __float2bfloat16(v1);
    __nv_bfloat16 l0 = __float2bfloat16(v0 - __bfloat162float(h0));
    __nv_bfloat16 l1 = __float2bfloat16(v1 - __bfloat162float(h1));
    __nv_bfloat162 hh; hh.x = h0; hh.y = h1;
    __nv_bfloat162 ll; ll.x = l0; ll.y = l1;
    *reinterpret_cast<__nv_bfloat162*>(Ph + (size_t)r * DD + c2) = hh;
    *reinterpret_cast<__nv_bfloat162*>(Pl + (size_t)r * DD + c2) = ll;
    if (c2 == 510) crossc[(size_t)r * DD + OM_] = kv;
}

// ------------------------- misc ----------------------------------------------
__global__ void zero_f(float* __restrict__ p, int n)
{ int i = blockIdx.x * blockDim.x + threadIdx.x; if (i < n) p[i] = 0.f; }
__global__ void zero_i(int* __restrict__ p, int n)
{ int i = blockIdx.x * blockDim.x + threadIdx.x; if (i < n) p[i] = 0; }

__global__ void set_ko(const int* __restrict__ bkm, float* __restrict__ ko)
{
    int i = blockIdx.x * blockDim.x + threadIdx.x;
    if (i < BB * KK) ko[(i >> 6) * NE_ + bkm[i]] = 1.0f;
}

// ------------------------- CSR build -----------------------------------------
__global__ void csr_count(const int* __restrict__ ei, int E, int* __restrict__ cnt)
{
    int i = blockIdx.x * blockDim.x + threadIdx.x;
    if (i < E) atomicAdd(&cnt[ei[E + i]], 1);
}

__global__ void __launch_bounds__(1024, 1)
csr_scan(const int* __restrict__ cnt, int* __restrict__ off, int* __restrict__ cur)
{
    __shared__ int sa[1024], sbuf[1024];
    int t = threadIdx.x;
    int base = t * 16;
    int loc[16];
    int s = 0;
#pragma unroll
    for (int j = 0; j < 16; j++) { loc[j] = cnt[base + j]; s += loc[j]; }
    sa[t] = s;
    __syncthreads();
    int* A = sa; int* Bf = sbuf;
    for (int d = 1; d < 1024; d <<= 1) {
        int v = A[t] + (t >= d ? A[t - d] : 0);
        __syncthreads();
        Bf[t] = v;
        __syncthreads();
        int* tmp = A; A = Bf; Bf = tmp;
    }
    int run = t ? A[t - 1] : 0;
#pragma unroll
    for (int j = 0; j < 16; j++) { off[base + j] = run; cur[base + j] = run; run += loc[j]; }
}

__global__ void csr_fill(const int* __restrict__ ei, int E,
                         int* __restrict__ cur, int* __restrict__ srt)
{
    int i = blockIdx.x * blockDim.x + threadIdx.x;
    if (i < E) {
        int p = atomicAdd(&cur[ei[E + i]], 1);
        srt[p] = ei[i];
    }
}

// gconv aggregate + epilogue.  mode 0: out = leaky(acc)+x_c -> Z ; mode 1: out = leaky(acc)
__global__ void __launch_bounds__(128, 8)
gconv_gather(const float* __restrict__ m, const float* __restrict__ bias,
             const int* __restrict__ off, const int* __restrict__ cnt,
             const int* __restrict__ srt,
             const float* __restrict__ x, const float* __restrict__ ko,
             float* __restrict__ out, int mode)
{
    const int r = blockIdx.x;
    const int t = threadIdx.x;
    float4 acc = reinterpret_cast<const float4*>(m + (size_t)r * DD)[t];
    float4 b   = reinterpret_cast<const float4*>(bias)[t];
    acc.x += b.x; acc.y += b.y; acc.z += b.z; acc.w += b.w;
    const int s0 = off[r];
    const int d  = cnt[r];
    for (int e = 0; e < d; e++) {
        int s = srt[s0 + e];
        float4 v = reinterpret_cast<const float4*>(m + (size_t)s * DD)[t];
        acc.x += v.x; acc.y += v.y; acc.z += v.z; acc.w += v.w;
    }
    acc.x = acc.x > 0.f ? acc.x : SLOPE_ * acc.x;
    acc.y = acc.y > 0.f ? acc.y : SLOPE_ * acc.y;
    acc.z = acc.z > 0.f ? acc.z : SLOPE_ * acc.z;
    acc.w = acc.w > 0.f ? acc.w : SLOPE_ * acc.w;
    if (mode == 0) {
        const int c0 = t * 4;
        float add[4];
#pragma unroll
        for (int q = 0; q < 4; q++) {
            int c = c0 + q;
            add[q] = (c < OM_) ? x[(size_t)r * OM_ + c] : ko[r];
        }
        acc.x += add[0]; acc.y += add[1]; acc.z += add[2]; acc.w += add[3];
    }
    reinterpret_cast<float4*>(out + (size_t)r * DD)[t] = acc;
}

// ------------------------- readout -------------------------------------------
__global__ void gather_zk(const float* __restrict__ Z2, const int* __restrict__ bkm,
                          float* __restrict__ ZK)
{
    int i = blockIdx.x * blockDim.x + threadIdx.x;
    if (i >= BB * KK * 128) return;
    int row = i >> 7, c4 = i & 127;
    int b = row >> 6;
    size_t src = (size_t)bkm[row] + (size_t)b * NE_;
    reinterpret_cast<float4*>(ZK)[(size_t)row * 128 + c4] =
        reinterpret_cast<const float4*>(Z2)[src * 128 + c4];
}

__global__ void tanh_dot(const float* __restrict__ H, const float* __restrict__ W2,
                         const float* __restrict__ b2, float* __restrict__ sc)
{
    int row = blockIdx.x;
    int tid = threadIdx.x;   // 128
    __shared__ float red[128];
    float p = 0.f;
    for (int j = tid; j < DD; j += 128)
        p = fmaf(tanhf(H[(size_t)row * DD + j]), W2[j], p);
    red[tid] = p;
    __syncthreads();
    for (int s = 64; s > 0; s >>= 1) {
        if (tid < s) red[tid] += red[tid + s];
        __syncthreads();
    }
    if (tid == 0) sc[row] = red[0] + b2[0];
}

__global__ void readout2(const float* __restrict__ ZK, const float* __restrict__ sc,
                         const float* __restrict__ regW, const float* __restrict__ regb,
                         float* __restrict__ out)
{
    int b = blockIdx.x;
    int tid = threadIdx.x;   // 256
    __shared__ float w[KK];
    __shared__ float red[256];
    __shared__ float sm;
    if (tid < KK) w[tid] = sc[b * KK + tid];
    __syncthreads();
    if (tid == 0) {
        float m = w[0];
        for (int k = 1; k < KK; k++) m = fmaxf(m, w[k]);
        float s = 0.f;
        for (int k = 0; k < KK; k++) { w[k] = expf(w[k] - m); s += w[k]; }
        sm = s;
    }
    __syncthreads();
    int c0 = tid, c1 = tid + 256;
    float r0 = 0.f, r1 = 0.f;
    for (int k = 0; k < KK; k++) {
        const float* z = ZK + ((size_t)b * KK + k) * DD;
        float wk = w[k];
        r0 = fmaf(wk, z[c0], r0);
        r1 = fmaf(wk, z[c1], r1);
    }
    float part = (r0 * regW[c0] + r1 * regW[c1]) / sm;
    red[tid] = part;
    __syncthreads();
    for (int s = 128; s > 0; s >>= 1) {
        if (tid < s) red[tid] += red[tid + s];
        __syncthreads();
    }
    if (tid == 0) out[b] = red[0] + regb[0];
}

// ------------------------- host side ------------------------------------------
static const int HG_SMEM = 2 * 40960;   // 81920 bytes

static inline void launch_hgemm(const __nv_bfloat16* Ah, const __nv_bfloat16* Al,
                                const __nv_bfloat16* Bh, const __nv_bfloat16* Bl,
                                const float* bias, const float* gat,
                                const float* Cin, float* C,
                                int M, int lda_b, int ldb_b, int nchunks,
                                int Nc, int Npad, int ldc, int flags)
{
    dim3 grid(Npad / 128, M / 128);
    hgemm<<<grid, 256, HG_SMEM>>>(Ah, Al, Bh, Bl, bias, gat, Cin, C,
                                  lda_b, ldb_b, nchunks, Nc, ldc, flags);
}

extern "C" void kernel_launch(void* const* d_in, const int* in_sizes, int n_in,
                              void* d_out, int out_size)
{
    int map_[31];
    {
        int p = 0;
        for (int l = 0; l < 31; l++) {
            if (l == 5 || l == 8) {
                bool present = (n_in == 31);
                if (present && p < n_in && in_sizes[p] == 1) map_[l] = p++;
                else map_[l] = -1;
            } else map_[l] = p++;
        }
    }
    auto F = [&](int l) -> const float* { return (const float*)d_in[map_[l]]; };
    auto I = [&](int l) -> const int*   { return (const int*)d_in[map_[l]]; };

    const float* x        = F(0);
    const float* pre_x    = F(1);
    const int*   edge_ei  = I(2);
    const int*   int_ei   = I(3);
    const float* name_emb = F(6);
    const float* desc_emb = F(7);
    const int*   bkm      = I(9);
    const float* name_W = F(11), *name_b = F(12);
    const float* desc_W = F(13), *desc_b = F(14);
    const float* omic_W = F(15), *omic_b = F(16);
    const float* fus_W  = F(17), *fus_b  = F(18);
    const float* pre_W  = F(19), *pre_b  = F(20);
    const float* ienc_W = F(21), *ienc_b = F(22);
    const float* enc_W  = F(23), *enc_b  = F(24);
    const float* gate_W1 = F(25), *gate_b1 = F(26);
    const float* gate_W2 = F(27), *gate_b2 = F(28);
    const float* reg_W   = F(29), *reg_b   = F(30);
    float* out = (float*)d_out;

    const int E_full = in_sizes[map_[2]] / 2;
    const int E_int  = in_sizes[map_[3]] / 2;

    __nv_bfloat16 *pAH, *pAL, *pPH, *pPL, *pWH, *pWL;
    float *pNDL, *pNDP, *pOMI, *pCRS, *pM, *pZ, *pKO, *pSC;
    int *pCNT, *pOFF, *pCUR, *pSRT;
    cudaGetSymbolAddress((void**)&pAH, g_AH);
    cudaGetSymbolAddress((void**)&pAL, g_AL);
    cudaGetSymbolAddress((void**)&pPH, g_PH);
    cudaGetSymbolAddress((void**)&pPL, g_PL);
    cudaGetSymbolAddress((void**)&pWH, g_WH);
    cudaGetSymbolAddress((void**)&pWL, g_WL);
    cudaGetSymbolAddress((void**)&pNDL, g_NDL);
    cudaGetSymbolAddress((void**)&pNDP, g_NDPART);
    cudaGetSymbolAddress((void**)&pOMI, g_OMICL);
    cudaGetSymbolAddress((void**)&pCRS, g_CROSSC);
    cudaGetSymbolAddress((void**)&pM,   g_M);
    cudaGetSymbolAddress((void**)&pZ,   g_Z);
    cudaGetSymbolAddress((void**)&pKO,  g_KO);
    cudaGetSymbolAddress((void**)&pSC,  g_SC);
    cudaGetSymbolAddress((void**)&pCNT, g_CNT);
    cudaGetSymbolAddress((void**)&pOFF, g_OFF);
    cudaGetSymbolAddress((void**)&pCUR, g_CUR);
    cudaGetSymbolAddress((void**)&pSRT, g_SRT);

    cudaFuncSetAttribute(hgemm, cudaFuncAttributeMaxDynamicSharedMemorySize, HG_SMEM);

    auto convA = [&](const float* A, int M, int K, int lda, int ldo) {
        int n = M * (ldo >> 1);
        cvt_splitA<<<(n + 255) / 256, 256>>>(A, M, K, lda, ldo, pAH, pAL);
    };
    auto convW = [&](const float* W, int K, int N, int ldw, int ldo, int Npad) {
        int n = Npad * ldo;
        cvt_splitWt<<<(n + 255) / 256, 256>>>(W, K, N, ldw, ldo, Npad, pWH, pWL);
    };

    // 1) KO
    zero_f<<<(NN + 255) / 256, 256>>>(pKO, NN);
    set_ko<<<(BB * KK + 255) / 256, 256>>>(bkm, pKO);

    // 2) name linear (leaky) -> NDL[:, 0:768]
    convA(name_emb, NE_, TX_, TX_, TX_);
    convW(name_W, TX_, TX_, TX_, TX_, TX_);
    launch_hgemm(pAH, pAL, pWH, pWL, name_b, nullptr, nullptr, pNDL,
                 NE_, TX_, TX_, 24, TX_, TX_, 1536, 1);

    // 3) desc linear (leaky) -> NDL[:, 768:1536]
    convA(desc_emb, NE_, TX_, TX_, TX_);
    convW(desc_W, TX_, TX_, TX_, TX_, TX_);
    launch_hgemm(pAH, pAL, pWH, pWL, desc_b, nullptr, nullptr, pNDL + TX_,
                 NE_, TX_, TX_, 24, TX_, TX_, 1536, 1);

    // 4) ndpart = NDL @ fus_W[0:1536] + fus_b -> NDPART (stride 512, Nc=511)
    convA(pNDL, NE_, 1536, 1536, 1536);
    convW(fus_W, 1536, OM_, OM_, 1536, 512);
    launch_hgemm(pAH, pAL, pWH, pWL, fus_b, nullptr, nullptr, pNDP,
                 NE_, 1536, 1536, 48, OM_, 512, 512, 0);

    // 5) omic = leaky(x @ omic_W + b) -> OMICL (stride 512)
    convA(x, NN, OM_, OM_, 512);
    convW(omic_W, OM_, OM_, OM_, 512, 512);
    launch_hgemm(pAH, pAL, pWH, pWL, omic_b, nullptr, nullptr, pOMI,
                 NN, 512, 512, 16, OM_, 512, 512, 1);

    // 6) PREC split + CROSSC[:,511] = ko
    pack_prec_bf<<<(NN * 256 + 255) / 256, 256>>>(pre_x, pKO, pPH, pPL, pCRS);

    // 7) cross_x = OMICL @ fus_W[1536:] + ndpart[row%NE] -> CROSSC cols 0..510
    convA(pOMI, NN, OM_, 512, 512);
    convW(fus_W + (size_t)1536 * OM_, OM_, OM_, OM_, 512, 512);
    launch_hgemm(pAH, pAL, pWH, pWL, nullptr, pNDP, nullptr, pCRS,
                 NN, 512, 512, 16, OM_, 512, 512, 4);

    // 8) ienc: M = CROSSC @ ienc_W (raw)
    convA(pCRS, NN, DD, DD, 512);
    convW(ienc_W, DD, DD, DD, 512, 512);
    launch_hgemm(pAH, pAL, pWH, pWL, nullptr, nullptr, nullptr, pM,
                 NN, 512, 512, 16, DD, 512, 512, 0);

    // 9) CSR(internal) + gather -> Z = leaky(M[r]+b+sum)+x_c
    zero_i<<<(NN + 255) / 256, 256>>>(pCNT, NN);
    csr_count<<<(E_int + 255) / 256, 256>>>(int_ei, E_int, pCNT);
    csr_scan<<<1, 1024>>>(pCNT, pOFF, pCUR);
    csr_fill<<<(E_int + 255) / 256, 256>>>(int_ei, E_int, pCUR, pSRT);
    gconv_gather<<<NN, 128>>>(pM, ienc_b, pOFF, pCNT, pSRT, x, pKO, pZ, 0);

    // 10) Z += PREC @ pre_W + pre_b
    convW(pre_W, DD, DD, DD, 512, 512);
    launch_hgemm(pPH, pPL, pWH, pWL, pre_b, nullptr, pZ, pZ,
                 NN, 512, 512, 16, DD, 512, 512, 2);

    // 11) enc: M = Z @ enc_W ; CSR(full) + gather -> Z2 (in CROSSC)
    convA(pZ, NN, DD, DD, 512);
    convW(enc_W, DD, DD, DD, 512, 512);
    launch_hgemm(pAH, pAL, pWH, pWL, nullptr, nullptr, nullptr, pM,
                 NN, 512, 512, 16, DD, 512, 512, 0);
    zero_i<<<(NN + 255) / 256, 256>>>(pCNT, NN);
    csr_count<<<(E_full + 255) / 256, 256>>>(edge_ei, E_full, pCNT);
    csr_scan<<<1, 1024>>>(pCNT, pOFF, pCUR);
    csr_fill<<<(E_full + 255) / 256, 256>>>(edge_ei, E_full, pCUR, pSRT);
    gconv_gather<<<NN, 128>>>(pM, enc_b, pOFF, pCNT, pSRT, nullptr, nullptr, pCRS, 1);

    // 12) readout
    float* pZK = pNDL;
    float* pH  = pNDL + NE_ * DD;
    gather_zk<<<(BB * KK * 128 + 255) / 256, 256>>>(pCRS, bkm, pZK);
    convA(pZK, NE_, DD, DD, 512);
    convW(gate_W1, DD, DD, DD, 512, 512);
    launch_hgemm(pAH, pAL, pWH, pWL, gate_b1, nullptr, nullptr, pH,
                 NE_, 512, 512, 16, DD, 512, 512, 0);
    tanh_dot<<<BB * KK, 128>>>(pH, gate_W2, gate_b2, pSC);
    readout2<<<BB, 256>>>(pZK, pSC, reg_W, reg_b, out);

    (void)out_size;
    (void)n_in;
}

// round 5
// speedup vs baseline: 4.5625x; 1.0407x over previous
#include <cuda_runtime.h>
#include <cuda_bf16.h>
#include <cstdint>

#define NN      16384
#define NE_     1024
#define BB      16
#define KK      64
#define TX_     768
#define OM_     511
#define DD      512
#define SLOPE_  0.3f

// ------------------------- helpers ------------------------------------------
__device__ __forceinline__ uint32_t smem_to_u32(const void* p) {
    uint32_t a;
    asm("{ .reg .u64 t; cvta.to.shared.u64 t, %1; cvt.u32.u64 %0, t; }"
        : "=r"(a) : "l"(p));
    return a;
}

#define CP_ASYNC16(saddr, gptr) \
    asm volatile("cp.async.cg.shared.global [%0], [%1], 16;" \
                 :: "r"(saddr), "l"(gptr) : "memory")

#define LDMX4(r0, r1, r2, r3, addr) \
    asm volatile("ldmatrix.sync.aligned.m8n8.x4.shared.b16 {%0,%1,%2,%3}, [%4];" \
                 : "=r"(r0), "=r"(r1), "=r"(r2), "=r"(r3) : "r"(addr))

#define MMA16816(c, a, b) \
    asm volatile("mma.sync.aligned.m16n8k16.row.col.f32.bf16.bf16.f32 " \
                 "{%0,%1,%2,%3},{%4,%5,%6,%7},{%8,%9},{%0,%1,%2,%3};" \
                 : "+f"((c)[0]), "+f"((c)[1]), "+f"((c)[2]), "+f"((c)[3]) \
                 : "r"((a)[0]), "r"((a)[1]), "r"((a)[2]), "r"((a)[3]), \
                   "r"((b)[0]), "r"((b)[1]))

// ------------------------- scratch (device globals) -------------------------
__device__ __nv_bfloat16 g_A1H[NN * DD];       // split activation buffer 1 (hi)
__device__ __nv_bfloat16 g_A1L[NN * DD];
__device__ __nv_bfloat16 g_A2H[NN * DD];       // split activation buffer 2 (hi)
__device__ __nv_bfloat16 g_A2L[NN * DD];
__device__ __nv_bfloat16 g_PH [NN * DD];       // PREC split
__device__ __nv_bfloat16 g_PL [NN * DD];
#define WT_TOTAL 3538944
__device__ __nv_bfloat16 g_WH[WT_TOTAL];       // all W^T splits (hi)
__device__ __nv_bfloat16 g_WL[WT_TOTAL];
__device__ float g_NDPART[NE_ * DD];           // fused name+desc part (stride 512)
__device__ float g_M  [NN * DD];               // gconv message buffer
__device__ float g_Z  [NN * DD];               // z
__device__ float g_Z2 [NN * DD];               // z2 (post enc-gconv)
__device__ float g_ZK [NE_ * DD];              // gathered zk fp32
__device__ float g_H  [NE_ * DD];              // gate hidden
__device__ float g_KO [NN];
__device__ float g_SC [BB * KK];
__device__ int   g_CNT[NN];
__device__ int   g_OFF[NN];
__device__ int   g_CUR[NN];
__device__ int   g_SRT[262144];

// ============================================================================
// HMMA split-bf16 GEMM.  C[M,Nc] = epilogue(A @ B^T), fp32 accumulate.
// Computes Ah*Bh + Ah*Bl + Al*Bh.
// flags: 1 leaky, 2 accumulate (+Cin), 4 add gat[(row&1023)*512+col],
//        8 write split-bf16 out (Oh/Ol, stride ldo, zero-pad [Nc,padN)),
//        16 skip fp32 C write
// ============================================================================
__global__ void __launch_bounds__(256, 2)
hgemm(const __nv_bfloat16* __restrict__ Ah, const __nv_bfloat16* __restrict__ Al,
      const __nv_bfloat16* __restrict__ Bh, const __nv_bfloat16* __restrict__ Bl,
      const float* __restrict__ bias, const float* __restrict__ gat,
      const float* __restrict__ Cin, float* __restrict__ C,
      __nv_bfloat16* __restrict__ Oh, __nv_bfloat16* __restrict__ Ol,
      int lda_b, int ldb_b, int nchunks, int Nc, int ldc, int ldo,
      int padN, int flags)
{
    extern __shared__ char smem[];
    const uint32_t sb = smem_to_u32(smem);
    const int tid  = threadIdx.x;
    const int lane = tid & 31;
    const int wid  = tid >> 5;
    const int wm   = (wid >> 2) * 64;
    const int wn   = (wid & 3) * 32;
    const int bm   = blockIdx.y * 128;
    const int bn   = blockIdx.x * 128;

    float acc[4][4][4];
#pragma unroll
    for (int i = 0; i < 4; i++)
#pragma unroll
        for (int j = 0; j < 4; j++)
#pragma unroll
            for (int q = 0; q < 4; q++) acc[i][j][q] = 0.f;

    auto load_stage = [&](int st, int k0) {
        const uint32_t base = sb + st * 40960;
#pragma unroll
        for (int i = 0; i < 2; i++) {
            const int idx = tid + i * 256;
            const int row = idx >> 2;
            const int c16 = idx & 3;
            const uint32_t so = base + row * 80 + c16 * 16;
            const size_t ga = (size_t)(bm + row) * lda_b + k0 + c16 * 8;
            const size_t gb = (size_t)(bn + row) * ldb_b + k0 + c16 * 8;
            CP_ASYNC16(so,          Ah + ga);
            CP_ASYNC16(so + 10240,  Al + ga);
            CP_ASYNC16(so + 20480,  Bh + gb);
            CP_ASYNC16(so + 30720,  Bl + gb);
        }
        asm volatile("cp.async.commit_group;" ::: "memory");
    };

    auto compute = [&](int st) {
        const uint32_t base = sb + st * 40960;
        const int arow = lane & 15;
        const int asub = (lane >> 4) * 8;
        const int brow = (lane & 7) + (lane >> 4) * 8;
        const int bsub = ((lane >> 3) & 1) * 8;
#pragma unroll
        for (int ks = 0; ks < 2; ks++) {
            const int kb = ks * 16;
            const uint32_t a0 = base + ((wm + arow) * 40 + kb + asub) * 2;
            const uint32_t b0 = base + 20480 + ((wn + brow) * 40 + kb + bsub) * 2;

            uint32_t ah[4][4], bh[4][2];
#pragma unroll
            for (int mt = 0; mt < 4; mt++)
                LDMX4(ah[mt][0], ah[mt][1], ah[mt][2], ah[mt][3], a0 + mt * 16 * 80);
#pragma unroll
            for (int p = 0; p < 2; p++)
                LDMX4(bh[2*p][0], bh[2*p][1], bh[2*p+1][0], bh[2*p+1][1],
                      b0 + p * 16 * 80);
            // pass 1: Ah * Bh
#pragma unroll
            for (int mt = 0; mt < 4; mt++)
#pragma unroll
                for (int nt = 0; nt < 4; nt++)
                    MMA16816(acc[mt][nt], ah[mt], bh[nt]);
            // pass 2: Ah * Bl (load bl just-in-time, 2 nt at a time)
#pragma unroll
            for (int p = 0; p < 2; p++) {
                uint32_t bl[2][2];
                LDMX4(bl[0][0], bl[0][1], bl[1][0], bl[1][1],
                      b0 + 10240 + p * 16 * 80);
#pragma unroll
                for (int mt = 0; mt < 4; mt++) {
                    MMA16816(acc[mt][2*p],   ah[mt], bl[0]);
                    MMA16816(acc[mt][2*p+1], ah[mt], bl[1]);
                }
            }
            // pass 3: Al * Bh (load al just-in-time per mt)
#pragma unroll
            for (int mt = 0; mt < 4; mt++) {
                uint32_t al[4];
                LDMX4(al[0], al[1], al[2], al[3], a0 + 10240 + mt * 16 * 80);
#pragma unroll
                for (int nt = 0; nt < 4; nt++)
                    MMA16816(acc[mt][nt], al, bh[nt]);
            }
        }
    };

    load_stage(0, 0);
    for (int c = 0; c < nchunks; c++) {
        if (c + 1 < nchunks) {
            load_stage((c + 1) & 1, (c + 1) * 32);
            asm volatile("cp.async.wait_group 1;" ::: "memory");
        } else {
            asm volatile("cp.async.wait_group 0;" ::: "memory");
        }
        __syncthreads();
        compute(c & 1);
        __syncthreads();
    }

    // ---- epilogue ----
    const int er = lane >> 2;
    const int ec = (lane & 3) * 2;
#pragma unroll
    for (int mt = 0; mt < 4; mt++) {
#pragma unroll
        for (int h = 0; h < 2; h++) {
            const int row = bm + wm + mt * 16 + er + h * 8;
            const size_t crow = (size_t)row * ldc;
            const size_t orow = (size_t)row * ldo;
            const size_t grow = (size_t)(row & (NE_ - 1)) * 512;
#pragma unroll
            for (int nt = 0; nt < 4; nt++) {
                const int col = bn + wn + nt * 8 + ec;
#pragma unroll
                for (int q = 0; q < 2; q++) {
                    const int cq = col + q;
                    if (cq < Nc) {
                        float v = acc[mt][nt][h * 2 + q];
                        if (bias)      v += bias[cq];
                        if (flags & 4) v += gat[grow + cq];
                        if (flags & 1) v = v > 0.f ? v : SLOPE_ * v;
                        if (flags & 2) v += Cin[crow + cq];
                        if (!(flags & 16)) C[crow + cq] = v;
                        if (flags & 8) {
                            __nv_bfloat16 hh = __float2bfloat16(v);
                            Oh[orow + cq] = hh;
                            Ol[orow + cq] = __float2bfloat16(v - __bfloat162float(hh));
                        }
                    } else if ((flags & 8) && cq < padN) {
                        Oh[orow + cq] = __float2bfloat16(0.f);
                        Ol[orow + cq] = __float2bfloat16(0.f);
                    }
                }
            }
        }
    }
}

// ------------------------- conversion kernels -------------------------------
__global__ void cvt_splitA(const float* __restrict__ A, int M, int K, int lda, int ldo,
                           __nv_bfloat16* __restrict__ Ah, __nv_bfloat16* __restrict__ Al)
{
    int i = blockIdx.x * blockDim.x + threadIdx.x;
    int half = ldo >> 1;
    int r = i / half;
    if (r >= M) return;
    int c2 = (i - r * half) * 2;
    float v0 = (c2 < K)     ? A[(size_t)r * lda + c2]     : 0.f;
    float v1 = (c2 + 1 < K) ? A[(size_t)r * lda + c2 + 1] : 0.f;
    __nv_bfloat16 h0 = __float2bfloat16(v0), h1 = __float2bfloat16(v1);
    __nv_bfloat16 l0 = __float2bfloat16(v0 - __bfloat162float(h0));
    __nv_bfloat16 l1 = __float2bfloat16(v1 - __bfloat162float(h1));
    __nv_bfloat162 hh; hh.x = h0; hh.y = h1;
    __nv_bfloat162 ll; ll.x = l0; ll.y = l1;
    *reinterpret_cast<__nv_bfloat162*>(Ah + (size_t)r * ldo + c2) = hh;
    *reinterpret_cast<__nv_bfloat162*>(Al + (size_t)r * ldo + c2) = ll;
}

// batched W^T split: all weights in one launch
struct WJobs {
    const float* W[9];
    long off[9];
    long cum[10];
    int K[9], N[9], ldw[9], ldo[9];
    int njobs;
};

__global__ void cvt_splitW_all(WJobs jobs,
                               __nv_bfloat16* __restrict__ Wh,
                               __nv_bfloat16* __restrict__ Wl)
{
    long gid = (long)blockIdx.x * blockDim.x + threadIdx.x;
    if (gid >= jobs.cum[jobs.njobs]) return;
    int j = 0;
    while (gid >= jobs.cum[j + 1]) j++;
    long local = gid - jobs.cum[j];
    int ldo = jobs.ldo[j];
    int n = (int)(local / ldo);
    int k = (int)(local - (long)n * ldo);
    float v = (n < jobs.N[j] && k < jobs.K[j])
            ? jobs.W[j][(size_t)k * jobs.ldw[j] + n] : 0.f;
    __nv_bfloat16 h = __float2bfloat16(v);
    Wh[jobs.off[j] + local] = h;
    Wl[jobs.off[j] + local] = __float2bfloat16(v - __bfloat162float(h));
}

// PREC = [pre_x | ko] split bf16; also A1 col 511 = ko split (for cross_c)
__global__ void pack_prec_bf(const float* __restrict__ pre_x, const float* __restrict__ ko,
                             __nv_bfloat16* __restrict__ Ph, __nv_bfloat16* __restrict__ Pl,
                             __nv_bfloat16* __restrict__ A1h, __nv_bfloat16* __restrict__ A1l)
{
    int i = blockIdx.x * blockDim.x + threadIdx.x;   // NN * 256
    if (i >= NN * 256) return;
    int r = i >> 8;
    int c2 = (i & 255) * 2;
    float kv = ko[r];
    float v0 = (c2 < OM_)     ? pre_x[(size_t)r * OM_ + c2]     : kv;
    float v1 = (c2 + 1 < OM_) ? pre_x[(size_t)r * OM_ + c2 + 1] : kv;
    __nv_bfloat16 h0 = __float2bfloat16(v0), h1 = __float2bfloat16(v1);
    __nv_bfloat16 l0 = __float2bfloat16(v0 - __bfloat162float(h0));
    __nv_bfloat16 l1 = __float2bfloat16(v1 - __bfloat162float(h1));
    __nv_bfloat162 hh; hh.x = h0; hh.y = h1;
    __nv_bfloat162 ll; ll.x = l0; ll.y = l1;
    *reinterpret_cast<__nv_bfloat162*>(Ph + (size_t)r * DD + c2) = hh;
    *reinterpret_cast<__nv_bfloat162*>(Pl + (size_t)r * DD + c2) = ll;
    if (c2 == 510) {
        A1h[(size_t)r * DD + OM_] = __float2bfloat16(kv);
        A1l[(size_t)r * DD + OM_] = __float2bfloat16(0.f);
    }
}

// ------------------------- misc ----------------------------------------------
__global__ void zero_f(float* __restrict__ p, int n)
{ int i = blockIdx.x * blockDim.x + threadIdx.x; if (i < n) p[i] = 0.f; }
__global__ void zero_i(int* __restrict__ p, int n)
{ int i = blockIdx.x * blockDim.x + threadIdx.x; if (i < n) p[i] = 0; }

__global__ void set_ko(const int* __restrict__ bkm, float* __restrict__ ko)
{
    int i = blockIdx.x * blockDim.x + threadIdx.x;
    if (i < BB * KK) ko[(i >> 6) * NE_ + bkm[i]] = 1.0f;
}

// ------------------------- CSR build -----------------------------------------
__global__ void csr_count(const int* __restrict__ ei, int E, int* __restrict__ cnt)
{
    int i = blockIdx.x * blockDim.x + threadIdx.x;
    if (i < E) atomicAdd(&cnt[ei[E + i]], 1);
}

__global__ void __launch_bounds__(1024, 1)
csr_scan(const int* __restrict__ cnt, int* __restrict__ off, int* __restrict__ cur)
{
    __shared__ int sa[1024], sbuf[1024];
    int t = threadIdx.x;
    int base = t * 16;
    int loc[16];
    int s = 0;
#pragma unroll
    for (int j = 0; j < 16; j++) { loc[j] = cnt[base + j]; s += loc[j]; }
    sa[t] = s;
    __syncthreads();
    int* A = sa; int* Bf = sbuf;
    for (int d = 1; d < 1024; d <<= 1) {
        int v = A[t] + (t >= d ? A[t - d] : 0);
        __syncthreads();
        Bf[t] = v;
        __syncthreads();
        int* tmp = A; A = Bf; Bf = tmp;
    }
    int run = t ? A[t - 1] : 0;
#pragma unroll
    for (int j = 0; j < 16; j++) { off[base + j] = run; cur[base + j] = run; run += loc[j]; }
}

__global__ void csr_fill(const int* __restrict__ ei, int E,
                         int* __restrict__ cur, int* __restrict__ srt)
{
    int i = blockIdx.x * blockDim.x + threadIdx.x;
    if (i < E) {
        int p = atomicAdd(&cur[ei[E + i]], 1);
        srt[p] = ei[i];
    }
}

// gconv aggregate + epilogue.  mode 0: out = leaky(acc)+x_c ; mode 1: out = leaky(acc)
__global__ void __launch_bounds__(128, 8)
gconv_gather(const float* __restrict__ m, const float* __restrict__ bias,
             const int* __restrict__ off, const int* __restrict__ cnt,
             const int* __restrict__ srt,
             const float* __restrict__ x, const float* __restrict__ ko,
             float* __restrict__ out, int mode)
{
    const int r = blockIdx.x;
    const int t = threadIdx.x;
    float4 acc = reinterpret_cast<const float4*>(m + (size_t)r * DD)[t];
    float4 b   = reinterpret_cast<const float4*>(bias)[t];
    acc.x += b.x; acc.y += b.y; acc.z += b.z; acc.w += b.w;
    const int s0 = off[r];
    const int d  = cnt[r];
    for (int e = 0; e < d; e++) {
        int s = srt[s0 + e];
        float4 v = reinterpret_cast<const float4*>(m + (size_t)s * DD)[t];
        acc.x += v.x; acc.y += v.y; acc.z += v.z; acc.w += v.w;
    }
    acc.x = acc.x > 0.f ? acc.x : SLOPE_ * acc.x;
    acc.y = acc.y > 0.f ? acc.y : SLOPE_ * acc.y;
    acc.z = acc.z > 0.f ? acc.z : SLOPE_ * acc.z;
    acc.w = acc.w > 0.f ? acc.w : SLOPE_ * acc.w;
    if (mode == 0) {
        const int c0 = t * 4;
        float add[4];
#pragma unroll
        for (int q = 0; q < 4; q++) {
            int c = c0 + q;
            add[q] = (c < OM_) ? x[(size_t)r * OM_ + c] : ko[r];
        }
        acc.x += add[0]; acc.y += add[1]; acc.z += add[2]; acc.w += add[3];
    }
    reinterpret_cast<float4*>(out + (size_t)r * DD)[t] = acc;
}

// ------------------------- readout -------------------------------------------
// gather zk rows: fp32 ZK + split bf16 (GEMM input)
__global__ void gather_zk(const float* __restrict__ Z2, const int* __restrict__ bkm,
                          float* __restrict__ ZK,
                          __nv_bfloat16* __restrict__ Ah, __nv_bfloat16* __restrict__ Al)
{
    int i = blockIdx.x * blockDim.x + threadIdx.x;
    if (i >= BB * KK * 128) return;
    int row = i >> 7, c4 = i & 127;
    int b = row >> 6;
    size_t src = (size_t)bkm[row] + (size_t)b * NE_;
    float4 v = reinterpret_cast<const float4*>(Z2)[src * 128 + c4];
    reinterpret_cast<float4*>(ZK)[(size_t)row * 128 + c4] = v;
    float vv[4] = {v.x, v.y, v.z, v.w};
    __nv_bfloat16 h[4], l[4];
#pragma unroll
    for (int q = 0; q < 4; q++) {
        h[q] = __float2bfloat16(vv[q]);
        l[q] = __float2bfloat16(vv[q] - __bfloat162float(h[q]));
    }
    size_t o = (size_t)row * DD + c4 * 4;
    __nv_bfloat162 h01; h01.x = h[0]; h01.y = h[1];
    __nv_bfloat162 h23; h23.x = h[2]; h23.y = h[3];
    __nv_bfloat162 l01; l01.x = l[0]; l01.y = l[1];
    __nv_bfloat162 l23; l23.x = l[2]; l23.y = l[3];
    *reinterpret_cast<__nv_bfloat162*>(Ah + o)     = h01;
    *reinterpret_cast<__nv_bfloat162*>(Ah + o + 2) = h23;
    *reinterpret_cast<__nv_bfloat162*>(Al + o)     = l01;
    *reinterpret_cast<__nv_bfloat162*>(Al + o + 2) = l23;
}

__global__ void tanh_dot(const float* __restrict__ H, const float* __restrict__ W2,
                         const float* __restrict__ b2, float* __restrict__ sc)
{
    int row = blockIdx.x;
    int tid = threadIdx.x;   // 128
    __shared__ float red[128];
    float p = 0.f;
    for (int j = tid; j < DD; j += 128)
        p = fmaf(tanhf(H[(size_t)row * DD + j]), W2[j], p);
    red[tid] = p;
    __syncthreads();
    for (int s = 64; s > 0; s >>= 1) {
        if (tid < s) red[tid] += red[tid + s];
        __syncthreads();
    }
    if (tid == 0) sc[row] = red[0] + b2[0];
}

__global__ void readout2(const float* __restrict__ ZK, const float* __restrict__ sc,
                         const float* __restrict__ regW, const float* __restrict__ regb,
                         float* __restrict__ out)
{
    int b = blockIdx.x;
    int tid = threadIdx.x;   // 256
    __shared__ float w[KK];
    __shared__ float red[256];
    __shared__ float sm;
    if (tid < KK) w[tid] = sc[b * KK + tid];
    __syncthreads();
    if (tid == 0) {
        float m = w[0];
        for (int k = 1; k < KK; k++) m = fmaxf(m, w[k]);
        float s = 0.f;
        for (int k = 0; k < KK; k++) { w[k] = expf(w[k] - m); s += w[k]; }
        sm = s;
    }
    __syncthreads();
    int c0 = tid, c1 = tid + 256;
    float r0 = 0.f, r1 = 0.f;
    for (int k = 0; k < KK; k++) {
        const float* z = ZK + ((size_t)b * KK + k) * DD;
        float wk = w[k];
        r0 = fmaf(wk, z[c0], r0);
        r1 = fmaf(wk, z[c1], r1);
    }
    float part = (r0 * regW[c0] + r1 * regW[c1]) / sm;
    red[tid] = part;
    __syncthreads();
    for (int s = 128; s > 0; s >>= 1) {
        if (tid < s) red[tid] += red[tid + s];
        __syncthreads();
    }
    if (tid == 0) out[b] = red[0] + regb[0];
}

// ------------------------- host side ------------------------------------------
static const int HG_SMEM = 2 * 40960;   // 81920 bytes

extern "C" void kernel_launch(void* const* d_in, const int* in_sizes, int n_in,
                              void* d_out, int out_size)
{
    int map_[31];
    {
        int p = 0;
        for (int l = 0; l < 31; l++) {
            if (l == 5 || l == 8) {
                bool present = (n_in == 31);
                if (present && p < n_in && in_sizes[p] == 1) map_[l] = p++;
                else map_[l] = -1;
            } else map_[l] = p++;
        }
    }
    auto F = [&](int l) -> const float* { return (const float*)d_in[map_[l]]; };
    auto I = [&](int l) -> const int*   { return (const int*)d_in[map_[l]]; };

    const float* x        = F(0);
    const float* pre_x    = F(1);
    const int*   edge_ei  = I(2);
    const int*   int_ei   = I(3);
    const float* name_emb = F(6);
    const float* desc_emb = F(7);
    const int*   bkm      = I(9);
    const float* name_W = F(11), *name_b = F(12);
    const float* desc_W = F(13), *desc_b = F(14);
    const float* omic_W = F(15), *omic_b = F(16);
    const float* fus_W  = F(17), *fus_b  = F(18);
    const float* pre_W  = F(19), *pre_b  = F(20);
    const float* ienc_W = F(21), *ienc_b = F(22);
    const float* enc_W  = F(23), *enc_b  = F(24);
    const float* gate_W1 = F(25), *gate_b1 = F(26);
    const float* gate_W2 = F(27), *gate_b2 = F(28);
    const float* reg_W   = F(29), *reg_b   = F(30);
    float* out = (float*)d_out;

    const int E_full = in_sizes[map_[2]] / 2;
    const int E_int  = in_sizes[map_[3]] / 2;

    __nv_bfloat16 *pA1H, *pA1L, *pA2H, *pA2L, *pPH, *pPL, *pWH, *pWL;
    float *pNDP, *pM, *pZ, *pZ2, *pZK, *pH, *pKO, *pSC;
    int *pCNT, *pOFF, *pCUR, *pSRT;
    cudaGetSymbolAddress((void**)&pA1H, g_A1H);
    cudaGetSymbolAddress((void**)&pA1L, g_A1L);
    cudaGetSymbolAddress((void**)&pA2H, g_A2H);
    cudaGetSymbolAddress((void**)&pA2L, g_A2L);
    cudaGetSymbolAddress((void**)&pPH,  g_PH);
    cudaGetSymbolAddress((void**)&pPL,  g_PL);
    cudaGetSymbolAddress((void**)&pWH,  g_WH);
    cudaGetSymbolAddress((void**)&pWL,  g_WL);
    cudaGetSymbolAddress((void**)&pNDP, g_NDPART);
    cudaGetSymbolAddress((void**)&pM,   g_M);
    cudaGetSymbolAddress((void**)&pZ,   g_Z);
    cudaGetSymbolAddress((void**)&pZ2,  g_Z2);
    cudaGetSymbolAddress((void**)&pZK,  g_ZK);
    cudaGetSymbolAddress((void**)&pH,   g_H);
    cudaGetSymbolAddress((void**)&pKO,  g_KO);
    cudaGetSymbolAddress((void**)&pSC,  g_SC);
    cudaGetSymbolAddress((void**)&pCNT, g_CNT);
    cudaGetSymbolAddress((void**)&pOFF, g_OFF);
    cudaGetSymbolAddress((void**)&pCUR, g_CUR);
    cudaGetSymbolAddress((void**)&pSRT, g_SRT);

    cudaFuncSetAttribute(hgemm, cudaFuncAttributeMaxDynamicSharedMemorySize, HG_SMEM);

    // weight layout offsets in WH/WL (elements)
    const long OFF_NAME = 0;
    const long OFF_DESC = OFF_NAME + 768L * 768;
    const long OFF_FUS1 = OFF_DESC + 768L * 768;
    const long OFF_OMIC = OFF_FUS1 + 512L * 1536;
    const long OFF_FUS2 = OFF_OMIC + 512L * 512;
    const long OFF_IENC = OFF_FUS2 + 512L * 512;
    const long OFF_PRE  = OFF_IENC + 512L * 512;
    const long OFF_ENC  = OFF_PRE  + 512L * 512;
    const long OFF_GATE = OFF_ENC  + 512L * 512;

    // 1) KO + batched weight conversion
    zero_f<<<(NN + 255) / 256, 256>>>(pKO, NN);
    set_ko<<<(BB * KK + 255) / 256, 256>>>(bkm, pKO);

    {
        WJobs jb;
        const float* Ws[9] = {name_W, desc_W, fus_W, omic_W,
                              fus_W + (size_t)1536 * OM_, ienc_W, pre_W, enc_W, gate_W1};
        int Ks[9]  = {TX_, TX_, 1536, OM_, OM_, DD, DD, DD, DD};
        int Ns[9]  = {TX_, TX_, OM_, OM_, OM_, DD, DD, DD, DD};
        int ldw[9] = {TX_, TX_, OM_, OM_, OM_, DD, DD, DD, DD};
        int ldo[9] = {TX_, TX_, 1536, 512, 512, 512, 512, 512, 512};
        int Np[9]  = {TX_, TX_, 512, 512, 512, 512, 512, 512, 512};
        long offs[9] = {OFF_NAME, OFF_DESC, OFF_FUS1, OFF_OMIC, OFF_FUS2,
                        OFF_IENC, OFF_PRE, OFF_ENC, OFF_GATE};
        long cum = 0;
        jb.njobs = 9;
        for (int j = 0; j < 9; j++) {
            jb.W[j] = Ws[j]; jb.K[j] = Ks[j]; jb.N[j] = Ns[j];
            jb.ldw[j] = ldw[j]; jb.ldo[j] = ldo[j]; jb.off[j] = offs[j];
            jb.cum[j] = cum; cum += (long)Np[j] * ldo[j];
        }
        jb.cum[9] = cum;
        cvt_splitW_all<<<(int)((cum + 255) / 256), 256>>>(jb, pWH, pWL);
    }

    // 2) name/desc emb -> split A1 (rows 0..1023 name, 1024..2047 desc, ld 768)
    cvt_splitA<<<(NE_ * 384 + 255) / 256, 256>>>(name_emb, NE_, TX_, TX_, TX_, pA1H, pA1L);
    cvt_splitA<<<(NE_ * 384 + 255) / 256, 256>>>(desc_emb, NE_, TX_, TX_, TX_,
                                                 pA1H + (size_t)NE_ * TX_,
                                                 pA1L + (size_t)NE_ * TX_);

    // 3) name linear (leaky) -> split A2[:, 0:768] (ld 1536)
    hgemm<<<dim3(6, 8), 256, HG_SMEM>>>(pA1H, pA1L, pWH + OFF_NAME, pWL + OFF_NAME,
        name_b, nullptr, nullptr, nullptr, pA2H, pA2L,
        TX_, TX_, 24, TX_, 0, 1536, TX_, 1 | 8 | 16);
    // 4) desc linear (leaky) -> split A2[:, 768:1536]
    hgemm<<<dim3(6, 8), 256, HG_SMEM>>>(pA1H + (size_t)NE_ * TX_, pA1L + (size_t)NE_ * TX_,
        pWH + OFF_DESC, pWL + OFF_DESC,
        desc_b, nullptr, nullptr, nullptr, pA2H + TX_, pA2L + TX_,
        TX_, TX_, 24, TX_, 0, 1536, TX_, 1 | 8 | 16);

    // 5) ndpart = A2 @ fus_W[0:1536] + fus_b -> NDPART fp32 (stride 512)
    hgemm<<<dim3(4, 8), 256, HG_SMEM>>>(pA2H, pA2L, pWH + OFF_FUS1, pWL + OFF_FUS1,
        fus_b, nullptr, nullptr, pNDP, nullptr, nullptr,
        1536, 1536, 48, OM_, 512, 0, 0, 0);

    // 6) x -> split A1 (ld 512)
    cvt_splitA<<<(NN * 256 + 255) / 256, 256>>>(x, NN, OM_, OM_, 512, pA1H, pA1L);

    // 7) omic = leaky(x @ omic_W + b) -> split A2 (ld 512, zero col 511)
    hgemm<<<dim3(4, 128), 256, HG_SMEM>>>(pA1H, pA1L, pWH + OFF_OMIC, pWL + OFF_OMIC,
        omic_b, nullptr, nullptr, nullptr, pA2H, pA2L,
        512, 512, 16, OM_, 0, 512, 512, 1 | 8 | 16);

    // 8) PREC split + A1 col 511 = ko split
    pack_prec_bf<<<(NN * 256 + 255) / 256, 256>>>(pre_x, pKO, pPH, pPL, pA1H, pA1L);

    // 9) cross_x = omic @ fus_W[1536:] + ndpart -> split A1 cols 0..510
    hgemm<<<dim3(4, 128), 256, HG_SMEM>>>(pA2H, pA2L, pWH + OFF_FUS2, pWL + OFF_FUS2,
        nullptr, pNDP, nullptr, nullptr, pA1H, pA1L,
        512, 512, 16, OM_, 0, 512, OM_, 4 | 8 | 16);

    // 10) ienc: M = cross_c @ ienc_W (raw fp32)
    hgemm<<<dim3(4, 128), 256, HG_SMEM>>>(pA1H, pA1L, pWH + OFF_IENC, pWL + OFF_IENC,
        nullptr, nullptr, nullptr, pM, nullptr, nullptr,
        512, 512, 16, DD, 512, 0, 0, 0);

    // 11) CSR(internal) + gather -> Z = leaky(M[r]+b+sum)+x_c
    zero_i<<<(NN + 255) / 256, 256>>>(pCNT, NN);
    csr_count<<<(E_int + 255) / 256, 256>>>(int_ei, E_int, pCNT);
    csr_scan<<<1, 1024>>>(pCNT, pOFF, pCUR);
    csr_fill<<<(E_int + 255) / 256, 256>>>(int_ei, E_int, pCUR, pSRT);
    gconv_gather<<<NN, 128>>>(pM, ienc_b, pOFF, pCNT, pSRT, x, pKO, pZ, 0);

    // 12) Z += PREC @ pre_W + pre_b ; also emit split -> A2
    hgemm<<<dim3(4, 128), 256, HG_SMEM>>>(pPH, pPL, pWH + OFF_PRE, pWL + OFF_PRE,
        pre_b, nullptr, pZ, pZ, pA2H, pA2L,
        512, 512, 16, DD, 512, 512, DD, 2 | 8);

    // 13) enc: M = Z @ enc_W ; CSR(full) + gather -> Z2
    hgemm<<<dim3(4, 128), 256, HG_SMEM>>>(pA2H, pA2L, pWH + OFF_ENC, pWL + OFF_ENC,
        nullptr, nullptr, nullptr, pM, nullptr, nullptr,
        512, 512, 16, DD, 512, 0, 0, 0);
    zero_i<<<(NN + 255) / 256, 256>>>(pCNT, NN);
    csr_count<<<(E_full + 255) / 256, 256>>>(edge_ei, E_full, pCNT);
    csr_scan<<<1, 1024>>>(pCNT, pOFF, pCUR);
    csr_fill<<<(E_full + 255) / 256, 256>>>(edge_ei, E_full, pCUR, pSRT);
    gconv_gather<<<NN, 128>>>(pM, enc_b, pOFF, pCNT, pSRT, nullptr, nullptr, pZ2, 1);

    // 14) readout: gather zk (fp32 + split A1), gate GEMM, tanh·W2, softmax+reg
    gather_zk<<<(BB * KK * 128 + 255) / 256, 256>>>(pZ2, bkm, pZK, pA1H, pA1L);
    hgemm<<<dim3(4, 8), 256, HG_SMEM>>>(pA1H, pA1L, pWH + OFF_GATE, pWL + OFF_GATE,
        gate_b1, nullptr, nullptr, pH, nullptr, nullptr,
        512, 512, 16, DD, 512, 0, 0, 0);
    tanh_dot<<<BB * KK, 128>>>(pH, gate_W2, gate_b2, pSC);
    readout2<<<BB, 256>>>(pZK, pSC, reg_W, reg_b, out);

    (void)out_size;
    (void)n_in;
}

// round 6
// speedup vs baseline: 5.3052x; 1.1628x over previous
#include <cuda_runtime.h>
#include <cuda_bf16.h>
#include <cstdint>

#define NN      16384
#define NE_     1024
#define BB      16
#define KK      64
#define TX_     768
#define OM_     511
#define DD      512
#define SLOPE_  0.3f
#define E_INT_MAX 131072
#define E_FULL_MAX 262144

// ------------------------- helpers ------------------------------------------
__device__ __forceinline__ uint32_t smem_to_u32(const void* p) {
    uint32_t a;
    asm("{ .reg .u64 t; cvta.to.shared.u64 t, %1; cvt.u32.u64 %0, t; }"
        : "=r"(a) : "l"(p));
    return a;
}

#define CP_ASYNC16(saddr, gptr) \
    asm volatile("cp.async.cg.shared.global [%0], [%1], 16;" \
                 :: "r"(saddr), "l"(gptr) : "memory")

#define LDMX4(r0, r1, r2, r3, addr) \
    asm volatile("ldmatrix.sync.aligned.m8n8.x4.shared.b16 {%0,%1,%2,%3}, [%4];" \
                 : "=r"(r0), "=r"(r1), "=r"(r2), "=r"(r3) : "r"(addr))

#define MMA16816(c, a, b) \
    asm volatile("mma.sync.aligned.m16n8k16.row.col.f32.bf16.bf16.f32 " \
                 "{%0,%1,%2,%3},{%4,%5,%6,%7},{%8,%9},{%0,%1,%2,%3};" \
                 : "+f"((c)[0]), "+f"((c)[1]), "+f"((c)[2]), "+f"((c)[3]) \
                 : "r"((a)[0]), "r"((a)[1]), "r"((a)[2]), "r"((a)[3]), \
                   "r"((b)[0]), "r"((b)[1]))

// ------------------------- scratch (device globals) -------------------------
__device__ __nv_bfloat16 g_A1H[NN * DD];
__device__ __nv_bfloat16 g_A1L[NN * DD];
__device__ __nv_bfloat16 g_A2H[NN * DD];
__device__ __nv_bfloat16 g_A2L[NN * DD];
#define WT_TOTAL 3538944
__device__ __nv_bfloat16 g_WH[WT_TOTAL];
__device__ __nv_bfloat16 g_WL[WT_TOTAL];
__device__ __nv_bfloat16 g_WFH[DD * DD];       // WFT split
__device__ __nv_bfloat16 g_WFL[DD * DD];
__device__ __nv_bfloat16 g_NDPH[NE_ * DD];     // ndpart split
__device__ __nv_bfloat16 g_NDPL[NE_ * DD];
__device__ float g_NDP2[NE_ * DD];             // ndpart @ Wienc'
__device__ float g_M  [NN * DD];
__device__ float g_Z  [NN * DD];
__device__ float g_Z2 [NN * DD];
__device__ float g_ZK [NE_ * DD];
__device__ float g_H  [NE_ * DD];
__device__ float g_KO [NN];
__device__ float g_SC [BB * KK];
__device__ int   g_CNT[2 * NN];
__device__ int   g_OFF[2 * NN];
__device__ int   g_CUR[2 * NN];
__device__ int   g_SRT[E_INT_MAX + E_FULL_MAX];

// ============================================================================
// HMMA split-bf16 GEMM.  C[M,Nc] = epilogue(A @ B^T), fp32 accumulate.
// Computes Ah*Bh + Ah*Bl + Al*Bh.
// flags: 1 leaky, 2 accumulate (+Cin), 4 add gat[(row&1023)*512+col],
//        8 write split-bf16 (Oh/Ol stride ldo, zero-pad cols [Nc,padN)),
//        16 skip fp32 C write, 32 add koV[row]*w511[col]
// ============================================================================
__global__ void __launch_bounds__(256, 2)
hgemm(const __nv_bfloat16* __restrict__ Ah, const __nv_bfloat16* __restrict__ Al,
      const __nv_bfloat16* __restrict__ Bh, const __nv_bfloat16* __restrict__ Bl,
      const float* __restrict__ bias, const float* __restrict__ gat,
      const float* __restrict__ koV, const float* __restrict__ w511,
      const float* __restrict__ Cin, float* __restrict__ C,
      __nv_bfloat16* __restrict__ Oh, __nv_bfloat16* __restrict__ Ol,
      int lda_b, int ldb_b, int nchunks, int Nc, int ldc, int ldo,
      int padN, int flags)
{
    extern __shared__ char smem[];
    const uint32_t sb = smem_to_u32(smem);
    const int tid  = threadIdx.x;
    const int lane = tid & 31;
    const int wid  = tid >> 5;
    const int wm   = (wid >> 2) * 64;
    const int wn   = (wid & 3) * 32;
    const int bm   = blockIdx.y * 128;
    const int bn   = blockIdx.x * 128;

    float acc[4][4][4];
#pragma unroll
    for (int i = 0; i < 4; i++)
#pragma unroll
        for (int j = 0; j < 4; j++)
#pragma unroll
            for (int q = 0; q < 4; q++) acc[i][j][q] = 0.f;

    auto load_stage = [&](int st, int k0) {
        const uint32_t base = sb + st * 40960;
#pragma unroll
        for (int i = 0; i < 2; i++) {
            const int idx = tid + i * 256;
            const int row = idx >> 2;
            const int c16 = idx & 3;
            const uint32_t so = base + row * 80 + c16 * 16;
            const size_t ga = (size_t)(bm + row) * lda_b + k0 + c16 * 8;
            const size_t gb = (size_t)(bn + row) * ldb_b + k0 + c16 * 8;
            CP_ASYNC16(so,          Ah + ga);
            CP_ASYNC16(so + 10240,  Al + ga);
            CP_ASYNC16(so + 20480,  Bh + gb);
            CP_ASYNC16(so + 30720,  Bl + gb);
        }
        asm volatile("cp.async.commit_group;" ::: "memory");
    };

    auto compute = [&](int st) {
        const uint32_t base = sb + st * 40960;
        const int arow = lane & 15;
        const int asub = (lane >> 4) * 8;
        const int brow = (lane & 7) + (lane >> 4) * 8;
        const int bsub = ((lane >> 3) & 1) * 8;
#pragma unroll
        for (int ks = 0; ks < 2; ks++) {
            const int kb = ks * 16;
            const uint32_t a0 = base + ((wm + arow) * 40 + kb + asub) * 2;
            const uint32_t b0 = base + 20480 + ((wn + brow) * 40 + kb + bsub) * 2;

            uint32_t ah[4][4], bh[4][2];
#pragma unroll
            for (int mt = 0; mt < 4; mt++)
                LDMX4(ah[mt][0], ah[mt][1], ah[mt][2], ah[mt][3], a0 + mt * 16 * 80);
#pragma unroll
            for (int p = 0; p < 2; p++)
                LDMX4(bh[2*p][0], bh[2*p][1], bh[2*p+1][0], bh[2*p+1][1],
                      b0 + p * 16 * 80);
#pragma unroll
            for (int mt = 0; mt < 4; mt++)
#pragma unroll
                for (int nt = 0; nt < 4; nt++)
                    MMA16816(acc[mt][nt], ah[mt], bh[nt]);
#pragma unroll
            for (int p = 0; p < 2; p++) {
                uint32_t bl[2][2];
                LDMX4(bl[0][0], bl[0][1], bl[1][0], bl[1][1],
                      b0 + 10240 + p * 16 * 80);
#pragma unroll
                for (int mt = 0; mt < 4; mt++) {
                    MMA16816(acc[mt][2*p],   ah[mt], bl[0]);
                    MMA16816(acc[mt][2*p+1], ah[mt], bl[1]);
                }
            }
#pragma unroll
            for (int mt = 0; mt < 4; mt++) {
                uint32_t al[4];
                LDMX4(al[0], al[1], al[2], al[3], a0 + 10240 + mt * 16 * 80);
#pragma unroll
                for (int nt = 0; nt < 4; nt++)
                    MMA16816(acc[mt][nt], al, bh[nt]);
            }
        }
    };

    load_stage(0, 0);
    for (int c = 0; c < nchunks; c++) {
        if (c + 1 < nchunks) {
            load_stage((c + 1) & 1, (c + 1) * 32);
            asm volatile("cp.async.wait_group 1;" ::: "memory");
        } else {
            asm volatile("cp.async.wait_group 0;" ::: "memory");
        }
        __syncthreads();
        compute(c & 1);
        __syncthreads();
    }

    // ---- epilogue (vectorized pairs) ----
    const int er = lane >> 2;
    const int ec = (lane & 3) * 2;
#pragma unroll
    for (int mt = 0; mt < 4; mt++) {
#pragma unroll
        for (int h = 0; h < 2; h++) {
            const int row = bm + wm + mt * 16 + er + h * 8;
            const size_t crow = (size_t)row * ldc;
            const size_t orow = (size_t)row * ldo;
            const size_t grow = (size_t)(row & (NE_ - 1)) * 512;
            const float kv = (flags & 32) ? koV[row] : 0.f;
#pragma unroll
            for (int nt = 0; nt < 4; nt++) {
                const int col = bn + wn + nt * 8 + ec;
                float v0 = acc[mt][nt][h * 2 + 0];
                float v1 = acc[mt][nt][h * 2 + 1];
                if (col + 1 < Nc) {
                    if (bias) {
                        float2 bb = *reinterpret_cast<const float2*>(bias + col);
                        v0 += bb.x; v1 += bb.y;
                    }
                    if (flags & 4) {
                        float2 gg = *reinterpret_cast<const float2*>(gat + grow + col);
                        v0 += gg.x; v1 += gg.y;
                    }
                    if (flags & 32) {
                        float2 ww = *reinterpret_cast<const float2*>(w511 + col);
                        v0 += kv * ww.x; v1 += kv * ww.y;
                    }
                    if (flags & 1) {
                        v0 = v0 > 0.f ? v0 : SLOPE_ * v0;
                        v1 = v1 > 0.f ? v1 : SLOPE_ * v1;
                    }
                    if (flags & 2) {
                        float2 ci = *reinterpret_cast<const float2*>(Cin + crow + col);
                        v0 += ci.x; v1 += ci.y;
                    }
                    if (!(flags & 16))
                        *reinterpret_cast<float2*>(C + crow + col) = make_float2(v0, v1);
                    if (flags & 8) {
                        __nv_bfloat16 h0 = __float2bfloat16(v0);
                        __nv_bfloat16 h1 = __float2bfloat16(v1);
                        __nv_bfloat162 hh; hh.x = h0; hh.y = h1;
                        __nv_bfloat162 ll;
                        ll.x = __float2bfloat16(v0 - __bfloat162float(h0));
                        ll.y = __float2bfloat16(v1 - __bfloat162float(h1));
                        *reinterpret_cast<__nv_bfloat162*>(Oh + orow + col) = hh;
                        *reinterpret_cast<__nv_bfloat162*>(Ol + orow + col) = ll;
                    }
                } else {
                    float vv[2] = {v0, v1};
#pragma unroll
                    for (int q = 0; q < 2; q++) {
                        const int cq = col + q;
                        if (cq < Nc) {
                            float v = vv[q];
                            if (bias)       v += bias[cq];
                            if (flags & 4)  v += gat[grow + cq];
                            if (flags & 32) v += kv * w511[cq];
                            if (flags & 1)  v = v > 0.f ? v : SLOPE_ * v;
                            if (flags & 2)  v += Cin[crow + cq];
                            if (!(flags & 16)) C[crow + cq] = v;
                            if (flags & 8) {
                                __nv_bfloat16 hh = __float2bfloat16(v);
                                Oh[orow + cq] = hh;
                                Ol[orow + cq] = __float2bfloat16(v - __bfloat162float(hh));
                            }
                        } else if ((flags & 8) && cq < padN) {
                            Oh[orow + cq] = __float2bfloat16(0.f);
                            Ol[orow + cq] = __float2bfloat16(0.f);
                        }
                    }
                }
            }
        }
    }
}

// ------------------------- conversion kernels -------------------------------
__global__ void cvt_splitA(const float* __restrict__ A, int M, int K, int lda, int ldo,
                           __nv_bfloat16* __restrict__ Ah, __nv_bfloat16* __restrict__ Al)
{
    int i = blockIdx.x * blockDim.x + threadIdx.x;
    int half = ldo >> 1;
    int r = i / half;
    if (r >= M) return;
    int c2 = (i - r * half) * 2;
    float v0 = (c2 < K)     ? A[(size_t)r * lda + c2]     : 0.f;
    float v1 = (c2 + 1 < K) ? A[(size_t)r * lda + c2 + 1] : 0.f;
    __nv_bfloat16 h0 = __float2bfloat16(v0), h1 = __float2bfloat16(v1);
    __nv_bfloat16 l0 = __float2bfloat16(v0 - __bfloat162float(h0));
    __nv_bfloat16 l1 = __float2bfloat16(v1 - __bfloat162float(h1));
    __nv_bfloat162 hh; hh.x = h0; hh.y = h1;
    __nv_bfloat162 ll; ll.x = l0; ll.y = l1;
    *reinterpret_cast<__nv_bfloat162*>(Ah + (size_t)r * ldo + c2) = hh;
    *reinterpret_cast<__nv_bfloat162*>(Al + (size_t)r * ldo + c2) = ll;
}

// batched weight split; trans=1: B[n,k]=W[k*ldw+n], trans=0: B[n,k]=W[n*ldw+k]
struct WJobs {
    const float* W[9];
    long off[9];
    long cum[10];
    int K[9], N[9], ldw[9], ldo[9], trans[9];
    int njobs;
};

__global__ void cvt_splitW_all(WJobs jobs,
                               __nv_bfloat16* __restrict__ Wh,
                               __nv_bfloat16* __restrict__ Wl)
{
    long gid = (long)blockIdx.x * blockDim.x + threadIdx.x;
    if (gid >= jobs.cum[jobs.njobs]) return;
    int j = 0;
    while (gid >= jobs.cum[j + 1]) j++;
    long local = gid - jobs.cum[j];
    int ldo = jobs.ldo[j];
    int n = (int)(local / ldo);
    int k = (int)(local - (long)n * ldo);
    float v = 0.f;
    if (n < jobs.N[j] && k < jobs.K[j])
        v = jobs.trans[j] ? jobs.W[j][(size_t)k * jobs.ldw[j] + n]
                          : jobs.W[j][(size_t)n * jobs.ldw[j] + k];
    __nv_bfloat16 h = __float2bfloat16(v);
    Wh[jobs.off[j] + local] = h;
    Wl[jobs.off[j] + local] = __float2bfloat16(v - __bfloat162float(h));
}

// ------------------------- misc ----------------------------------------------
__global__ void zero_f(float* __restrict__ p, int n)
{ int i = blockIdx.x * blockDim.x + threadIdx.x; if (i < n) p[i] = 0.f; }
__global__ void zero_i(int* __restrict__ p, int n)
{ int i = blockIdx.x * blockDim.x + threadIdx.x; if (i < n) p[i] = 0; }

__global__ void set_ko(const int* __restrict__ bkm, float* __restrict__ ko)
{
    int i = blockIdx.x * blockDim.x + threadIdx.x;
    if (i < BB * KK) ko[(i >> 6) * NE_ + bkm[i]] = 1.0f;
}

// ------------------------- CSR build (both graphs batched) -------------------
__global__ void csr_count2(const int* __restrict__ iei, int Ei,
                           const int* __restrict__ fei, int Ef,
                           int* __restrict__ cnt)
{
    int i = blockIdx.x * blockDim.x + threadIdx.x;
    if (i < Ei) atomicAdd(&cnt[iei[Ei + i]], 1);
    else if (i < Ei + Ef) {
        int j = i - Ei;
        atomicAdd(&cnt[NN + fei[Ef + j]], 1);
    }
}

__global__ void __launch_bounds__(1024, 1)
csr_scan2(const int* __restrict__ cnt, int* __restrict__ off,
          int* __restrict__ cur, int base1)
{
    __shared__ int sa[1024], sbuf[1024];
    const int g = blockIdx.x;
    const int* c = cnt + g * NN;
    int* o = off + g * NN;
    int* u = cur + g * NN;
    int t = threadIdx.x;
    int base = t * 16;
    int loc[16];
    int s = 0;
#pragma unroll
    for (int j = 0; j < 16; j++) { loc[j] = c[base + j]; s += loc[j]; }
    sa[t] = s;
    __syncthreads();
    int* A = sa; int* Bf = sbuf;
    for (int d = 1; d < 1024; d <<= 1) {
        int v = A[t] + (t >= d ? A[t - d] : 0);
        __syncthreads();
        Bf[t] = v;
        __syncthreads();
        int* tmp = A; A = Bf; Bf = tmp;
    }
    int run = (t ? A[t - 1] : 0) + (g ? base1 : 0);
#pragma unroll
    for (int j = 0; j < 16; j++) { o[base + j] = run; u[base + j] = run; run += loc[j]; }
}

__global__ void csr_fill2(const int* __restrict__ iei, int Ei,
                          const int* __restrict__ fei, int Ef,
                          int* __restrict__ cur, int* __restrict__ srt)
{
    int i = blockIdx.x * blockDim.x + threadIdx.x;
    if (i < Ei) {
        int p = atomicAdd(&cur[iei[Ei + i]], 1);
        srt[p] = iei[i];
    } else if (i < Ei + Ef) {
        int j = i - Ei;
        int p = atomicAdd(&cur[NN + fei[Ef + j]], 1);
        srt[p] = fei[j];
    }
}

// gconv aggregate + epilogue.  mode 0: out = leaky(acc)+x_c ; mode 1: out = leaky(acc)
__global__ void __launch_bounds__(128, 8)
gconv_gather(const float* __restrict__ m, const float* __restrict__ bias,
             const int* __restrict__ off, const int* __restrict__ cnt,
             const int* __restrict__ srt,
             const float* __restrict__ x, const float* __restrict__ ko,
             float* __restrict__ out, int mode)
{
    const int r = blockIdx.x;
    const int t = threadIdx.x;
    float4 acc = reinterpret_cast<const float4*>(m + (size_t)r * DD)[t];
    float4 b   = reinterpret_cast<const float4*>(bias)[t];
    acc.x += b.x; acc.y += b.y; acc.z += b.z; acc.w += b.w;
    const int s0 = off[r];
    const int d  = cnt[r];
    for (int e = 0; e < d; e++) {
        int s = srt[s0 + e];
        float4 v = reinterpret_cast<const float4*>(m + (size_t)s * DD)[t];
        acc.x += v.x; acc.y += v.y; acc.z += v.z; acc.w += v.w;
    }
    acc.x = acc.x > 0.f ? acc.x : SLOPE_ * acc.x;
    acc.y = acc.y > 0.f ? acc.y : SLOPE_ * acc.y;
    acc.z = acc.z > 0.f ? acc.z : SLOPE_ * acc.z;
    acc.w = acc.w > 0.f ? acc.w : SLOPE_ * acc.w;
    if (mode == 0) {
        const int c0 = t * 4;
        float add[4];
#pragma unroll
        for (int q = 0; q < 4; q++) {
            int c = c0 + q;
            add[q] = (c < OM_) ? x[(size_t)r * OM_ + c] : ko[r];
        }
        acc.x += add[0]; acc.y += add[1]; acc.z += add[2]; acc.w += add[3];
    }
    reinterpret_cast<float4*>(out + (size_t)r * DD)[t] = acc;
}

// ------------------------- readout -------------------------------------------
__global__ void gather_zk(const float* __restrict__ Z2, const int* __restrict__ bkm,
                          float* __restrict__ ZK,
                          __nv_bfloat16* __restrict__ Ah, __nv_bfloat16* __restrict__ Al)
{
    int i = blockIdx.x * blockDim.x + threadIdx.x;
    if (i >= BB * KK * 128) return;
    int row = i >> 7, c4 = i & 127;
    int b = row >> 6;
    size_t src = (size_t)bkm[row] + (size_t)b * NE_;
    float4 v = reinterpret_cast<const float4*>(Z2)[src * 128 + c4];
    reinterpret_cast<float4*>(ZK)[(size_t)row * 128 + c4] = v;
    float vv[4] = {v.x, v.y, v.z, v.w};
    __nv_bfloat16 h[4], l[4];
#pragma unroll
    for (int q = 0; q < 4; q++) {
        h[q] = __float2bfloat16(vv[q]);
        l[q] = __float2bfloat16(vv[q] - __bfloat162float(h[q]));
    }
    size_t o = (size_t)row * DD + c4 * 4;
    __nv_bfloat162 h01; h01.x = h[0]; h01.y = h[1];
    __nv_bfloat162 h23; h23.x = h[2]; h23.y = h[3];
    __nv_bfloat162 l01; l01.x = l[0]; l01.y = l[1];
    __nv_bfloat162 l23; l23.x = l[2]; l23.y = l[3];
    *reinterpret_cast<__nv_bfloat162*>(Ah + o)     = h01;
    *reinterpret_cast<__nv_bfloat162*>(Ah + o + 2) = h23;
    *reinterpret_cast<__nv_bfloat162*>(Al + o)     = l01;
    *reinterpret_cast<__nv_bfloat162*>(Al + o + 2) = l23;
}

__global__ void tanh_dot(const float* __restrict__ H, const float* __restrict__ W2,
                         const float* __restrict__ b2, float* __restrict__ sc)
{
    int row = blockIdx.x;
    int tid = threadIdx.x;   // 128
    __shared__ float red[128];
    float p = 0.f;
    for (int j = tid; j < DD; j += 128)
        p = fmaf(tanhf(H[(size_t)row * DD + j]), W2[j], p);
    red[tid] = p;
    __syncthreads();
    for (int s = 64; s > 0; s >>= 1) {
        if (tid < s) red[tid] += red[tid + s];
        __syncthreads();
    }
    if (tid == 0) sc[row] = red[0] + b2[0];
}

__global__ void readout2(const float* __restrict__ ZK, const float* __restrict__ sc,
                         const float* __restrict__ regW, const float* __restrict__ regb,
                         float* __restrict__ out)
{
    int b = blockIdx.x;
    int tid = threadIdx.x;   // 256
    __shared__ float w[KK];
    __shared__ float red[256];
    __shared__ float sm;
    if (tid < KK) w[tid] = sc[b * KK + tid];
    __syncthreads();
    if (tid == 0) {
        float m = w[0];
        for (int k = 1; k < KK; k++) m = fmaxf(m, w[k]);
        float s = 0.f;
        for (int k = 0; k < KK; k++) { w[k] = expf(w[k] - m); s += w[k]; }
        sm = s;
    }
    __syncthreads();
    int c0 = tid, c1 = tid + 256;
    float r0 = 0.f, r1 = 0.f;
    for (int k = 0; k < KK; k++) {
        const float* z = ZK + ((size_t)b * KK + k) * DD;
        float wk = w[k];
        r0 = fmaf(wk, z[c0], r0);
        r1 = fmaf(wk, z[c1], r1);
    }
    float part = (r0 * regW[c0] + r1 * regW[c1]) / sm;
    red[tid] = part;
    __syncthreads();
    for (int s = 128; s > 0; s >>= 1) {
        if (tid < s) red[tid] += red[tid + s];
        __syncthreads();
    }
    if (tid == 0) out[b] = red[0] + regb[0];
}

// ------------------------- host side ------------------------------------------
static const int HG_SMEM = 2 * 40960;

extern "C" void kernel_launch(void* const* d_in, const int* in_sizes, int n_in,
                              void* d_out, int out_size)
{
    int map_[31];
    {
        int p = 0;
        for (int l = 0; l < 31; l++) {
            if (l == 5 || l == 8) {
                bool present = (n_in == 31);
                if (present && p < n_in && in_sizes[p] == 1) map_[l] = p++;
                else map_[l] = -1;
            } else map_[l] = p++;
        }
    }
    auto F = [&](int l) -> const float* { return (const float*)d_in[map_[l]]; };
    auto I = [&](int l) -> const int*   { return (const int*)d_in[map_[l]]; };

    const float* x        = F(0);
    const float* pre_x    = F(1);
    const int*   edge_ei  = I(2);
    const int*   int_ei   = I(3);
    const float* name_emb = F(6);
    const float* desc_emb = F(7);
    const int*   bkm      = I(9);
    const float* name_W = F(11), *name_b = F(12);
    const float* desc_W = F(13), *desc_b = F(14);
    const float* omic_W = F(15), *omic_b = F(16);
    const float* fus_W  = F(17), *fus_b  = F(18);
    const float* pre_W  = F(19), *pre_b  = F(20);
    const float* ienc_W = F(21), *ienc_b = F(22);
    const float* enc_W  = F(23), *enc_b  = F(24);
    const float* gate_W1 = F(25), *gate_b1 = F(26);
    const float* gate_W2 = F(27), *gate_b2 = F(28);
    const float* reg_W   = F(29), *reg_b   = F(30);
    float* out = (float*)d_out;

    const int E_full = in_sizes[map_[2]] / 2;
    const int E_int  = in_sizes[map_[3]] / 2;
    const float* W2 = fus_W + (size_t)1536 * OM_;   // [511,511] row-major

    __nv_bfloat16 *pA1H, *pA1L, *pA2H, *pA2L, *pWH, *pWL, *pWFH, *pWFL, *pNDPH, *pNDPL;
    float *pNDP2, *pM, *pZ, *pZ2, *pZK, *pH, *pKO, *pSC;
    int *pCNT, *pOFF, *pCUR, *pSRT;
    cudaGetSymbolAddress((void**)&pA1H, g_A1H);
    cudaGetSymbolAddress((void**)&pA1L, g_A1L);
    cudaGetSymbolAddress((void**)&pA2H, g_A2H);
    cudaGetSymbolAddress((void**)&pA2L, g_A2L);
    cudaGetSymbolAddress((void**)&pWH,  g_WH);
    cudaGetSymbolAddress((void**)&pWL,  g_WL);
    cudaGetSymbolAddress((void**)&pWFH, g_WFH);
    cudaGetSymbolAddress((void**)&pWFL, g_WFL);
    cudaGetSymbolAddress((void**)&pNDPH, g_NDPH);
    cudaGetSymbolAddress((void**)&pNDPL, g_NDPL);
    cudaGetSymbolAddress((void**)&pNDP2, g_NDP2);
    cudaGetSymbolAddress((void**)&pM,   g_M);
    cudaGetSymbolAddress((void**)&pZ,   g_Z);
    cudaGetSymbolAddress((void**)&pZ2,  g_Z2);
    cudaGetSymbolAddress((void**)&pZK,  g_ZK);
    cudaGetSymbolAddress((void**)&pH,   g_H);
    cudaGetSymbolAddress((void**)&pKO,  g_KO);
    cudaGetSymbolAddress((void**)&pSC,  g_SC);
    cudaGetSymbolAddress((void**)&pCNT, g_CNT);
    cudaGetSymbolAddress((void**)&pOFF, g_OFF);
    cudaGetSymbolAddress((void**)&pCUR, g_CUR);
    cudaGetSymbolAddress((void**)&pSRT, g_SRT);

    cudaFuncSetAttribute(hgemm, cudaFuncAttributeMaxDynamicSharedMemorySize, HG_SMEM);

    // weight region offsets
    const long OFF_NAME  = 0;
    const long OFF_DESC  = OFF_NAME  + 768L * 768;
    const long OFF_FUS1  = OFF_DESC  + 768L * 768;
    const long OFF_OMIC  = OFF_FUS1  + 512L * 1536;
    const long OFF_IENC2 = OFF_OMIC  + 512L * 512;
    const long OFF_W2D   = OFF_IENC2 + 512L * 512;
    const long OFF_PRE   = OFF_W2D   + 512L * 512;
    const long OFF_ENC   = OFF_PRE   + 512L * 512;
    const long OFF_GATE  = OFF_ENC   + 512L * 512;

    // 1) KO + CSR builds (both graphs) + weight conversion
    zero_f<<<(NN + 255) / 256, 256>>>(pKO, NN);
    set_ko<<<(BB * KK + 255) / 256, 256>>>(bkm, pKO);
    zero_i<<<(2 * NN + 255) / 256, 256>>>(pCNT, 2 * NN);
    csr_count2<<<(E_int + E_full + 255) / 256, 256>>>(int_ei, E_int, edge_ei, E_full, pCNT);
    csr_scan2<<<2, 1024>>>(pCNT, pOFF, pCUR, E_int);
    csr_fill2<<<(E_int + E_full + 255) / 256, 256>>>(int_ei, E_int, edge_ei, E_full, pCUR, pSRT);

    {
        WJobs jb;
        const float* Ws[9] = {name_W, desc_W, fus_W, omic_W, ienc_W, W2, pre_W, enc_W, gate_W1};
        int Ks[9]  = {TX_, TX_, 1536, OM_, OM_, OM_, OM_, DD, DD};
        int Ns[9]  = {TX_, TX_, OM_, OM_, DD, OM_, DD, DD, DD};
        int ldw[9] = {TX_, TX_, OM_, OM_, DD, OM_, DD, DD, DD};
        int ldo[9] = {TX_, TX_, 1536, 512, 512, 512, 512, 512, 512};
        int Np[9]  = {TX_, TX_, 512, 512, 512, 512, 512, 512, 512};
        int tr[9]  = {1, 1, 1, 1, 1, 0, 1, 1, 1};
        long offs[9] = {OFF_NAME, OFF_DESC, OFF_FUS1, OFF_OMIC, OFF_IENC2,
                        OFF_W2D, OFF_PRE, OFF_ENC, OFF_GATE};
        long cum = 0;
        jb.njobs = 9;
        for (int j = 0; j < 9; j++) {
            jb.W[j] = Ws[j]; jb.K[j] = Ks[j]; jb.N[j] = Ns[j];
            jb.ldw[j] = ldw[j]; jb.ldo[j] = ldo[j]; jb.trans[j] = tr[j];
            jb.off[j] = offs[j];
            jb.cum[j] = cum; cum += (long)Np[j] * ldo[j];
        }
        jb.cum[9] = cum;
        cvt_splitW_all<<<(int)((cum + 255) / 256), 256>>>(jb, pWH, pWL);
    }

    // 2) WFT = (W2 @ Wienc')^T  : A = ienc2 split, B = W2 direct split
    hgemm<<<dim3(4, 4), 256, HG_SMEM>>>(pWH + OFF_IENC2, pWL + OFF_IENC2,
        pWH + OFF_W2D, pWL + OFF_W2D,
        nullptr, nullptr, nullptr, nullptr, nullptr, nullptr, pWFH, pWFL,
        512, 512, 16, OM_, 0, 512, 512, 8 | 16);

    // 3) name/desc emb -> split A1 ; linears -> split A2 [1024 x 1536]
    cvt_splitA<<<(NE_ * 384 + 255) / 256, 256>>>(name_emb, NE_, TX_, TX_, TX_, pA1H, pA1L);
    cvt_splitA<<<(NE_ * 384 + 255) / 256, 256>>>(desc_emb, NE_, TX_, TX_, TX_,
                                                 pA1H + (size_t)NE_ * TX_,
                                                 pA1L + (size_t)NE_ * TX_);
    hgemm<<<dim3(6, 8), 256, HG_SMEM>>>(pA1H, pA1L, pWH + OFF_NAME, pWL + OFF_NAME,
        name_b, nullptr, nullptr, nullptr, nullptr, nullptr, pA2H, pA2L,
        TX_, TX_, 24, TX_, 0, 1536, TX_, 1 | 8 | 16);
    hgemm<<<dim3(6, 8), 256, HG_SMEM>>>(pA1H + (size_t)NE_ * TX_, pA1L + (size_t)NE_ * TX_,
        pWH + OFF_DESC, pWL + OFF_DESC,
        desc_b, nullptr, nullptr, nullptr, nullptr, nullptr, pA2H + TX_, pA2L + TX_,
        TX_, TX_, 24, TX_, 0, 1536, TX_, 1 | 8 | 16);

    // 4) ndpart = A2 @ fus_W[0:1536] + fus_b -> split NDPH/L [1024, 511→512]
    hgemm<<<dim3(4, 8), 256, HG_SMEM>>>(pA2H, pA2L, pWH + OFF_FUS1, pWL + OFF_FUS1,
        fus_b, nullptr, nullptr, nullptr, nullptr, nullptr, pNDPH, pNDPL,
        1536, 1536, 48, OM_, 0, 512, 512, 8 | 16);

    // 5) NDP2 = ndpart @ Wienc' -> fp32 [1024, 512]
    hgemm<<<dim3(4, 8), 256, HG_SMEM>>>(pNDPH, pNDPL, pWH + OFF_IENC2, pWL + OFF_IENC2,
        nullptr, nullptr, nullptr, nullptr, nullptr, pNDP2, nullptr, nullptr,
        512, 512, 16, DD, 512, 0, 0, 0);

    // 6) x -> split A1 ; omic = leaky(x @ omic_W + b) -> split A2
    cvt_splitA<<<(NN * 256 + 255) / 256, 256>>>(x, NN, OM_, OM_, 512, pA1H, pA1L);
    hgemm<<<dim3(4, 128), 256, HG_SMEM>>>(pA1H, pA1L, pWH + OFF_OMIC, pWL + OFF_OMIC,
        omic_b, nullptr, nullptr, nullptr, nullptr, nullptr, pA2H, pA2L,
        512, 512, 16, OM_, 0, 512, 512, 1 | 8 | 16);

    // 7) pre_x -> split A1 (A1's x-copy no longer needed)
    cvt_splitA<<<(NN * 256 + 255) / 256, 256>>>(pre_x, NN, OM_, OM_, 512, pA1H, pA1L);

    // 8) ienc message (folded): M = omic @ WFT + NDP2[r%1024] + ko⊗w511  -> fp32
    hgemm<<<dim3(4, 128), 256, HG_SMEM>>>(pA2H, pA2L, pWFH, pWFL,
        nullptr, pNDP2, pKO, ienc_W + (size_t)511 * DD,
        nullptr, pM, nullptr, nullptr,
        512, 512, 16, DD, 512, 0, 0, 4 | 32);

    // 9) gconv(int) -> Z = leaky(M[r]+b+sum)+x_c
    gconv_gather<<<NN, 128>>>(pM, ienc_b, pOFF, pCNT, pSRT, x, pKO, pZ, 0);

    // 10) Z += pre_x @ pre_W' + pre_b + ko⊗preW[511] ; emit split -> A2
    hgemm<<<dim3(4, 128), 256, HG_SMEM>>>(pA1H, pA1L, pWH + OFF_PRE, pWL + OFF_PRE,
        pre_b, nullptr, pKO, pre_W + (size_t)511 * DD,
        pZ, pZ, pA2H, pA2L,
        512, 512, 16, DD, 512, 512, DD, 2 | 8 | 32);

    // 11) enc: M = Z @ enc_W ; gconv(full) -> Z2
    hgemm<<<dim3(4, 128), 256, HG_SMEM>>>(pA2H, pA2L, pWH + OFF_ENC, pWL + OFF_ENC,
        nullptr, nullptr, nullptr, nullptr, nullptr, pM, nullptr, nullptr,
        512, 512, 16, DD, 512, 0, 0, 0);
    gconv_gather<<<NN, 128>>>(pM, enc_b, pOFF + NN, pCNT + NN, pSRT,
                              nullptr, nullptr, pZ2, 1);

    // 12) readout
    gather_zk<<<(BB * KK * 128 + 255) / 256, 256>>>(pZ2, bkm, pZK, pA1H, pA1L);
    hgemm<<<dim3(4, 8), 256, HG_SMEM>>>(pA1H, pA1L, pWH + OFF_GATE, pWL + OFF_GATE,
        gate_b1, nullptr, nullptr, nullptr, nullptr, pH, nullptr, nullptr,
        512, 512, 16, DD, 512, 0, 0, 0);
    tanh_dot<<<BB * KK, 128>>>(pH, gate_W2, gate_b2, pSC);
    readout2<<<BB, 256>>>(pZK, pSC, reg_W, reg_b, out);

    (void)out_size;
    (void)n_in;
}

// round 7
// speedup vs baseline: 5.9335x; 1.1184x over previous
#include <cuda_runtime.h>
#include <cuda_bf16.h>
#include <cstdint>

#define NN      16384
#define NE_     1024
#define BB      16
#define KK      64
#define TX_     768
#define OM_     511
#define DD      512
#define SLOPE_  0.3f
#define E_INT_MAX 131072
#define E_FULL_MAX 262144

// ------------------------- helpers ------------------------------------------
__device__ __forceinline__ uint32_t smem_to_u32(const void* p) {
    uint32_t a;
    asm("{ .reg .u64 t; cvta.to.shared.u64 t, %1; cvt.u32.u64 %0, t; }"
        : "=r"(a) : "l"(p));
    return a;
}

#define CP_ASYNC16(saddr, gptr) \
    asm volatile("cp.async.cg.shared.global [%0], [%1], 16;" \
                 :: "r"(saddr), "l"(gptr) : "memory")

#define LDMX4(r0, r1, r2, r3, addr) \
    asm volatile("ldmatrix.sync.aligned.m8n8.x4.shared.b16 {%0,%1,%2,%3}, [%4];" \
                 : "=r"(r0), "=r"(r1), "=r"(r2), "=r"(r3) : "r"(addr))

#define MMA16816(c, a, b) \
    asm volatile("mma.sync.aligned.m16n8k16.row.col.f32.bf16.bf16.f32 " \
                 "{%0,%1,%2,%3},{%4,%5,%6,%7},{%8,%9},{%0,%1,%2,%3};" \
                 : "+f"((c)[0]), "+f"((c)[1]), "+f"((c)[2]), "+f"((c)[3]) \
                 : "r"((a)[0]), "r"((a)[1]), "r"((a)[2]), "r"((a)[3]), \
                   "r"((b)[0]), "r"((b)[1]))

// ------------------------- scratch (device globals) -------------------------
__device__ __nv_bfloat16 g_A1H[NN * DD];
__device__ __nv_bfloat16 g_A1L[NN * DD];
__device__ __nv_bfloat16 g_A2H[NN * DD];
__device__ __nv_bfloat16 g_A2L[NN * DD];
__device__ __nv_bfloat16 g_P1H[NN * DD];       // pre_x split (parallel chain)
__device__ __nv_bfloat16 g_P1L[NN * DD];
__device__ __nv_bfloat16 g_E1H[2048 * TX_];    // entity emb split (name|desc)
__device__ __nv_bfloat16 g_E1L[2048 * TX_];
__device__ __nv_bfloat16 g_E2H[NE_ * 1536];    // entity linears split
__device__ __nv_bfloat16 g_E2L[NE_ * 1536];
#define WT_TOTAL 3538944
__device__ __nv_bfloat16 g_WH[WT_TOTAL];
__device__ __nv_bfloat16 g_WL[WT_TOTAL];
__device__ __nv_bfloat16 g_WFH[DD * DD];       // WFT split
__device__ __nv_bfloat16 g_WFL[DD * DD];
__device__ __nv_bfloat16 g_NDPH[NE_ * DD];     // ndpart split
__device__ __nv_bfloat16 g_NDPL[NE_ * DD];
__device__ float g_NDP2[NE_ * DD];             // ndpart @ Wienc'
__device__ float g_M  [NN * DD];
__device__ float g_Z  [NN * DD];
__device__ float g_Z2 [NN * DD];
__device__ float g_ZK [NE_ * DD];
__device__ float g_H  [NE_ * DD];
__device__ float g_KO [NN];
__device__ float g_SC [BB * KK];
__device__ int   g_CNT[2 * NN];
__device__ int   g_OFF[2 * NN];
__device__ int   g_CUR[2 * NN];
__device__ int   g_SRT[E_INT_MAX + E_FULL_MAX];

// ============================================================================
// HMMA split-bf16 GEMM (unchanged core from R6)
// flags: 1 leaky, 2 accumulate (+Cin), 4 add gat[(row&1023)*512+col],
//        8 write split-bf16 (Oh/Ol stride ldo, zero-pad cols [Nc,padN)),
//        16 skip fp32 C write, 32 add koV[row]*w511[col]
// ============================================================================
__global__ void __launch_bounds__(256, 2)
hgemm(const __nv_bfloat16* __restrict__ Ah, const __nv_bfloat16* __restrict__ Al,
      const __nv_bfloat16* __restrict__ Bh, const __nv_bfloat16* __restrict__ Bl,
      const float* __restrict__ bias, const float* __restrict__ gat,
      const float* __restrict__ koV, const float* __restrict__ w511,
      const float* __restrict__ Cin, float* __restrict__ C,
      __nv_bfloat16* __restrict__ Oh, __nv_bfloat16* __restrict__ Ol,
      int lda_b, int ldb_b, int nchunks, int Nc, int ldc, int ldo,
      int padN, int flags)
{
    extern __shared__ char smem[];
    const uint32_t sb = smem_to_u32(smem);
    const int tid  = threadIdx.x;
    const int lane = tid & 31;
    const int wid  = tid >> 5;
    const int wm   = (wid >> 2) * 64;
    const int wn   = (wid & 3) * 32;
    const int bm   = blockIdx.y * 128;
    const int bn   = blockIdx.x * 128;

    float acc[4][4][4];
#pragma unroll
    for (int i = 0; i < 4; i++)
#pragma unroll
        for (int j = 0; j < 4; j++)
#pragma unroll
            for (int q = 0; q < 4; q++) acc[i][j][q] = 0.f;

    auto load_stage = [&](int st, int k0) {
        const uint32_t base = sb + st * 40960;
#pragma unroll
        for (int i = 0; i < 2; i++) {
            const int idx = tid + i * 256;
            const int row = idx >> 2;
            const int c16 = idx & 3;
            const uint32_t so = base + row * 80 + c16 * 16;
            const size_t ga = (size_t)(bm + row) * lda_b + k0 + c16 * 8;
            const size_t gb = (size_t)(bn + row) * ldb_b + k0 + c16 * 8;
            CP_ASYNC16(so,          Ah + ga);
            CP_ASYNC16(so + 10240,  Al + ga);
            CP_ASYNC16(so + 20480,  Bh + gb);
            CP_ASYNC16(so + 30720,  Bl + gb);
        }
        asm volatile("cp.async.commit_group;" ::: "memory");
    };

    auto compute = [&](int st) {
        const uint32_t base = sb + st * 40960;
        const int arow = lane & 15;
        const int asub = (lane >> 4) * 8;
        const int brow = (lane & 7) + (lane >> 4) * 8;
        const int bsub = ((lane >> 3) & 1) * 8;
#pragma unroll
        for (int ks = 0; ks < 2; ks++) {
            const int kb = ks * 16;
            const uint32_t a0 = base + ((wm + arow) * 40 + kb + asub) * 2;
            const uint32_t b0 = base + 20480 + ((wn + brow) * 40 + kb + bsub) * 2;

            uint32_t ah[4][4], bh[4][2];
#pragma unroll
            for (int mt = 0; mt < 4; mt++)
                LDMX4(ah[mt][0], ah[mt][1], ah[mt][2], ah[mt][3], a0 + mt * 16 * 80);
#pragma unroll
            for (int p = 0; p < 2; p++)
                LDMX4(bh[2*p][0], bh[2*p][1], bh[2*p+1][0], bh[2*p+1][1],
                      b0 + p * 16 * 80);
#pragma unroll
            for (int mt = 0; mt < 4; mt++)
#pragma unroll
                for (int nt = 0; nt < 4; nt++)
                    MMA16816(acc[mt][nt], ah[mt], bh[nt]);
#pragma unroll
            for (int p = 0; p < 2; p++) {
                uint32_t bl[2][2];
                LDMX4(bl[0][0], bl[0][1], bl[1][0], bl[1][1],
                      b0 + 10240 + p * 16 * 80);
#pragma unroll
                for (int mt = 0; mt < 4; mt++) {
                    MMA16816(acc[mt][2*p],   ah[mt], bl[0]);
                    MMA16816(acc[mt][2*p+1], ah[mt], bl[1]);
                }
            }
#pragma unroll
            for (int mt = 0; mt < 4; mt++) {
                uint32_t al[4];
                LDMX4(al[0], al[1], al[2], al[3], a0 + 10240 + mt * 16 * 80);
#pragma unroll
                for (int nt = 0; nt < 4; nt++)
                    MMA16816(acc[mt][nt], al, bh[nt]);
            }
        }
    };

    load_stage(0, 0);
    for (int c = 0; c < nchunks; c++) {
        if (c + 1 < nchunks) {
            load_stage((c + 1) & 1, (c + 1) * 32);
            asm volatile("cp.async.wait_group 1;" ::: "memory");
        } else {
            asm volatile("cp.async.wait_group 0;" ::: "memory");
        }
        __syncthreads();
        compute(c & 1);
        __syncthreads();
    }

    // ---- epilogue ----
    const int er = lane >> 2;
    const int ec = (lane & 3) * 2;
#pragma unroll
    for (int mt = 0; mt < 4; mt++) {
#pragma unroll
        for (int h = 0; h < 2; h++) {
            const int row = bm + wm + mt * 16 + er + h * 8;
            const size_t crow = (size_t)row * ldc;
            const size_t orow = (size_t)row * ldo;
            const size_t grow = (size_t)(row & (NE_ - 1)) * 512;
            const float kv = (flags & 32) ? koV[row] : 0.f;
#pragma unroll
            for (int nt = 0; nt < 4; nt++) {
                const int col = bn + wn + nt * 8 + ec;
                float v0 = acc[mt][nt][h * 2 + 0];
                float v1 = acc[mt][nt][h * 2 + 1];
                if (col + 1 < Nc) {
                    if (bias) {
                        float2 bb = *reinterpret_cast<const float2*>(bias + col);
                        v0 += bb.x; v1 += bb.y;
                    }
                    if (flags & 4) {
                        float2 gg = *reinterpret_cast<const float2*>(gat + grow + col);
                        v0 += gg.x; v1 += gg.y;
                    }
                    if (flags & 32) {
                        float2 ww = *reinterpret_cast<const float2*>(w511 + col);
                        v0 += kv * ww.x; v1 += kv * ww.y;
                    }
                    if (flags & 1) {
                        v0 = v0 > 0.f ? v0 : SLOPE_ * v0;
                        v1 = v1 > 0.f ? v1 : SLOPE_ * v1;
                    }
                    if (flags & 2) {
                        float2 ci = *reinterpret_cast<const float2*>(Cin + crow + col);
                        v0 += ci.x; v1 += ci.y;
                    }
                    if (!(flags & 16))
                        *reinterpret_cast<float2*>(C + crow + col) = make_float2(v0, v1);
                    if (flags & 8) {
                        __nv_bfloat16 h0 = __float2bfloat16(v0);
                        __nv_bfloat16 h1 = __float2bfloat16(v1);
                        __nv_bfloat162 hh; hh.x = h0; hh.y = h1;
                        __nv_bfloat162 ll;
                        ll.x = __float2bfloat16(v0 - __bfloat162float(h0));
                        ll.y = __float2bfloat16(v1 - __bfloat162float(h1));
                        *reinterpret_cast<__nv_bfloat162*>(Oh + orow + col) = hh;
                        *reinterpret_cast<__nv_bfloat162*>(Ol + orow + col) = ll;
                    }
                } else {
                    float vv[2] = {v0, v1};
#pragma unroll
                    for (int q = 0; q < 2; q++) {
                        const int cq = col + q;
                        if (cq < Nc) {
                            float v = vv[q];
                            if (bias)       v += bias[cq];
                            if (flags & 4)  v += gat[grow + cq];
                            if (flags & 32) v += kv * w511[cq];
                            if (flags & 1)  v = v > 0.f ? v : SLOPE_ * v;
                            if (flags & 2)  v += Cin[crow + cq];
                            if (!(flags & 16)) C[crow + cq] = v;
                            if (flags & 8) {
                                __nv_bfloat16 hh = __float2bfloat16(v);
                                Oh[orow + cq] = hh;
                                Ol[orow + cq] = __float2bfloat16(v - __bfloat162float(hh));
                            }
                        } else if ((flags & 8) && cq < padN) {
                            Oh[orow + cq] = __float2bfloat16(0.f);
                            Ol[orow + cq] = __float2bfloat16(0.f);
                        }
                    }
                }
            }
        }
    }
}

// ------------------------- conversion kernels -------------------------------
__global__ void cvt_splitA(const float* __restrict__ A, int M, int K, int lda, int ldo,
                           __nv_bfloat16* __restrict__ Ah, __nv_bfloat16* __restrict__ Al)
{
    int i = blockIdx.x * blockDim.x + threadIdx.x;
    int half = ldo >> 1;
    int r = i / half;
    if (r >= M) return;
    int c2 = (i - r * half) * 2;
    float v0 = (c2 < K)     ? A[(size_t)r * lda + c2]     : 0.f;
    float v1 = (c2 + 1 < K) ? A[(size_t)r * lda + c2 + 1] : 0.f;
    __nv_bfloat16 h0 = __float2bfloat16(v0), h1 = __float2bfloat16(v1);
    __nv_bfloat16 l0 = __float2bfloat16(v0 - __bfloat162float(h0));
    __nv_bfloat16 l1 = __float2bfloat16(v1 - __bfloat162float(h1));
    __nv_bfloat162 hh; hh.x = h0; hh.y = h1;
    __nv_bfloat162 ll; ll.x = l0; ll.y = l1;
    *reinterpret_cast<__nv_bfloat162*>(Ah + (size_t)r * ldo + c2) = hh;
    *reinterpret_cast<__nv_bfloat162*>(Al + (size_t)r * ldo + c2) = ll;
}

struct WJobs {
    const float* W[9];
    long off[9];
    long cum[10];
    int K[9], N[9], ldw[9], ldo[9], trans[9];
    int njobs;
};

__global__ void cvt_splitW_all(WJobs jobs,
                               __nv_bfloat16* __restrict__ Wh,
                               __nv_bfloat16* __restrict__ Wl)
{
    long gid = (long)blockIdx.x * blockDim.x + threadIdx.x;
    if (gid >= jobs.cum[jobs.njobs]) return;
    int j = 0;
    while (gid >= jobs.cum[j + 1]) j++;
    long local = gid - jobs.cum[j];
    int ldo = jobs.ldo[j];
    int n = (int)(local / ldo);
    int k = (int)(local - (long)n * ldo);
    float v = 0.f;
    if (n < jobs.N[j] && k < jobs.K[j])
        v = jobs.trans[j] ? jobs.W[j][(size_t)k * jobs.ldw[j] + n]
                          : jobs.W[j][(size_t)n * jobs.ldw[j] + k];
    __nv_bfloat16 h = __float2bfloat16(v);
    Wh[jobs.off[j] + local] = h;
    Wl[jobs.off[j] + local] = __float2bfloat16(v - __bfloat162float(h));
}

// ------------------------- misc ----------------------------------------------
__global__ void zero_f(float* __restrict__ p, int n)
{ int i = blockIdx.x * blockDim.x + threadIdx.x; if (i < n) p[i] = 0.f; }
__global__ void zero_i(int* __restrict__ p, int n)
{ int i = blockIdx.x * blockDim.x + threadIdx.x; if (i < n) p[i] = 0; }

__global__ void set_ko(const int* __restrict__ bkm, float* __restrict__ ko)
{
    int i = blockIdx.x * blockDim.x + threadIdx.x;
    if (i < BB * KK) ko[(i >> 6) * NE_ + bkm[i]] = 1.0f;
}

// ------------------------- CSR build -----------------------------------------
__global__ void csr_count2(const int* __restrict__ iei, int Ei,
                           const int* __restrict__ fei, int Ef,
                           int* __restrict__ cnt)
{
    int i = blockIdx.x * blockDim.x + threadIdx.x;
    if (i < Ei) atomicAdd(&cnt[iei[Ei + i]], 1);
    else if (i < Ei + Ef) {
        int j = i - Ei;
        atomicAdd(&cnt[NN + fei[Ef + j]], 1);
    }
}

__global__ void __launch_bounds__(1024, 1)
csr_scan2(const int* __restrict__ cnt, int* __restrict__ off,
          int* __restrict__ cur, int base1)
{
    __shared__ int sa[1024], sbuf[1024];
    const int g = blockIdx.x;
    const int* c = cnt + g * NN;
    int* o = off + g * NN;
    int* u = cur + g * NN;
    int t = threadIdx.x;
    int base = t * 16;
    int loc[16];
    int s = 0;
#pragma unroll
    for (int j = 0; j < 16; j++) { loc[j] = c[base + j]; s += loc[j]; }
    sa[t] = s;
    __syncthreads();
    int* A = sa; int* Bf = sbuf;
    for (int d = 1; d < 1024; d <<= 1) {
        int v = A[t] + (t >= d ? A[t - d] : 0);
        __syncthreads();
        Bf[t] = v;
        __syncthreads();
        int* tmp = A; A = Bf; Bf = tmp;
    }
    int run = (t ? A[t - 1] : 0) + (g ? base1 : 0);
#pragma unroll
    for (int j = 0; j < 16; j++) { o[base + j] = run; u[base + j] = run; run += loc[j]; }
}

__global__ void csr_fill2(const int* __restrict__ iei, int Ei,
                          const int* __restrict__ fei, int Ef,
                          int* __restrict__ cur, int* __restrict__ srt)
{
    int i = blockIdx.x * blockDim.x + threadIdx.x;
    if (i < Ei) {
        int p = atomicAdd(&cur[iei[Ei + i]], 1);
        srt[p] = iei[i];
    } else if (i < Ei + Ef) {
        int j = i - Ei;
        int p = atomicAdd(&cur[NN + fei[Ef + j]], 1);
        srt[p] = fei[j];
    }
}

// gconv aggregate + epilogue
__global__ void __launch_bounds__(128, 8)
gconv_gather(const float* __restrict__ m, const float* __restrict__ bias,
             const int* __restrict__ off, const int* __restrict__ cnt,
             const int* __restrict__ srt,
             const float* __restrict__ x, const float* __restrict__ ko,
             float* __restrict__ out, int mode)
{
    const int r = blockIdx.x;
    const int t = threadIdx.x;
    float4 acc = reinterpret_cast<const float4*>(m + (size_t)r * DD)[t];
    float4 b   = reinterpret_cast<const float4*>(bias)[t];
    acc.x += b.x; acc.y += b.y; acc.z += b.z; acc.w += b.w;
    const int s0 = off[r];
    const int d  = cnt[r];
    for (int e = 0; e < d; e++) {
        int s = srt[s0 + e];
        float4 v = reinterpret_cast<const float4*>(m + (size_t)s * DD)[t];
        acc.x += v.x; acc.y += v.y; acc.z += v.z; acc.w += v.w;
    }
    acc.x = acc.x > 0.f ? acc.x : SLOPE_ * acc.x;
    acc.y = acc.y > 0.f ? acc.y : SLOPE_ * acc.y;
    acc.z = acc.z > 0.f ? acc.z : SLOPE_ * acc.z;
    acc.w = acc.w > 0.f ? acc.w : SLOPE_ * acc.w;
    if (mode == 0) {
        const int c0 = t * 4;
        float add[4];
#pragma unroll
        for (int q = 0; q < 4; q++) {
            int c = c0 + q;
            add[q] = (c < OM_) ? x[(size_t)r * OM_ + c] : ko[r];
        }
        acc.x += add[0]; acc.y += add[1]; acc.z += add[2]; acc.w += add[3];
    }
    reinterpret_cast<float4*>(out + (size_t)r * DD)[t] = acc;
}

// ------------------------- readout -------------------------------------------
__global__ void gather_zk(const float* __restrict__ Z2, const int* __restrict__ bkm,
                          float* __restrict__ ZK,
                          __nv_bfloat16* __restrict__ Ah, __nv_bfloat16* __restrict__ Al)
{
    int i = blockIdx.x * blockDim.x + threadIdx.x;
    if (i >= BB * KK * 128) return;
    int row = i >> 7, c4 = i & 127;
    int b = row >> 6;
    size_t src = (size_t)bkm[row] + (size_t)b * NE_;
    float4 v = reinterpret_cast<const float4*>(Z2)[src * 128 + c4];
    reinterpret_cast<float4*>(ZK)[(size_t)row * 128 + c4] = v;
    float vv[4] = {v.x, v.y, v.z, v.w};
    __nv_bfloat16 h[4], l[4];
#pragma unroll
    for (int q = 0; q < 4; q++) {
        h[q] = __float2bfloat16(vv[q]);
        l[q] = __float2bfloat16(vv[q] - __bfloat162float(h[q]));
    }
    size_t o = (size_t)row * DD + c4 * 4;
    __nv_bfloat162 h01; h01.x = h[0]; h01.y = h[1];
    __nv_bfloat162 h23; h23.x = h[2]; h23.y = h[3];
    __nv_bfloat162 l01; l01.x = l[0]; l01.y = l[1];
    __nv_bfloat162 l23; l23.x = l[2]; l23.y = l[3];
    *reinterpret_cast<__nv_bfloat162*>(Ah + o)     = h01;
    *reinterpret_cast<__nv_bfloat162*>(Ah + o + 2) = h23;
    *reinterpret_cast<__nv_bfloat162*>(Al + o)     = l01;
    *reinterpret_cast<__nv_bfloat162*>(Al + o + 2) = l23;
}

__global__ void tanh_dot(const float* __restrict__ H, const float* __restrict__ W2,
                         const float* __restrict__ b2, float* __restrict__ sc)
{
    int row = blockIdx.x;
    int tid = threadIdx.x;
    __shared__ float red[128];
    float p = 0.f;
    for (int j = tid; j < DD; j += 128)
        p = fmaf(tanhf(H[(size_t)row * DD + j]), W2[j], p);
    red[tid] = p;
    __syncthreads();
    for (int s = 64; s > 0; s >>= 1) {
        if (tid < s) red[tid] += red[tid + s];
        __syncthreads();
    }
    if (tid == 0) sc[row] = red[0] + b2[0];
}

__global__ void readout2(const float* __restrict__ ZK, const float* __restrict__ sc,
                         const float* __restrict__ regW, const float* __restrict__ regb,
                         float* __restrict__ out)
{
    int b = blockIdx.x;
    int tid = threadIdx.x;
    __shared__ float w[KK];
    __shared__ float red[256];
    __shared__ float sm;
    if (tid < KK) w[tid] = sc[b * KK + tid];
    __syncthreads();
    if (tid == 0) {
        float m = w[0];
        for (int k = 1; k < KK; k++) m = fmaxf(m, w[k]);
        float s = 0.f;
        for (int k = 0; k < KK; k++) { w[k] = expf(w[k] - m); s += w[k]; }
        sm = s;
    }
    __syncthreads();
    int c0 = tid, c1 = tid + 256;
    float r0 = 0.f, r1 = 0.f;
    for (int k = 0; k < KK; k++) {
        const float* z = ZK + ((size_t)b * KK + k) * DD;
        float wk = w[k];
        r0 = fmaf(wk, z[c0], r0);
        r1 = fmaf(wk, z[c1], r1);
    }
    float part = (r0 * regW[c0] + r1 * regW[c1]) / sm;
    red[tid] = part;
    __syncthreads();
    for (int s = 128; s > 0; s >>= 1) {
        if (tid < s) red[tid] += red[tid + s];
        __syncthreads();
    }
    if (tid == 0) out[b] = red[0] + regb[0];
}

// ------------------------- host side ------------------------------------------
static const int HG_SMEM = 2 * 40960;

extern "C" void kernel_launch(void* const* d_in, const int* in_sizes, int n_in,
                              void* d_out, int out_size)
{
    int map_[31];
    {
        int p = 0;
        for (int l = 0; l < 31; l++) {
            if (l == 5 || l == 8) {
                bool present = (n_in == 31);
                if (present && p < n_in && in_sizes[p] == 1) map_[l] = p++;
                else map_[l] = -1;
            } else map_[l] = p++;
        }
    }
    auto F = [&](int l) -> const float* { return (const float*)d_in[map_[l]]; };
    auto I = [&](int l) -> const int*   { return (const int*)d_in[map_[l]]; };

    const float* x        = F(0);
    const float* pre_x    = F(1);
    const int*   edge_ei  = I(2);
    const int*   int_ei   = I(3);
    const float* name_emb = F(6);
    const float* desc_emb = F(7);
    const int*   bkm      = I(9);
    const float* name_W = F(11), *name_b = F(12);
    const float* desc_W = F(13), *desc_b = F(14);
    const float* omic_W = F(15), *omic_b = F(16);
    const float* fus_W  = F(17), *fus_b  = F(18);
    const float* pre_W  = F(19), *pre_b  = F(20);
    const float* ienc_W = F(21), *ienc_b = F(22);
    const float* enc_W  = F(23), *enc_b  = F(24);
    const float* gate_W1 = F(25), *gate_b1 = F(26);
    const float* gate_W2 = F(27), *gate_b2 = F(28);
    const float* reg_W   = F(29), *reg_b   = F(30);
    float* out = (float*)d_out;

    const int E_full = in_sizes[map_[2]] / 2;
    const int E_int  = in_sizes[map_[3]] / 2;
    const float* W2 = fus_W + (size_t)1536 * OM_;

    __nv_bfloat16 *pA1H, *pA1L, *pA2H, *pA2L, *pP1H, *pP1L, *pE1H, *pE1L, *pE2H, *pE2L;
    __nv_bfloat16 *pWH, *pWL, *pWFH, *pWFL, *pNDPH, *pNDPL;
    float *pNDP2, *pM, *pZ, *pZ2, *pZK, *pH, *pKO, *pSC;
    int *pCNT, *pOFF, *pCUR, *pSRT;
    cudaGetSymbolAddress((void**)&pA1H, g_A1H);
    cudaGetSymbolAddress((void**)&pA1L, g_A1L);
    cudaGetSymbolAddress((void**)&pA2H, g_A2H);
    cudaGetSymbolAddress((void**)&pA2L, g_A2L);
    cudaGetSymbolAddress((void**)&pP1H, g_P1H);
    cudaGetSymbolAddress((void**)&pP1L, g_P1L);
    cudaGetSymbolAddress((void**)&pE1H, g_E1H);
    cudaGetSymbolAddress((void**)&pE1L, g_E1L);
    cudaGetSymbolAddress((void**)&pE2H, g_E2H);
    cudaGetSymbolAddress((void**)&pE2L, g_E2L);
    cudaGetSymbolAddress((void**)&pWH,  g_WH);
    cudaGetSymbolAddress((void**)&pWL,  g_WL);
    cudaGetSymbolAddress((void**)&pWFH, g_WFH);
    cudaGetSymbolAddress((void**)&pWFL, g_WFL);
    cudaGetSymbolAddress((void**)&pNDPH, g_NDPH);
    cudaGetSymbolAddress((void**)&pNDPL, g_NDPL);
    cudaGetSymbolAddress((void**)&pNDP2, g_NDP2);
    cudaGetSymbolAddress((void**)&pM,   g_M);
    cudaGetSymbolAddress((void**)&pZ,   g_Z);
    cudaGetSymbolAddress((void**)&pZ2,  g_Z2);
    cudaGetSymbolAddress((void**)&pZK,  g_ZK);
    cudaGetSymbolAddress((void**)&pH,   g_H);
    cudaGetSymbolAddress((void**)&pKO,  g_KO);
    cudaGetSymbolAddress((void**)&pSC,  g_SC);
    cudaGetSymbolAddress((void**)&pCNT, g_CNT);
    cudaGetSymbolAddress((void**)&pOFF, g_OFF);
    cudaGetSymbolAddress((void**)&pCUR, g_CUR);
    cudaGetSymbolAddress((void**)&pSRT, g_SRT);

    cudaFuncSetAttribute(hgemm, cudaFuncAttributeMaxDynamicSharedMemorySize, HG_SMEM);

    const long OFF_NAME  = 0;
    const long OFF_DESC  = OFF_NAME  + 768L * 768;
    const long OFF_FUS1  = OFF_DESC  + 768L * 768;
    const long OFF_OMIC  = OFF_FUS1  + 512L * 1536;
    const long OFF_IENC2 = OFF_OMIC  + 512L * 512;
    const long OFF_W2D   = OFF_IENC2 + 512L * 512;
    const long OFF_PRE   = OFF_W2D   + 512L * 512;
    const long OFF_ENC   = OFF_PRE   + 512L * 512;
    const long OFF_GATE  = OFF_ENC   + 512L * 512;

    // ---- streams & events (host objects; created per call; destroyed only
    //      when not capturing — destroying a capturing stream breaks capture)
    cudaStream_t s1, s2;
    cudaStreamCreateWithFlags(&s1, cudaStreamNonBlocking);
    cudaStreamCreateWithFlags(&s2, cudaStreamNonBlocking);
    cudaEvent_t evStart, evW, ev1, ev2;
    cudaEventCreateWithFlags(&evStart, cudaEventDisableTiming);
    cudaEventCreateWithFlags(&evW,     cudaEventDisableTiming);
    cudaEventCreateWithFlags(&ev1,     cudaEventDisableTiming);
    cudaEventCreateWithFlags(&ev2,     cudaEventDisableTiming);

    // fork s2 off capture stream immediately
    cudaEventRecord(evStart, 0);
    cudaStreamWaitEvent(s2, evStart, 0);

    // ---------------- s2: KO + CSR + pre_x split -------------------------
    zero_f<<<(NN + 255) / 256, 256, 0, s2>>>(pKO, NN);
    set_ko<<<(BB * KK + 255) / 256, 256, 0, s2>>>(bkm, pKO);
    zero_i<<<(2 * NN + 255) / 256, 256, 0, s2>>>(pCNT, 2 * NN);
    csr_count2<<<(E_int + E_full + 255) / 256, 256, 0, s2>>>(int_ei, E_int, edge_ei, E_full, pCNT);
    csr_scan2<<<2, 1024, 0, s2>>>(pCNT, pOFF, pCUR, E_int);
    csr_fill2<<<(E_int + E_full + 255) / 256, 256, 0, s2>>>(int_ei, E_int, edge_ei, E_full, pCUR, pSRT);
    cvt_splitA<<<(NN * 256 + 255) / 256, 256, 0, s2>>>(pre_x, NN, OM_, OM_, 512, pP1H, pP1L);
    cudaEventRecord(ev2, s2);

    // ---------------- s0: weight conversion ------------------------------
    {
        WJobs jb;
        const float* Ws[9] = {name_W, desc_W, fus_W, omic_W, ienc_W, W2, pre_W, enc_W, gate_W1};
        int Ks[9]  = {TX_, TX_, 1536, OM_, OM_, OM_, OM_, DD, DD};
        int Ns[9]  = {TX_, TX_, OM_, OM_, DD, OM_, DD, DD, DD};
        int ldw[9] = {TX_, TX_, OM_, OM_, DD, OM_, DD, DD, DD};
        int ldo[9] = {TX_, TX_, 1536, 512, 512, 512, 512, 512, 512};
        int Np[9]  = {TX_, TX_, 512, 512, 512, 512, 512, 512, 512};
        int tr[9]  = {1, 1, 1, 1, 1, 0, 1, 1, 1};
        long offs[9] = {OFF_NAME, OFF_DESC, OFF_FUS1, OFF_OMIC, OFF_IENC2,
                        OFF_W2D, OFF_PRE, OFF_ENC, OFF_GATE};
        long cum = 0;
        jb.njobs = 9;
        for (int j = 0; j < 9; j++) {
            jb.W[j] = Ws[j]; jb.K[j] = Ks[j]; jb.N[j] = Ns[j];
            jb.ldw[j] = ldw[j]; jb.ldo[j] = ldo[j]; jb.trans[j] = tr[j];
            jb.off[j] = offs[j];
            jb.cum[j] = cum; cum += (long)Np[j] * ldo[j];
        }
        jb.cum[9] = cum;
        cvt_splitW_all<<<(int)((cum + 255) / 256), 256>>>(jb, pWH, pWL);
    }
    cudaEventRecord(evW, 0);

    // ---------------- s1: WFT + entity chain -----------------------------
    cudaStreamWaitEvent(s1, evW, 0);
    // WFT = (W2 @ Wienc')^T
    hgemm<<<dim3(4, 4), 256, HG_SMEM, s1>>>(pWH + OFF_IENC2, pWL + OFF_IENC2,
        pWH + OFF_W2D, pWL + OFF_W2D,
        nullptr, nullptr, nullptr, nullptr, nullptr, nullptr, pWFH, pWFL,
        512, 512, 16, OM_, 0, 512, 512, 8 | 16);
    cvt_splitA<<<(NE_ * 384 + 255) / 256, 256, 0, s1>>>(name_emb, NE_, TX_, TX_, TX_, pE1H, pE1L);
    cvt_splitA<<<(NE_ * 384 + 255) / 256, 256, 0, s1>>>(desc_emb, NE_, TX_, TX_, TX_,
                                                        pE1H + (size_t)NE_ * TX_,
                                                        pE1L + (size_t)NE_ * TX_);
    hgemm<<<dim3(6, 8), 256, HG_SMEM, s1>>>(pE1H, pE1L, pWH + OFF_NAME, pWL + OFF_NAME,
        name_b, nullptr, nullptr, nullptr, nullptr, nullptr, pE2H, pE2L,
        TX_, TX_, 24, TX_, 0, 1536, TX_, 1 | 8 | 16);
    hgemm<<<dim3(6, 8), 256, HG_SMEM, s1>>>(pE1H + (size_t)NE_ * TX_, pE1L + (size_t)NE_ * TX_,
        pWH + OFF_DESC, pWL + OFF_DESC,
        desc_b, nullptr, nullptr, nullptr, nullptr, nullptr, pE2H + TX_, pE2L + TX_,
        TX_, TX_, 24, TX_, 0, 1536, TX_, 1 | 8 | 16);
    hgemm<<<dim3(4, 8), 256, HG_SMEM, s1>>>(pE2H, pE2L, pWH + OFF_FUS1, pWL + OFF_FUS1,
        fus_b, nullptr, nullptr, nullptr, nullptr, nullptr, pNDPH, pNDPL,
        1536, 1536, 48, OM_, 0, 512, 512, 8 | 16);
    hgemm<<<dim3(4, 8), 256, HG_SMEM, s1>>>(pNDPH, pNDPL, pWH + OFF_IENC2, pWL + OFF_IENC2,
        nullptr, nullptr, nullptr, nullptr, nullptr, pNDP2, nullptr, nullptr,
        512, 512, 16, DD, 512, 0, 0, 0);
    cudaEventRecord(ev1, s1);

    // ---------------- s0: omic chain + joined tail ------------------------
    cvt_splitA<<<(NN * 256 + 255) / 256, 256>>>(x, NN, OM_, OM_, 512, pA1H, pA1L);
    hgemm<<<dim3(4, 128), 256, HG_SMEM>>>(pA1H, pA1L, pWH + OFF_OMIC, pWL + OFF_OMIC,
        omic_b, nullptr, nullptr, nullptr, nullptr, nullptr, pA2H, pA2L,
        512, 512, 16, OM_, 0, 512, 512, 1 | 8 | 16);

    cudaStreamWaitEvent(0, ev1, 0);
    cudaStreamWaitEvent(0, ev2, 0);

    // ienc message (folded): M = omic @ WFT + NDP2[r%1024] + ko⊗w511
    hgemm<<<dim3(4, 128), 256, HG_SMEM>>>(pA2H, pA2L, pWFH, pWFL,
        nullptr, pNDP2, pKO, ienc_W + (size_t)511 * DD,
        nullptr, pM, nullptr, nullptr,
        512, 512, 16, DD, 512, 0, 0, 4 | 32);

    gconv_gather<<<NN, 128>>>(pM, ienc_b, pOFF, pCNT, pSRT, x, pKO, pZ, 0);

    // Z += pre_x @ pre_W' + pre_b + ko⊗preW[511] ; emit split -> A2
    hgemm<<<dim3(4, 128), 256, HG_SMEM>>>(pP1H, pP1L, pWH + OFF_PRE, pWL + OFF_PRE,
        pre_b, nullptr, pKO, pre_W + (size_t)511 * DD,
        pZ, pZ, pA2H, pA2L,
        512, 512, 16, DD, 512, 512, DD, 2 | 8 | 32);

    // enc: M = Z @ enc_W ; gconv(full) -> Z2
    hgemm<<<dim3(4, 128), 256, HG_SMEM>>>(pA2H, pA2L, pWH + OFF_ENC, pWL + OFF_ENC,
        nullptr, nullptr, nullptr, nullptr, nullptr, pM, nullptr, nullptr,
        512, 512, 16, DD, 512, 0, 0, 0);
    gconv_gather<<<NN, 128>>>(pM, enc_b, pOFF + NN, pCNT + NN, pSRT,
                              nullptr, nullptr, pZ2, 1);

    // readout
    gather_zk<<<(BB * KK * 128 + 255) / 256, 256>>>(pZ2, bkm, pZK, pA1H, pA1L);
    hgemm<<<dim3(4, 8), 256, HG_SMEM>>>(pA1H, pA1L, pWH + OFF_GATE, pWL + OFF_GATE,
        gate_b1, nullptr, nullptr, nullptr, nullptr, pH, nullptr, nullptr,
        512, 512, 16, DD, 512, 0, 0, 0);
    tanh_dot<<<BB * KK, 128>>>(pH, gate_W2, gate_b2, pSC);
    readout2<<<BB, 256>>>(pZK, pSC, reg_W, reg_b, out);

    // tidy up only when NOT capturing (destroying capturing streams breaks capture)
    cudaStreamCaptureStatus cap = cudaStreamCaptureStatusNone;
    cudaStreamIsCapturing(0, &cap);
    if (cap == cudaStreamCaptureStatusNone) {
        cudaStreamDestroy(s1);
        cudaStreamDestroy(s2);
        cudaEventDestroy(evStart);
        cudaEventDestroy(evW);
        cudaEventDestroy(ev1);
        cudaEventDestroy(ev2);
    }

    (void)out_size;
    (void)n_in;
}

// round 8
// speedup vs baseline: 6.3750x; 1.0744x over previous
#include <cuda_runtime.h>
#include <cuda_bf16.h>
#include <cstdint>

#define NN      16384
#define NE_     1024
#define BB      16
#define KK      64
#define TX_     768
#define OM_     511
#define DD      512
#define SLOPE_  0.3f
#define E_INT_MAX 131072
#define E_FULL_MAX 262144

// ------------------------- helpers ------------------------------------------
__device__ __forceinline__ uint32_t smem_to_u32(const void* p) {
    uint32_t a;
    asm("{ .reg .u64 t; cvta.to.shared.u64 t, %1; cvt.u32.u64 %0, t; }"
        : "=r"(a) : "l"(p));
    return a;
}

#define CP_ASYNC16(saddr, gptr) \
    asm volatile("cp.async.cg.shared.global [%0], [%1], 16;" \
                 :: "r"(saddr), "l"(gptr) : "memory")

#define LDMX4(r0, r1, r2, r3, addr) \
    asm volatile("ldmatrix.sync.aligned.m8n8.x4.shared.b16 {%0,%1,%2,%3}, [%4];" \
                 : "=r"(r0), "=r"(r1), "=r"(r2), "=r"(r3) : "r"(addr))

#define MMA16816(c, a, b) \
    asm volatile("mma.sync.aligned.m16n8k16.row.col.f32.bf16.bf16.f32 " \
                 "{%0,%1,%2,%3},{%4,%5,%6,%7},{%8,%9},{%0,%1,%2,%3};" \
                 : "+f"((c)[0]), "+f"((c)[1]), "+f"((c)[2]), "+f"((c)[3]) \
                 : "r"((a)[0]), "r"((a)[1]), "r"((a)[2]), "r"((a)[3]), \
                   "r"((b)[0]), "r"((b)[1]))

// ------------------------- scratch (device globals) -------------------------
__device__ __nv_bfloat16 g_A1H[NN * DD];
__device__ __nv_bfloat16 g_A1L[NN * DD];
__device__ __nv_bfloat16 g_A2H[NN * DD];
__device__ __nv_bfloat16 g_A2L[NN * DD];
__device__ __nv_bfloat16 g_CHH[NN * 1024];     // combined [Zg | pre_x] split (hi)
__device__ __nv_bfloat16 g_CHL[NN * 1024];
__device__ __nv_bfloat16 g_E1H[2048 * TX_];    // entity emb split (name|desc)
__device__ __nv_bfloat16 g_E1L[2048 * TX_];
__device__ __nv_bfloat16 g_E2H[NE_ * 1536];    // entity linears split
__device__ __nv_bfloat16 g_E2L[NE_ * 1536];
#define WT_TOTAL 3801088
__device__ __nv_bfloat16 g_WH[WT_TOTAL];
__device__ __nv_bfloat16 g_WL[WT_TOTAL];
__device__ __nv_bfloat16 g_WFH[DD * DD];       // WFT split (ienc fold)
__device__ __nv_bfloat16 g_WFL[DD * DD];
__device__ __nv_bfloat16 g_NDPH[NE_ * DD];     // ndpart split
__device__ __nv_bfloat16 g_NDPL[NE_ * DD];
__device__ float g_NDP2[NE_ * DD];             // ndpart @ Wienc'
__device__ float g_B2  [2 * DD];               // [pre_b@Wenc | preW511@Wenc]
__device__ float g_M  [NN * DD];
__device__ float g_Z2 [NN * DD];
__device__ float g_ZK [NE_ * DD];
__device__ float g_H  [NE_ * DD];
__device__ float g_KO [NN];
__device__ float g_SC [BB * KK];
__device__ int   g_CNT[2 * NN];
__device__ int   g_OFF[2 * NN];
__device__ int   g_CUR[2 * NN];
__device__ int   g_SRT[E_INT_MAX + E_FULL_MAX];

// ============================================================================
// HMMA split-bf16 GEMM (calibrated core — unchanged)
// flags: 1 leaky, 2 accumulate (+Cin), 4 add gat[(row&1023)*512+col],
//        8 write split-bf16 (Oh/Ol stride ldo, zero-pad cols [Nc,padN)),
//        16 skip fp32 C write, 32 add koV[row]*w511[col]
// ============================================================================
__global__ void __launch_bounds__(256, 2)
hgemm(const __nv_bfloat16* __restrict__ Ah, const __nv_bfloat16* __restrict__ Al,
      const __nv_bfloat16* __restrict__ Bh, const __nv_bfloat16* __restrict__ Bl,
      const float* __restrict__ bias, const float* __restrict__ gat,
      const float* __restrict__ koV, const float* __restrict__ w511,
      const float* __restrict__ Cin, float* __restrict__ C,
      __nv_bfloat16* __restrict__ Oh, __nv_bfloat16* __restrict__ Ol,
      int lda_b, int ldb_b, int nchunks, int Nc, int ldc, int ldo,
      int padN, int flags)
{
    extern __shared__ char smem[];
    const uint32_t sb = smem_to_u32(smem);
    const int tid  = threadIdx.x;
    const int lane = tid & 31;
    const int wid  = tid >> 5;
    const int wm   = (wid >> 2) * 64;
    const int wn   = (wid & 3) * 32;
    const int bm   = blockIdx.y * 128;
    const int bn   = blockIdx.x * 128;

    float acc[4][4][4];
#pragma unroll
    for (int i = 0; i < 4; i++)
#pragma unroll
        for (int j = 0; j < 4; j++)
#pragma unroll
            for (int q = 0; q < 4; q++) acc[i][j][q] = 0.f;

    auto load_stage = [&](int st, int k0) {
        const uint32_t base = sb + st * 40960;
#pragma unroll
        for (int i = 0; i < 2; i++) {
            const int idx = tid + i * 256;
            const int row = idx >> 2;
            const int c16 = idx & 3;
            const uint32_t so = base + row * 80 + c16 * 16;
            const size_t ga = (size_t)(bm + row) * lda_b + k0 + c16 * 8;
            const size_t gb = (size_t)(bn + row) * ldb_b + k0 + c16 * 8;
            CP_ASYNC16(so,          Ah + ga);
            CP_ASYNC16(so + 10240,  Al + ga);
            CP_ASYNC16(so + 20480,  Bh + gb);
            CP_ASYNC16(so + 30720,  Bl + gb);
        }
        asm volatile("cp.async.commit_group;" ::: "memory");
    };

    auto compute = [&](int st) {
        const uint32_t base = sb + st * 40960;
        const int arow = lane & 15;
        const int asub = (lane >> 4) * 8;
        const int brow = (lane & 7) + (lane >> 4) * 8;
        const int bsub = ((lane >> 3) & 1) * 8;
#pragma unroll
        for (int ks = 0; ks < 2; ks++) {
            const int kb = ks * 16;
            const uint32_t a0 = base + ((wm + arow) * 40 + kb + asub) * 2;
            const uint32_t b0 = base + 20480 + ((wn + brow) * 40 + kb + bsub) * 2;

            uint32_t ah[4][4], bh[4][2];
#pragma unroll
            for (int mt = 0; mt < 4; mt++)
                LDMX4(ah[mt][0], ah[mt][1], ah[mt][2], ah[mt][3], a0 + mt * 16 * 80);
#pragma unroll
            for (int p = 0; p < 2; p++)
                LDMX4(bh[2*p][0], bh[2*p][1], bh[2*p+1][0], bh[2*p+1][1],
                      b0 + p * 16 * 80);
#pragma unroll
            for (int mt = 0; mt < 4; mt++)
#pragma unroll
                for (int nt = 0; nt < 4; nt++)
                    MMA16816(acc[mt][nt], ah[mt], bh[nt]);
#pragma unroll
            for (int p = 0; p < 2; p++) {
                uint32_t bl[2][2];
                LDMX4(bl[0][0], bl[0][1], bl[1][0], bl[1][1],
                      b0 + 10240 + p * 16 * 80);
#pragma unroll
                for (int mt = 0; mt < 4; mt++) {
                    MMA16816(acc[mt][2*p],   ah[mt], bl[0]);
                    MMA16816(acc[mt][2*p+1], ah[mt], bl[1]);
                }
            }
#pragma unroll
            for (int mt = 0; mt < 4; mt++) {
                uint32_t al[4];
                LDMX4(al[0], al[1], al[2], al[3], a0 + 10240 + mt * 16 * 80);
#pragma unroll
                for (int nt = 0; nt < 4; nt++)
                    MMA16816(acc[mt][nt], al, bh[nt]);
            }
        }
    };

    load_stage(0, 0);
    for (int c = 0; c < nchunks; c++) {
        if (c + 1 < nchunks) {
            load_stage((c + 1) & 1, (c + 1) * 32);
            asm volatile("cp.async.wait_group 1;" ::: "memory");
        } else {
            asm volatile("cp.async.wait_group 0;" ::: "memory");
        }
        __syncthreads();
        compute(c & 1);
        __syncthreads();
    }

    // ---- epilogue ----
    const int er = lane >> 2;
    const int ec = (lane & 3) * 2;
#pragma unroll
    for (int mt = 0; mt < 4; mt++) {
#pragma unroll
        for (int h = 0; h < 2; h++) {
            const int row = bm + wm + mt * 16 + er + h * 8;
            const size_t crow = (size_t)row * ldc;
            const size_t orow = (size_t)row * ldo;
            const size_t grow = (size_t)(row & (NE_ - 1)) * 512;
            const float kv = (flags & 32) ? koV[row] : 0.f;
#pragma unroll
            for (int nt = 0; nt < 4; nt++) {
                const int col = bn + wn + nt * 8 + ec;
                float v0 = acc[mt][nt][h * 2 + 0];
                float v1 = acc[mt][nt][h * 2 + 1];
                if (col + 1 < Nc) {
                    if (bias) {
                        float2 bb = *reinterpret_cast<const float2*>(bias + col);
                        v0 += bb.x; v1 += bb.y;
                    }
                    if (flags & 4) {
                        float2 gg = *reinterpret_cast<const float2*>(gat + grow + col);
                        v0 += gg.x; v1 += gg.y;
                    }
                    if (flags & 32) {
                        float2 ww = *reinterpret_cast<const float2*>(w511 + col);
                        v0 += kv * ww.x; v1 += kv * ww.y;
                    }
                    if (flags & 1) {
                        v0 = v0 > 0.f ? v0 : SLOPE_ * v0;
                        v1 = v1 > 0.f ? v1 : SLOPE_ * v1;
                    }
                    if (flags & 2) {
                        float2 ci = *reinterpret_cast<const float2*>(Cin + crow + col);
                        v0 += ci.x; v1 += ci.y;
                    }
                    if (!(flags & 16))
                        *reinterpret_cast<float2*>(C + crow + col) = make_float2(v0, v1);
                    if (flags & 8) {
                        __nv_bfloat16 h0 = __float2bfloat16(v0);
                        __nv_bfloat16 h1 = __float2bfloat16(v1);
                        __nv_bfloat162 hh; hh.x = h0; hh.y = h1;
                        __nv_bfloat162 ll;
                        ll.x = __float2bfloat16(v0 - __bfloat162float(h0));
                        ll.y = __float2bfloat16(v1 - __bfloat162float(h1));
                        *reinterpret_cast<__nv_bfloat162*>(Oh + orow + col) = hh;
                        *reinterpret_cast<__nv_bfloat162*>(Ol + orow + col) = ll;
                    }
                } else {
                    float vv[2] = {v0, v1};
#pragma unroll
                    for (int q = 0; q < 2; q++) {
                        const int cq = col + q;
                        if (cq < Nc) {
                            float v = vv[q];
                            if (bias)       v += bias[cq];
                            if (flags & 4)  v += gat[grow + cq];
                            if (flags & 32) v += kv * w511[cq];
                            if (flags & 1)  v = v > 0.f ? v : SLOPE_ * v;
                            if (flags & 2)  v += Cin[crow + cq];
                            if (!(flags & 16)) C[crow + cq] = v;
                            if (flags & 8) {
                                __nv_bfloat16 hh = __float2bfloat16(v);
                                Oh[orow + cq] = hh;
                                Ol[orow + cq] = __float2bfloat16(v - __bfloat162float(hh));
                            }
                        } else if ((flags & 8) && cq < padN) {
                            Oh[orow + cq] = __float2bfloat16(0.f);
                            Ol[orow + cq] = __float2bfloat16(0.f);
                        }
                    }
                }
            }
        }
    }
}

// ------------------------- conversion kernels -------------------------------
// split A: write [M, width] (cols >= K zeroed) at row stride ldrow
__global__ void cvt_splitA(const float* __restrict__ A, int M, int K, int lda,
                           int width, int ldrow,
                           __nv_bfloat16* __restrict__ Ah, __nv_bfloat16* __restrict__ Al)
{
    int i = blockIdx.x * blockDim.x + threadIdx.x;
    int half = width >> 1;
    int r = i / half;
    if (r >= M) return;
    int c2 = (i - r * half) * 2;
    float v0 = (c2 < K)     ? A[(size_t)r * lda + c2]     : 0.f;
    float v1 = (c2 + 1 < K) ? A[(size_t)r * lda + c2 + 1] : 0.f;
    __nv_bfloat16 h0 = __float2bfloat16(v0), h1 = __float2bfloat16(v1);
    __nv_bfloat16 l0 = __float2bfloat16(v0 - __bfloat162float(h0));
    __nv_bfloat16 l1 = __float2bfloat16(v1 - __bfloat162float(h1));
    __nv_bfloat162 hh; hh.x = h0; hh.y = h1;
    __nv_bfloat162 ll; ll.x = l0; ll.y = l1;
    *reinterpret_cast<__nv_bfloat162*>(Ah + (size_t)r * ldrow + c2) = hh;
    *reinterpret_cast<__nv_bfloat162*>(Al + (size_t)r * ldrow + c2) = ll;
}

struct WJobs {
    const float* W[9];
    long off[9];
    long cum[10];
    int K[9], N[9], ldw[9], ldo[9], trans[9];
    int njobs;
};

__global__ void cvt_splitW_all(WJobs jobs,
                               __nv_bfloat16* __restrict__ Wh,
                               __nv_bfloat16* __restrict__ Wl)
{
    long gid = (long)blockIdx.x * blockDim.x + threadIdx.x;
    if (gid >= jobs.cum[jobs.njobs]) return;
    int j = 0;
    while (gid >= jobs.cum[j + 1]) j++;
    long local = gid - jobs.cum[j];
    int ldo = jobs.ldo[j];
    int n = (int)(local / ldo);
    int k = (int)(local - (long)n * ldo);
    float v = 0.f;
    if (n < jobs.N[j] && k < jobs.K[j])
        v = jobs.trans[j] ? jobs.W[j][(size_t)k * jobs.ldw[j] + n]
                          : jobs.W[j][(size_t)n * jobs.ldw[j] + k];
    __nv_bfloat16 h = __float2bfloat16(v);
    Wh[jobs.off[j] + local] = h;
    Wl[jobs.off[j] + local] = __float2bfloat16(v - __bfloat162float(h));
}

// B2[0,:] = pre_b @ enc_W ; B2[1,:] = pre_W[511,:] @ enc_W
__global__ void fold_bias(const float* __restrict__ pre_b, const float* __restrict__ pre_W,
                          const float* __restrict__ enc_W, float* __restrict__ B2)
{
    int n = threadIdx.x;              // 512
    int which = blockIdx.x;           // 2
    const float* v = which ? (pre_W + (size_t)511 * DD) : pre_b;
    float acc = 0.f;
    for (int j = 0; j < DD; j++)
        acc = fmaf(v[j], enc_W[(size_t)j * DD + n], acc);
    B2[which * DD + n] = acc;
}

// ------------------------- misc ----------------------------------------------
__global__ void zero_f(float* __restrict__ p, int n)
{ int i = blockIdx.x * blockDim.x + threadIdx.x; if (i < n) p[i] = 0.f; }
__global__ void zero_i(int* __restrict__ p, int n)
{ int i = blockIdx.x * blockDim.x + threadIdx.x; if (i < n) p[i] = 0; }

__global__ void set_ko(const int* __restrict__ bkm, float* __restrict__ ko)
{
    int i = blockIdx.x * blockDim.x + threadIdx.x;
    if (i < BB * KK) ko[(i >> 6) * NE_ + bkm[i]] = 1.0f;
}

// ------------------------- CSR build -----------------------------------------
__global__ void csr_count2(const int* __restrict__ iei, int Ei,
                           const int* __restrict__ fei, int Ef,
                           int* __restrict__ cnt)
{
    int i = blockIdx.x * blockDim.x + threadIdx.x;
    if (i < Ei) atomicAdd(&cnt[iei[Ei + i]], 1);
    else if (i < Ei + Ef) {
        int j = i - Ei;
        atomicAdd(&cnt[NN + fei[Ef + j]], 1);
    }
}

__global__ void __launch_bounds__(1024, 1)
csr_scan2(const int* __restrict__ cnt, int* __restrict__ off,
          int* __restrict__ cur, int base1)
{
    __shared__ int sa[1024], sbuf[1024];
    const int g = blockIdx.x;
    const int* c = cnt + g * NN;
    int* o = off + g * NN;
    int* u = cur + g * NN;
    int t = threadIdx.x;
    int base = t * 16;
    int loc[16];
    int s = 0;
#pragma unroll
    for (int j = 0; j < 16; j++) { loc[j] = c[base + j]; s += loc[j]; }
    sa[t] = s;
    __syncthreads();
    int* A = sa; int* Bf = sbuf;
    for (int d = 1; d < 1024; d <<= 1) {
        int v = A[t] + (t >= d ? A[t - d] : 0);
        __syncthreads();
        Bf[t] = v;
        __syncthreads();
        int* tmp = A; A = Bf; Bf = tmp;
    }
    int run = (t ? A[t - 1] : 0) + (g ? base1 : 0);
#pragma unroll
    for (int j = 0; j < 16; j++) { o[base + j] = run; u[base + j] = run; run += loc[j]; }
}

__global__ void csr_fill2(const int* __restrict__ iei, int Ei,
                          const int* __restrict__ fei, int Ef,
                          int* __restrict__ cur, int* __restrict__ srt)
{
    int i = blockIdx.x * blockDim.x + threadIdx.x;
    if (i < Ei) {
        int p = atomicAdd(&cur[iei[Ei + i]], 1);
        srt[p] = iei[i];
    } else if (i < Ei + Ef) {
        int j = i - Ei;
        int p = atomicAdd(&cur[NN + fei[Ef + j]], 1);
        srt[p] = fei[j];
    }
}

// gconv aggregate + epilogue.
// mode 0: Zg = leaky(acc)+x_c, emit SPLIT bf16 into Oh/Ol at row stride 1024
// mode 1: out = leaky(acc) fp32 (stride 512)
__global__ void __launch_bounds__(128, 8)
gconv_gather(const float* __restrict__ m, const float* __restrict__ bias,
             const int* __restrict__ off, const int* __restrict__ cnt,
             const int* __restrict__ srt,
             const float* __restrict__ x, const float* __restrict__ ko,
             float* __restrict__ out,
             __nv_bfloat16* __restrict__ Oh, __nv_bfloat16* __restrict__ Ol,
             int mode)
{
    const int r = blockIdx.x;
    const int t = threadIdx.x;
    float4 acc = reinterpret_cast<const float4*>(m + (size_t)r * DD)[t];
    float4 b   = reinterpret_cast<const float4*>(bias)[t];
    acc.x += b.x; acc.y += b.y; acc.z += b.z; acc.w += b.w;
    const int s0 = off[r];
    const int d  = cnt[r];
    for (int e = 0; e < d; e++) {
        int s = srt[s0 + e];
        float4 v = reinterpret_cast<const float4*>(m + (size_t)s * DD)[t];
        acc.x += v.x; acc.y += v.y; acc.z += v.z; acc.w += v.w;
    }
    acc.x = acc.x > 0.f ? acc.x : SLOPE_ * acc.x;
    acc.y = acc.y > 0.f ? acc.y : SLOPE_ * acc.y;
    acc.z = acc.z > 0.f ? acc.z : SLOPE_ * acc.z;
    acc.w = acc.w > 0.f ? acc.w : SLOPE_ * acc.w;
    if (mode == 0) {
        const int c0 = t * 4;
        float vv[4] = {acc.x, acc.y, acc.z, acc.w};
#pragma unroll
        for (int q = 0; q < 4; q++) {
            int c = c0 + q;
            vv[q] += (c < OM_) ? x[(size_t)r * OM_ + c] : ko[r];
        }
        __nv_bfloat16 h[4], l[4];
#pragma unroll
        for (int q = 0; q < 4; q++) {
            h[q] = __float2bfloat16(vv[q]);
            l[q] = __float2bfloat16(vv[q] - __bfloat162float(h[q]));
        }
        size_t o = (size_t)r * 1024 + c0;
        __nv_bfloat162 h01; h01.x = h[0]; h01.y = h[1];
        __nv_bfloat162 h23; h23.x = h[2]; h23.y = h[3];
        __nv_bfloat162 l01; l01.x = l[0]; l01.y = l[1];
        __nv_bfloat162 l23; l23.x = l[2]; l23.y = l[3];
        *reinterpret_cast<__nv_bfloat162*>(Oh + o)     = h01;
        *reinterpret_cast<__nv_bfloat162*>(Oh + o + 2) = h23;
        *reinterpret_cast<__nv_bfloat162*>(Ol + o)     = l01;
        *reinterpret_cast<__nv_bfloat162*>(Ol + o + 2) = l23;
    } else {
        reinterpret_cast<float4*>(out + (size_t)r * DD)[t] = acc;
    }
}

// ------------------------- readout -------------------------------------------
__global__ void gather_zk(const float* __restrict__ Z2, const int* __restrict__ bkm,
                          float* __restrict__ ZK,
                          __nv_bfloat16* __restrict__ Ah, __nv_bfloat16* __restrict__ Al)
{
    int i = blockIdx.x * blockDim.x + threadIdx.x;
    if (i >= BB * KK * 128) return;
    int row = i >> 7, c4 = i & 127;
    int b = row >> 6;
    size_t src = (size_t)bkm[row] + (size_t)b * NE_;
    float4 v = reinterpret_cast<const float4*>(Z2)[src * 128 + c4];
    reinterpret_cast<float4*>(ZK)[(size_t)row * 128 + c4] = v;
    float vv[4] = {v.x, v.y, v.z, v.w};
    __nv_bfloat16 h[4], l[4];
#pragma unroll
    for (int q = 0; q < 4; q++) {
        h[q] = __float2bfloat16(vv[q]);
        l[q] = __float2bfloat16(vv[q] - __bfloat162float(h[q]));
    }
    size_t o = (size_t)row * DD + c4 * 4;
    __nv_bfloat162 h01; h01.x = h[0]; h01.y = h[1];
    __nv_bfloat162 h23; h23.x = h[2]; h23.y = h[3];
    __nv_bfloat162 l01; l01.x = l[0]; l01.y = l[1];
    __nv_bfloat162 l23; l23.x = l[2]; l23.y = l[3];
    *reinterpret_cast<__nv_bfloat162*>(Ah + o)     = h01;
    *reinterpret_cast<__nv_bfloat162*>(Ah + o + 2) = h23;
    *reinterpret_cast<__nv_bfloat162*>(Al + o)     = l01;
    *reinterpret_cast<__nv_bfloat162*>(Al + o + 2) = l23;
}

__global__ void tanh_dot(const float* __restrict__ H, const float* __restrict__ W2,
                         const float* __restrict__ b2, float* __restrict__ sc)
{
    int row = blockIdx.x;
    int tid = threadIdx.x;
    __shared__ float red[128];
    float p = 0.f;
    for (int j = tid; j < DD; j += 128)
        p = fmaf(tanhf(H[(size_t)row * DD + j]), W2[j], p);
    red[tid] = p;
    __syncthreads();
    for (int s = 64; s > 0; s >>= 1) {
        if (tid < s) red[tid] += red[tid + s];
        __syncthreads();
    }
    if (tid == 0) sc[row] = red[0] + b2[0];
}

__global__ void readout2(const float* __restrict__ ZK, const float* __restrict__ sc,
                         const float* __restrict__ regW, const float* __restrict__ regb,
                         float* __restrict__ out)
{
    int b = blockIdx.x;
    int tid = threadIdx.x;
    __shared__ float w[KK];
    __shared__ float red[256];
    __shared__ float sm;
    if (tid < KK) w[tid] = sc[b * KK + tid];
    __syncthreads();
    if (tid == 0) {
        float m = w[0];
        for (int k = 1; k < KK; k++) m = fmaxf(m, w[k]);
        float s = 0.f;
        for (int k = 0; k < KK; k++) { w[k] = expf(w[k] - m); s += w[k]; }
        sm = s;
    }
    __syncthreads();
    int c0 = tid, c1 = tid + 256;
    float r0 = 0.f, r1 = 0.f;
    for (int k = 0; k < KK; k++) {
        const float* z = ZK + ((size_t)b * KK + k) * DD;
        float wk = w[k];
        r0 = fmaf(wk, z[c0], r0);
        r1 = fmaf(wk, z[c1], r1);
    }
    float part = (r0 * regW[c0] + r1 * regW[c1]) / sm;
    red[tid] = part;
    __syncthreads();
    for (int s = 128; s > 0; s >>= 1) {
        if (tid < s) red[tid] += red[tid + s];
        __syncthreads();
    }
    if (tid == 0) out[b] = red[0] + regb[0];
}

// ------------------------- host side ------------------------------------------
static const int HG_SMEM = 2 * 40960;

extern "C" void kernel_launch(void* const* d_in, const int* in_sizes, int n_in,
                              void* d_out, int out_size)
{
    int map_[31];
    {
        int p = 0;
        for (int l = 0; l < 31; l++) {
            if (l == 5 || l == 8) {
                bool present = (n_in == 31);
                if (present && p < n_in && in_sizes[p] == 1) map_[l] = p++;
                else map_[l] = -1;
            } else map_[l] = p++;
        }
    }
    auto F = [&](int l) -> const float* { return (const float*)d_in[map_[l]]; };
    auto I = [&](int l) -> const int*   { return (const int*)d_in[map_[l]]; };

    const float* x        = F(0);
    const float* pre_x    = F(1);
    const int*   edge_ei  = I(2);
    const int*   int_ei   = I(3);
    const float* name_emb = F(6);
    const float* desc_emb = F(7);
    const int*   bkm      = I(9);
    const float* name_W = F(11), *name_b = F(12);
    const float* desc_W = F(13), *desc_b = F(14);
    const float* omic_W = F(15), *omic_b = F(16);
    const float* fus_W  = F(17), *fus_b  = F(18);
    const float* pre_W  = F(19), *pre_b  = F(20);
    const float* ienc_W = F(21), *ienc_b = F(22);
    const float* enc_W  = F(23), *enc_b  = F(24);
    const float* gate_W1 = F(25), *gate_b1 = F(26);
    const float* gate_W2 = F(27), *gate_b2 = F(28);
    const float* reg_W   = F(29), *reg_b   = F(30);
    float* out = (float*)d_out;

    const int E_full = in_sizes[map_[2]] / 2;
    const int E_int  = in_sizes[map_[3]] / 2;
    const float* W2 = fus_W + (size_t)1536 * OM_;

    __nv_bfloat16 *pA1H, *pA1L, *pA2H, *pA2L, *pCHH, *pCHL, *pE1H, *pE1L, *pE2H, *pE2L;
    __nv_bfloat16 *pWH, *pWL, *pWFH, *pWFL, *pNDPH, *pNDPL;
    float *pNDP2, *pB2, *pM, *pZ2, *pZK, *pH, *pKO, *pSC;
    int *pCNT, *pOFF, *pCUR, *pSRT;
    cudaGetSymbolAddress((void**)&pA1H, g_A1H);
    cudaGetSymbolAddress((void**)&pA1L, g_A1L);
    cudaGetSymbolAddress((void**)&pA2H, g_A2H);
    cudaGetSymbolAddress((void**)&pA2L, g_A2L);
    cudaGetSymbolAddress((void**)&pCHH, g_CHH);
    cudaGetSymbolAddress((void**)&pCHL, g_CHL);
    cudaGetSymbolAddress((void**)&pE1H, g_E1H);
    cudaGetSymbolAddress((void**)&pE1L, g_E1L);
    cudaGetSymbolAddress((void**)&pE2H, g_E2H);
    cudaGetSymbolAddress((void**)&pE2L, g_E2L);
    cudaGetSymbolAddress((void**)&pWH,  g_WH);
    cudaGetSymbolAddress((void**)&pWL,  g_WL);
    cudaGetSymbolAddress((void**)&pWFH, g_WFH);
    cudaGetSymbolAddress((void**)&pWFL, g_WFL);
    cudaGetSymbolAddress((void**)&pNDPH, g_NDPH);
    cudaGetSymbolAddress((void**)&pNDPL, g_NDPL);
    cudaGetSymbolAddress((void**)&pNDP2, g_NDP2);
    cudaGetSymbolAddress((void**)&pB2,  g_B2);
    cudaGetSymbolAddress((void**)&pM,   g_M);
    cudaGetSymbolAddress((void**)&pZ2,  g_Z2);
    cudaGetSymbolAddress((void**)&pZK,  g_ZK);
    cudaGetSymbolAddress((void**)&pH,   g_H);
    cudaGetSymbolAddress((void**)&pKO,  g_KO);
    cudaGetSymbolAddress((void**)&pSC,  g_SC);
    cudaGetSymbolAddress((void**)&pCNT, g_CNT);
    cudaGetSymbolAddress((void**)&pOFF, g_OFF);
    cudaGetSymbolAddress((void**)&pCUR, g_CUR);
    cudaGetSymbolAddress((void**)&pSRT, g_SRT);

    cudaFuncSetAttribute(hgemm, cudaFuncAttributeMaxDynamicSharedMemorySize, HG_SMEM);

    // weight region offsets (contiguous)
    const long OFF_NAME  = 0;        // 768x768  (name^T)
    const long OFF_DESC  = 589824;   // 768x768  (desc^T)
    const long OFF_FUS1  = 1179648;  // 512x1536 (fus[0:1536]^T)
    const long OFF_OMIC  = 1966080;  // 512x512  (omic^T)
    const long OFF_IENC2 = 2228224;  // 512x512  (ienc'^T)
    const long OFF_W2D   = 2490368;  // 512x512  (fus2 direct)
    const long OFF_PRED  = 2752512;  // 512x512  (pre_W direct)
    const long OFF_ENC2  = 3014656;  // 512x1024 ([enc^T | WPE^T])
    const long OFF_GATE  = 3538944;  // 512x512  (gate1^T)

    // ---- streams & events
    cudaStream_t s1, s2, s3;
    cudaStreamCreateWithFlags(&s1, cudaStreamNonBlocking);
    cudaStreamCreateWithFlags(&s2, cudaStreamNonBlocking);
    cudaStreamCreateWithFlags(&s3, cudaStreamNonBlocking);
    cudaEvent_t evStart, evW, ev1, ev2, ev3;
    cudaEventCreateWithFlags(&evStart, cudaEventDisableTiming);
    cudaEventCreateWithFlags(&evW,     cudaEventDisableTiming);
    cudaEventCreateWithFlags(&ev1,     cudaEventDisableTiming);
    cudaEventCreateWithFlags(&ev2,     cudaEventDisableTiming);
    cudaEventCreateWithFlags(&ev3,     cudaEventDisableTiming);

    cudaEventRecord(evStart, 0);
    cudaStreamWaitEvent(s2, evStart, 0);

    // ---------------- s2: KO + CSR + pre_x split into CH cols 512..1023 ---
    zero_f<<<(NN + 255) / 256, 256, 0, s2>>>(pKO, NN);
    set_ko<<<(BB * KK + 255) / 256, 256, 0, s2>>>(bkm, pKO);
    zero_i<<<(2 * NN + 255) / 256, 256, 0, s2>>>(pCNT, 2 * NN);
    csr_count2<<<(E_int + E_full + 255) / 256, 256, 0, s2>>>(int_ei, E_int, edge_ei, E_full, pCNT);
    csr_scan2<<<2, 1024, 0, s2>>>(pCNT, pOFF, pCUR, E_int);
    csr_fill2<<<(E_int + E_full + 255) / 256, 256, 0, s2>>>(int_ei, E_int, edge_ei, E_full, pCUR, pSRT);
    cvt_splitA<<<(NN * 256 + 255) / 256, 256, 0, s2>>>(pre_x, NN, OM_, OM_, 512, 1024,
                                                       pCHH + 512, pCHL + 512);
    cudaEventRecord(ev2, s2);

    // ---------------- s0: weight conversion ------------------------------
    {
        WJobs jb;
        const float* Ws[9] = {name_W, desc_W, fus_W, omic_W, ienc_W, W2, pre_W, enc_W, gate_W1};
        int Ks[9]  = {TX_, TX_, 1536, OM_, OM_, OM_, DD, DD, DD};
        int Ns[9]  = {TX_, TX_, OM_, OM_, DD, OM_, DD, DD, DD};
        int ldw[9] = {TX_, TX_, OM_, OM_, DD, OM_, DD, DD, DD};
        int ldo[9] = {TX_, TX_, 1536, 512, 512, 512, 512, 1024, 512};
        int Np[9]  = {TX_, TX_, 512, 512, 512, 512, 512, 512, 512};
        int tr[9]  = {1, 1, 1, 1, 1, 0, 0, 1, 1};
        long offs[9] = {OFF_NAME, OFF_DESC, OFF_FUS1, OFF_OMIC, OFF_IENC2,
                        OFF_W2D, OFF_PRED, OFF_ENC2, OFF_GATE};
        long cum = 0;
        jb.njobs = 9;
        for (int j = 0; j < 9; j++) {
            jb.W[j] = Ws[j]; jb.K[j] = Ks[j]; jb.N[j] = Ns[j];
            jb.ldw[j] = ldw[j]; jb.ldo[j] = ldo[j]; jb.trans[j] = tr[j];
            jb.off[j] = offs[j];
            jb.cum[j] = cum; cum += (long)Np[j] * ldo[j];
        }
        jb.cum[9] = cum;
        cvt_splitW_all<<<(int)((cum + 255) / 256), 256>>>(jb, pWH, pWL);
    }
    cudaEventRecord(evW, 0);

    // ---------------- s3: WFT + WPE + fold_bias ---------------------------
    cudaStreamWaitEvent(s3, evW, 0);
    fold_bias<<<2, DD, 0, s3>>>(pre_b, pre_W, enc_W, pB2);
    // WFT = (W2 @ Wienc')^T
    hgemm<<<dim3(4, 4), 256, HG_SMEM, s3>>>(pWH + OFF_IENC2, pWL + OFF_IENC2,
        pWH + OFF_W2D, pWL + OFF_W2D,
        nullptr, nullptr, nullptr, nullptr, nullptr, nullptr, pWFH, pWFL,
        512, 512, 16, OM_, 0, 512, 512, 8 | 16);
    // WPE^T -> WE2 cols 512..1023 (A = enc^T split inside WE2, B = pre_W direct)
    hgemm<<<dim3(4, 4), 256, HG_SMEM, s3>>>(pWH + OFF_ENC2, pWL + OFF_ENC2,
        pWH + OFF_PRED, pWL + OFF_PRED,
        nullptr, nullptr, nullptr, nullptr, nullptr, nullptr,
        pWH + OFF_ENC2 + 512, pWL + OFF_ENC2 + 512,
        1024, 512, 16, 512, 0, 1024, 512, 8 | 16);
    cudaEventRecord(ev3, s3);

    // ---------------- s1: entity chain ------------------------------------
    cudaStreamWaitEvent(s1, evW, 0);
    cvt_splitA<<<(NE_ * 384 + 255) / 256, 256, 0, s1>>>(name_emb, NE_, TX_, TX_, TX_, TX_, pE1H, pE1L);
    cvt_splitA<<<(NE_ * 384 + 255) / 256, 256, 0, s1>>>(desc_emb, NE_, TX_, TX_, TX_, TX_,
                                                        pE1H + (size_t)NE_ * TX_,
                                                        pE1L + (size_t)NE_ * TX_);
    hgemm<<<dim3(6, 8), 256, HG_SMEM, s1>>>(pE1H, pE1L, pWH + OFF_NAME, pWL + OFF_NAME,
        name_b, nullptr, nullptr, nullptr, nullptr, nullptr, pE2H, pE2L,
        TX_, TX_, 24, TX_, 0, 1536, TX_, 1 | 8 | 16);
    hgemm<<<dim3(6, 8), 256, HG_SMEM, s1>>>(pE1H + (size_t)NE_ * TX_, pE1L + (size_t)NE_ * TX_,
        pWH + OFF_DESC, pWL + OFF_DESC,
        desc_b, nullptr, nullptr, nullptr, nullptr, nullptr, pE2H + TX_, pE2L + TX_,
        TX_, TX_, 24, TX_, 0, 1536, TX_, 1 | 8 | 16);
    hgemm<<<dim3(4, 8), 256, HG_SMEM, s1>>>(pE2H, pE2L, pWH + OFF_FUS1, pWL + OFF_FUS1,
        fus_b, nullptr, nullptr, nullptr, nullptr, nullptr, pNDPH, pNDPL,
        1536, 1536, 48, OM_, 0, 512, 512, 8 | 16);
    hgemm<<<dim3(4, 8), 256, HG_SMEM, s1>>>(pNDPH, pNDPL, pWH + OFF_IENC2, pWL + OFF_IENC2,
        nullptr, nullptr, nullptr, nullptr, nullptr, pNDP2, nullptr, nullptr,
        512, 512, 16, DD, 512, 0, 0, 0);
    cudaEventRecord(ev1, s1);

    // ---------------- s0: omic chain + joined tail ------------------------
    cvt_splitA<<<(NN * 256 + 255) / 256, 256>>>(x, NN, OM_, OM_, 512, 512, pA1H, pA1L);
    hgemm<<<dim3(4, 128), 256, HG_SMEM>>>(pA1H, pA1L, pWH + OFF_OMIC, pWL + OFF_OMIC,
        omic_b, nullptr, nullptr, nullptr, nullptr, nullptr, pA2H, pA2L,
        512, 512, 16, OM_, 0, 512, 512, 1 | 8 | 16);

    cudaStreamWaitEvent(0, ev1, 0);
    cudaStreamWaitEvent(0, ev2, 0);
    cudaStreamWaitEvent(0, ev3, 0);

    // ienc message (folded): M = omic @ WFT + NDP2[r%1024] + ko⊗ienc_w511
    hgemm<<<dim3(4, 128), 256, HG_SMEM>>>(pA2H, pA2L, pWFH, pWFL,
        nullptr, pNDP2, pKO, ienc_W + (size_t)511 * DD,
        nullptr, pM, nullptr, nullptr,
        512, 512, 16, DD, 512, 0, 0, 4 | 32);

    // gconv(int) -> Zg split into CH cols 0..511
    gconv_gather<<<NN, 128>>>(pM, ienc_b, pOFF, pCNT, pSRT, x, pKO,
                              nullptr, pCHH, pCHL, 0);

    // combined enc: M = [Zg|pre_x] @ [Wenc;WPE]^T + pre_b@Wenc + ko⊗(preW511@Wenc)
    hgemm<<<dim3(4, 128), 256, HG_SMEM>>>(pCHH, pCHL, pWH + OFF_ENC2, pWL + OFF_ENC2,
        pB2, nullptr, pKO, pB2 + DD,
        nullptr, pM, nullptr, nullptr,
        1024, 1024, 32, DD, 512, 0, 0, 32);

    // gconv(full) -> Z2
    gconv_gather<<<NN, 128>>>(pM, enc_b, pOFF + NN, pCNT + NN, pSRT,
                              nullptr, nullptr, pZ2, nullptr, nullptr, 1);

    // readout
    gather_zk<<<(BB * KK * 128 + 255) / 256, 256>>>(pZ2, bkm, pZK, pA1H, pA1L);
    hgemm<<<dim3(4, 8), 256, HG_SMEM>>>(pA1H, pA1L, pWH + OFF_GATE, pWL + OFF_GATE,
        gate_b1, nullptr, nullptr, nullptr, nullptr, pH, nullptr, nullptr,
        512, 512, 16, DD, 512, 0, 0, 0);
    tanh_dot<<<BB * KK, 128>>>(pH, gate_W2, gate_b2, pSC);
    readout2<<<BB, 256>>>(pZK, pSC, reg_W, reg_b, out);

    // tidy up only when NOT capturing
    cudaStreamCaptureStatus cap = cudaStreamCaptureStatusNone;
    cudaStreamIsCapturing(0, &cap);
    if (cap == cudaStreamCaptureStatusNone) {
        cudaStreamDestroy(s1);
        cudaStreamDestroy(s2);
        cudaStreamDestroy(s3);
        cudaEventDestroy(evStart);
        cudaEventDestroy(evW);
        cudaEventDestroy(ev1);
        cudaEventDestroy(ev2);
        cudaEventDestroy(ev3);
    }

    (void)out_size;
    (void)n_in;
}

// round 9
// speedup vs baseline: 6.8699x; 1.0776x over previous
#include <cuda_runtime.h>
#include <cuda_bf16.h>
#include <cstdint>

#define NN      16384
#define NE_     1024
#define BB      16
#define KK      64
#define TX_     768
#define OM_     511
#define DD      512
#define SLOPE_  0.3f
#define E_INT_MAX 131072
#define E_FULL_MAX 262144

// ------------------------- helpers ------------------------------------------
__device__ __forceinline__ uint32_t smem_to_u32(const void* p) {
    uint32_t a;
    asm("{ .reg .u64 t; cvta.to.shared.u64 t, %1; cvt.u32.u64 %0, t; }"
        : "=r"(a) : "l"(p));
    return a;
}

#define CP_ASYNC16(saddr, gptr) \
    asm volatile("cp.async.cg.shared.global [%0], [%1], 16;" \
                 :: "r"(saddr), "l"(gptr) : "memory")

#define LDMX4(r0, r1, r2, r3, addr) \
    asm volatile("ldmatrix.sync.aligned.m8n8.x4.shared.b16 {%0,%1,%2,%3}, [%4];" \
                 : "=r"(r0), "=r"(r1), "=r"(r2), "=r"(r3) : "r"(addr))

#define MMA16816(c, a, b) \
    asm volatile("mma.sync.aligned.m16n8k16.row.col.f32.bf16.bf16.f32 " \
                 "{%0,%1,%2,%3},{%4,%5,%6,%7},{%8,%9},{%0,%1,%2,%3};" \
                 : "+f"((c)[0]), "+f"((c)[1]), "+f"((c)[2]), "+f"((c)[3]) \
                 : "r"((a)[0]), "r"((a)[1]), "r"((a)[2]), "r"((a)[3]), \
                   "r"((b)[0]), "r"((b)[1]))

// ------------------------- scratch (device globals) -------------------------
__device__ __nv_bfloat16 g_A1H[NN * DD];       // x split; later ZK split
__device__ __nv_bfloat16 g_A1L[NN * DD];
__device__ __nv_bfloat16 g_A2H[NN * DD];       // omic split; later Zg split
__device__ __nv_bfloat16 g_A2L[NN * DD];
__device__ __nv_bfloat16 g_CHH[NN * DD];       // pre_x split
__device__ __nv_bfloat16 g_CHL[NN * DD];
__device__ __nv_bfloat16 g_E1H[2048 * TX_];    // entity emb split (name|desc)
__device__ __nv_bfloat16 g_E1L[2048 * TX_];
__device__ __nv_bfloat16 g_E2H[NE_ * 1536];    // entity linears split
__device__ __nv_bfloat16 g_E2L[NE_ * 1536];
#define WT_TOTAL 3801088
__device__ __nv_bfloat16 g_WH[WT_TOTAL];
__device__ __nv_bfloat16 g_WL[WT_TOTAL];
__device__ __nv_bfloat16 g_WFH[DD * DD];       // WFT split (ienc fold)
__device__ __nv_bfloat16 g_WFL[DD * DD];
__device__ __nv_bfloat16 g_NDPH[NE_ * DD];     // ndpart split
__device__ __nv_bfloat16 g_NDPL[NE_ * DD];
__device__ float g_NDP2[NE_ * DD];             // ndpart @ Wienc'
__device__ float g_B2  [2 * DD];               // [pre_b@Wenc | preW511@Wenc]
__device__ float g_M   [NN * DD];              // message buffer (ienc, then enc)
__device__ float g_MP  [NN * DD];              // M_pre = pre-fold part of enc msg
__device__ float g_ZK  [NE_ * DD];
__device__ float g_H   [NE_ * DD];
__device__ float g_KO  [NN];
__device__ float g_SC  [BB * KK];
__device__ int   g_CNT[2 * NN];
__device__ int   g_OFF[2 * NN];
__device__ int   g_CUR[2 * NN];
__device__ int   g_SRT[E_INT_MAX + E_FULL_MAX];

// ============================================================================
// HMMA split-bf16 GEMM (calibrated core — unchanged)
// flags: 1 leaky, 2 accumulate (+Cin), 4 add gat[(row&1023)*512+col],
//        8 write split-bf16 (Oh/Ol stride ldo, zero-pad cols [Nc,padN)),
//        16 skip fp32 C write, 32 add koV[row]*w511[col]
// ============================================================================
__global__ void __launch_bounds__(256, 2)
hgemm(const __nv_bfloat16* __restrict__ Ah, const __nv_bfloat16* __restrict__ Al,
      const __nv_bfloat16* __restrict__ Bh, const __nv_bfloat16* __restrict__ Bl,
      const float* __restrict__ bias, const float* __restrict__ gat,
      const float* __restrict__ koV, const float* __restrict__ w511,
      const float* __restrict__ Cin, float* __restrict__ C,
      __nv_bfloat16* __restrict__ Oh, __nv_bfloat16* __restrict__ Ol,
      int lda_b, int ldb_b, int nchunks, int Nc, int ldc, int ldo,
      int padN, int flags)
{
    extern __shared__ char smem[];
    const uint32_t sb = smem_to_u32(smem);
    const int tid  = threadIdx.x;
    const int lane = tid & 31;
    const int wid  = tid >> 5;
    const int wm   = (wid >> 2) * 64;
    const int wn   = (wid & 3) * 32;
    const int bm   = blockIdx.y * 128;
    const int bn   = blockIdx.x * 128;

    float acc[4][4][4];
#pragma unroll
    for (int i = 0; i < 4; i++)
#pragma unroll
        for (int j = 0; j < 4; j++)
#pragma unroll
            for (int q = 0; q < 4; q++) acc[i][j][q] = 0.f;

    auto load_stage = [&](int st, int k0) {
        const uint32_t base = sb + st * 40960;
#pragma unroll
        for (int i = 0; i < 2; i++) {
            const int idx = tid + i * 256;
            const int row = idx >> 2;
            const int c16 = idx & 3;
            const uint32_t so = base + row * 80 + c16 * 16;
            const size_t ga = (size_t)(bm + row) * lda_b + k0 + c16 * 8;
            const size_t gb = (size_t)(bn + row) * ldb_b + k0 + c16 * 8;
            CP_ASYNC16(so,          Ah + ga);
            CP_ASYNC16(so + 10240,  Al + ga);
            CP_ASYNC16(so + 20480,  Bh + gb);
            CP_ASYNC16(so + 30720,  Bl + gb);
        }
        asm volatile("cp.async.commit_group;" ::: "memory");
    };

    auto compute = [&](int st) {
        const uint32_t base = sb + st * 40960;
        const int arow = lane & 15;
        const int asub = (lane >> 4) * 8;
        const int brow = (lane & 7) + (lane >> 4) * 8;
        const int bsub = ((lane >> 3) & 1) * 8;
#pragma unroll
        for (int ks = 0; ks < 2; ks++) {
            const int kb = ks * 16;
            const uint32_t a0 = base + ((wm + arow) * 40 + kb + asub) * 2;
            const uint32_t b0 = base + 20480 + ((wn + brow) * 40 + kb + bsub) * 2;

            uint32_t ah[4][4], bh[4][2];
#pragma unroll
            for (int mt = 0; mt < 4; mt++)
                LDMX4(ah[mt][0], ah[mt][1], ah[mt][2], ah[mt][3], a0 + mt * 16 * 80);
#pragma unroll
            for (int p = 0; p < 2; p++)
                LDMX4(bh[2*p][0], bh[2*p][1], bh[2*p+1][0], bh[2*p+1][1],
                      b0 + p * 16 * 80);
#pragma unroll
            for (int mt = 0; mt < 4; mt++)
#pragma unroll
                for (int nt = 0; nt < 4; nt++)
                    MMA16816(acc[mt][nt], ah[mt], bh[nt]);
#pragma unroll
            for (int p = 0; p < 2; p++) {
                uint32_t bl[2][2];
                LDMX4(bl[0][0], bl[0][1], bl[1][0], bl[1][1],
                      b0 + 10240 + p * 16 * 80);
#pragma unroll
                for (int mt = 0; mt < 4; mt++) {
                    MMA16816(acc[mt][2*p],   ah[mt], bl[0]);
                    MMA16816(acc[mt][2*p+1], ah[mt], bl[1]);
                }
            }
#pragma unroll
            for (int mt = 0; mt < 4; mt++) {
                uint32_t al[4];
                LDMX4(al[0], al[1], al[2], al[3], a0 + 10240 + mt * 16 * 80);
#pragma unroll
                for (int nt = 0; nt < 4; nt++)
                    MMA16816(acc[mt][nt], al, bh[nt]);
            }
        }
    };

    load_stage(0, 0);
    for (int c = 0; c < nchunks; c++) {
        if (c + 1 < nchunks) {
            load_stage((c + 1) & 1, (c + 1) * 32);
            asm volatile("cp.async.wait_group 1;" ::: "memory");
        } else {
            asm volatile("cp.async.wait_group 0;" ::: "memory");
        }
        __syncthreads();
        compute(c & 1);
        __syncthreads();
    }

    // ---- epilogue ----
    const int er = lane >> 2;
    const int ec = (lane & 3) * 2;
#pragma unroll
    for (int mt = 0; mt < 4; mt++) {
#pragma unroll
        for (int h = 0; h < 2; h++) {
            const int row = bm + wm + mt * 16 + er + h * 8;
            const size_t crow = (size_t)row * ldc;
            const size_t orow = (size_t)row * ldo;
            const size_t grow = (size_t)(row & (NE_ - 1)) * 512;
            const float kv = (flags & 32) ? koV[row] : 0.f;
#pragma unroll
            for (int nt = 0; nt < 4; nt++) {
                const int col = bn + wn + nt * 8 + ec;
                float v0 = acc[mt][nt][h * 2 + 0];
                float v1 = acc[mt][nt][h * 2 + 1];
                if (col + 1 < Nc) {
                    if (bias) {
                        float2 bb = *reinterpret_cast<const float2*>(bias + col);
                        v0 += bb.x; v1 += bb.y;
                    }
                    if (flags & 4) {
                        float2 gg = *reinterpret_cast<const float2*>(gat + grow + col);
                        v0 += gg.x; v1 += gg.y;
                    }
                    if (flags & 32) {
                        float2 ww = *reinterpret_cast<const float2*>(w511 + col);
                        v0 += kv * ww.x; v1 += kv * ww.y;
                    }
                    if (flags & 1) {
                        v0 = v0 > 0.f ? v0 : SLOPE_ * v0;
                        v1 = v1 > 0.f ? v1 : SLOPE_ * v1;
                    }
                    if (flags & 2) {
                        float2 ci = *reinterpret_cast<const float2*>(Cin + crow + col);
                        v0 += ci.x; v1 += ci.y;
                    }
                    if (!(flags & 16))
                        *reinterpret_cast<float2*>(C + crow + col) = make_float2(v0, v1);
                    if (flags & 8) {
                        __nv_bfloat16 h0 = __float2bfloat16(v0);
                        __nv_bfloat16 h1 = __float2bfloat16(v1);
                        __nv_bfloat162 hh; hh.x = h0; hh.y = h1;
                        __nv_bfloat162 ll;
                        ll.x = __float2bfloat16(v0 - __bfloat162float(h0));
                        ll.y = __float2bfloat16(v1 - __bfloat162float(h1));
                        *reinterpret_cast<__nv_bfloat162*>(Oh + orow + col) = hh;
                        *reinterpret_cast<__nv_bfloat162*>(Ol + orow + col) = ll;
                    }
                } else {
                    float vv[2] = {v0, v1};
#pragma unroll
                    for (int q = 0; q < 2; q++) {
                        const int cq = col + q;
                        if (cq < Nc) {
                            float v = vv[q];
                            if (bias)       v += bias[cq];
                            if (flags & 4)  v += gat[grow + cq];
                            if (flags & 32) v += kv * w511[cq];
                            if (flags & 1)  v = v > 0.f ? v : SLOPE_ * v;
                            if (flags & 2)  v += Cin[crow + cq];
                            if (!(flags & 16)) C[crow + cq] = v;
                            if (flags & 8) {
                                __nv_bfloat16 hh = __float2bfloat16(v);
                                Oh[orow + cq] = hh;
                                Ol[orow + cq] = __float2bfloat16(v - __bfloat162float(hh));
                            }
                        } else if ((flags & 8) && cq < padN) {
                            Oh[orow + cq] = __float2bfloat16(0.f);
                            Ol[orow + cq] = __float2bfloat16(0.f);
                        }
                    }
                }
            }
        }
    }
}

// ------------------------- conversion kernels -------------------------------
__global__ void cvt_splitA(const float* __restrict__ A, int M, int K, int lda,
                           int width, int ldrow,
                           __nv_bfloat16* __restrict__ Ah, __nv_bfloat16* __restrict__ Al)
{
    int i = blockIdx.x * blockDim.x + threadIdx.x;
    int half = width >> 1;
    int r = i / half;
    if (r >= M) return;
    int c2 = (i - r * half) * 2;
    float v0 = (c2 < K)     ? A[(size_t)r * lda + c2]     : 0.f;
    float v1 = (c2 + 1 < K) ? A[(size_t)r * lda + c2 + 1] : 0.f;
    __nv_bfloat16 h0 = __float2bfloat16(v0), h1 = __float2bfloat16(v1);
    __nv_bfloat16 l0 = __float2bfloat16(v0 - __bfloat162float(h0));
    __nv_bfloat16 l1 = __float2bfloat16(v1 - __bfloat162float(h1));
    __nv_bfloat162 hh; hh.x = h0; hh.y = h1;
    __nv_bfloat162 ll; ll.x = l0; ll.y = l1;
    *reinterpret_cast<__nv_bfloat162*>(Ah + (size_t)r * ldrow + c2) = hh;
    *reinterpret_cast<__nv_bfloat162*>(Al + (size_t)r * ldrow + c2) = ll;
}

struct WJobs {
    const float* W[9];
    long off[9];
    long cum[10];
    int K[9], N[9], ldw[9], ldo[9], trans[9];
    int njobs;
};

__global__ void cvt_splitW_all(WJobs jobs,
                               __nv_bfloat16* __restrict__ Wh,
                               __nv_bfloat16* __restrict__ Wl)
{
    long gid = (long)blockIdx.x * blockDim.x + threadIdx.x;
    if (gid >= jobs.cum[jobs.njobs]) return;
    int j = 0;
    while (gid >= jobs.cum[j + 1]) j++;
    long local = gid - jobs.cum[j];
    int ldo = jobs.ldo[j];
    int n = (int)(local / ldo);
    int k = (int)(local - (long)n * ldo);
    float v = 0.f;
    if (n < jobs.N[j] && k < jobs.K[j])
        v = jobs.trans[j] ? jobs.W[j][(size_t)k * jobs.ldw[j] + n]
                          : jobs.W[j][(size_t)n * jobs.ldw[j] + k];
    __nv_bfloat16 h = __float2bfloat16(v);
    Wh[jobs.off[j] + local] = h;
    Wl[jobs.off[j] + local] = __float2bfloat16(v - __bfloat162float(h));
}

// B2[0,:] = pre_b @ enc_W ; B2[1,:] = pre_W[511,:] @ enc_W
__global__ void fold_bias(const float* __restrict__ pre_b, const float* __restrict__ pre_W,
                          const float* __restrict__ enc_W, float* __restrict__ B2)
{
    int n = threadIdx.x;
    int which = blockIdx.x;
    const float* v = which ? (pre_W + (size_t)511 * DD) : pre_b;
    float acc = 0.f;
    for (int j = 0; j < DD; j++)
        acc = fmaf(v[j], enc_W[(size_t)j * DD + n], acc);
    B2[which * DD + n] = acc;
}

// ------------------------- misc ----------------------------------------------
__global__ void zero_f(float* __restrict__ p, int n)
{ int i = blockIdx.x * blockDim.x + threadIdx.x; if (i < n) p[i] = 0.f; }
__global__ void zero_i(int* __restrict__ p, int n)
{ int i = blockIdx.x * blockDim.x + threadIdx.x; if (i < n) p[i] = 0; }

__global__ void set_ko(const int* __restrict__ bkm, float* __restrict__ ko)
{
    int i = blockIdx.x * blockDim.x + threadIdx.x;
    if (i < BB * KK) ko[(i >> 6) * NE_ + bkm[i]] = 1.0f;
}

// ------------------------- CSR build -----------------------------------------
__global__ void csr_count2(const int* __restrict__ iei, int Ei,
                           const int* __restrict__ fei, int Ef,
                           int* __restrict__ cnt)
{
    int i = blockIdx.x * blockDim.x + threadIdx.x;
    if (i < Ei) atomicAdd(&cnt[iei[Ei + i]], 1);
    else if (i < Ei + Ef) {
        int j = i - Ei;
        atomicAdd(&cnt[NN + fei[Ef + j]], 1);
    }
}

__global__ void __launch_bounds__(1024, 1)
csr_scan2(const int* __restrict__ cnt, int* __restrict__ off,
          int* __restrict__ cur, int base1)
{
    __shared__ int sa[1024], sbuf[1024];
    const int g = blockIdx.x;
    const int* c = cnt + g * NN;
    int* o = off + g * NN;
    int* u = cur + g * NN;
    int t = threadIdx.x;
    int base = t * 16;
    int loc[16];
    int s = 0;
#pragma unroll
    for (int j = 0; j < 16; j++) { loc[j] = c[base + j]; s += loc[j]; }
    sa[t] = s;
    __syncthreads();
    int* A = sa; int* Bf = sbuf;
    for (int d = 1; d < 1024; d <<= 1) {
        int v = A[t] + (t >= d ? A[t - d] : 0);
        __syncthreads();
        Bf[t] = v;
        __syncthreads();
        int* tmp = A; A = Bf; Bf = tmp;
    }
    int run = (t ? A[t - 1] : 0) + (g ? base1 : 0);
#pragma unroll
    for (int j = 0; j < 16; j++) { o[base + j] = run; u[base + j] = run; run += loc[j]; }
}

__global__ void csr_fill2(const int* __restrict__ iei, int Ei,
                          const int* __restrict__ fei, int Ef,
                          int* __restrict__ cur, int* __restrict__ srt)
{
    int i = blockIdx.x * blockDim.x + threadIdx.x;
    if (i < Ei) {
        int p = atomicAdd(&cur[iei[Ei + i]], 1);
        srt[p] = iei[i];
    } else if (i < Ei + Ef) {
        int j = i - Ei;
        int p = atomicAdd(&cur[NN + fei[Ef + j]], 1);
        srt[p] = fei[j];
    }
}

// gconv(int): Zg = leaky(M[r]+b+sum) + x_c ; emit split bf16 (ld 512)
__global__ void __launch_bounds__(128, 8)
gconv_int(const float* __restrict__ m, const float* __restrict__ bias,
          const int* __restrict__ off, const int* __restrict__ cnt,
          const int* __restrict__ srt,
          const float* __restrict__ x, const float* __restrict__ ko,
          __nv_bfloat16* __restrict__ Oh, __nv_bfloat16* __restrict__ Ol)
{
    const int r = blockIdx.x;
    const int t = threadIdx.x;
    float4 acc = reinterpret_cast<const float4*>(m + (size_t)r * DD)[t];
    float4 b   = reinterpret_cast<const float4*>(bias)[t];
    acc.x += b.x; acc.y += b.y; acc.z += b.z; acc.w += b.w;
    const int s0 = off[r];
    const int d  = cnt[r];
    for (int e = 0; e < d; e++) {
        int s = srt[s0 + e];
        float4 v = reinterpret_cast<const float4*>(m + (size_t)s * DD)[t];
        acc.x += v.x; acc.y += v.y; acc.z += v.z; acc.w += v.w;
    }
    acc.x = acc.x > 0.f ? acc.x : SLOPE_ * acc.x;
    acc.y = acc.y > 0.f ? acc.y : SLOPE_ * acc.y;
    acc.z = acc.z > 0.f ? acc.z : SLOPE_ * acc.z;
    acc.w = acc.w > 0.f ? acc.w : SLOPE_ * acc.w;
    const int c0 = t * 4;
    float vv[4] = {acc.x, acc.y, acc.z, acc.w};
#pragma unroll
    for (int q = 0; q < 4; q++) {
        int c = c0 + q;
        vv[q] += (c < OM_) ? x[(size_t)r * OM_ + c] : ko[r];
    }
    __nv_bfloat16 h[4], l[4];
#pragma unroll
    for (int q = 0; q < 4; q++) {
        h[q] = __float2bfloat16(vv[q]);
        l[q] = __float2bfloat16(vv[q] - __bfloat162float(h[q]));
    }
    size_t o = (size_t)r * DD + c0;
    __nv_bfloat162 h01; h01.x = h[0]; h01.y = h[1];
    __nv_bfloat162 h23; h23.x = h[2]; h23.y = h[3];
    __nv_bfloat162 l01; l01.x = l[0]; l01.y = l[1];
    __nv_bfloat162 l23; l23.x = l[2]; l23.y = l[3];
    *reinterpret_cast<__nv_bfloat162*>(Oh + o)     = h01;
    *reinterpret_cast<__nv_bfloat162*>(Oh + o + 2) = h23;
    *reinterpret_cast<__nv_bfloat162*>(Ol + o)     = l01;
    *reinterpret_cast<__nv_bfloat162*>(Ol + o + 2) = l23;
}

// gconv(full) ONLY at the 1024 gathered KO rows; fused with gather_zk:
// ZK[i] fp32 + split bf16 emit for the gate GEMM.
__global__ void __launch_bounds__(128, 8)
gconv_rows(const float* __restrict__ m, const float* __restrict__ bias,
           const int* __restrict__ off, const int* __restrict__ cnt,
           const int* __restrict__ srt, const int* __restrict__ bkm,
           float* __restrict__ ZK,
           __nv_bfloat16* __restrict__ Ah, __nv_bfloat16* __restrict__ Al)
{
    const int i = blockIdx.x;              // 0..1023
    const int t = threadIdx.x;
    const int r = bkm[i] + (i >> 6) * NE_;
    float4 acc = reinterpret_cast<const float4*>(m + (size_t)r * DD)[t];
    float4 b   = reinterpret_cast<const float4*>(bias)[t];
    acc.x += b.x; acc.y += b.y; acc.z += b.z; acc.w += b.w;
    const int s0 = off[r];
    const int d  = cnt[r];
    for (int e = 0; e < d; e++) {
        int s = srt[s0 + e];
        float4 v = reinterpret_cast<const float4*>(m + (size_t)s * DD)[t];
        acc.x += v.x; acc.y += v.y; acc.z += v.z; acc.w += v.w;
    }
    acc.x = acc.x > 0.f ? acc.x : SLOPE_ * acc.x;
    acc.y = acc.y > 0.f ? acc.y : SLOPE_ * acc.y;
    acc.z = acc.z > 0.f ? acc.z : SLOPE_ * acc.z;
    acc.w = acc.w > 0.f ? acc.w : SLOPE_ * acc.w;
    reinterpret_cast<float4*>(ZK + (size_t)i * DD)[t] = acc;
    float vv[4] = {acc.x, acc.y, acc.z, acc.w};
    __nv_bfloat16 h[4], l[4];
#pragma unroll
    for (int q = 0; q < 4; q++) {
        h[q] = __float2bfloat16(vv[q]);
        l[q] = __float2bfloat16(vv[q] - __bfloat162float(h[q]));
    }
    size_t o = (size_t)i * DD + t * 4;
    __nv_bfloat162 h01; h01.x = h[0]; h01.y = h[1];
    __nv_bfloat162 h23; h23.x = h[2]; h23.y = h[3];
    __nv_bfloat162 l01; l01.x = l[0]; l01.y = l[1];
    __nv_bfloat162 l23; l23.x = l[2]; l23.y = l[3];
    *reinterpret_cast<__nv_bfloat162*>(Ah + o)     = h01;
    *reinterpret_cast<__nv_bfloat162*>(Ah + o + 2) = h23;
    *reinterpret_cast<__nv_bfloat162*>(Al + o)     = l01;
    *reinterpret_cast<__nv_bfloat162*>(Al + o + 2) = l23;
}

// ------------------------- readout -------------------------------------------
__global__ void tanh_dot(const float* __restrict__ H, const float* __restrict__ W2,
                         const float* __restrict__ b2, float* __restrict__ sc)
{
    int row = blockIdx.x;
    int tid = threadIdx.x;
    __shared__ float red[128];
    float p = 0.f;
    for (int j = tid; j < DD; j += 128)
        p = fmaf(tanhf(H[(size_t)row * DD + j]), W2[j], p);
    red[tid] = p;
    __syncthreads();
    for (int s = 64; s > 0; s >>= 1) {
        if (tid < s) red[tid] += red[tid + s];
        __syncthreads();
    }
    if (tid == 0) sc[row] = red[0] + b2[0];
}

__global__ void readout2(const float* __restrict__ ZK, const float* __restrict__ sc,
                         const float* __restrict__ regW, const float* __restrict__ regb,
                         float* __restrict__ out)
{
    int b = blockIdx.x;
    int tid = threadIdx.x;
    __shared__ float w[KK];
    __shared__ float red[256];
    __shared__ float sm;
    if (tid < KK) w[tid] = sc[b * KK + tid];
    __syncthreads();
    if (tid == 0) {
        float m = w[0];
        for (int k = 1; k < KK; k++) m = fmaxf(m, w[k]);
        float s = 0.f;
        for (int k = 0; k < KK; k++) { w[k] = expf(w[k] - m); s += w[k]; }
        sm = s;
    }
    __syncthreads();
    int c0 = tid, c1 = tid + 256;
    float r0 = 0.f, r1 = 0.f;
    for (int k = 0; k < KK; k++) {
        const float* z = ZK + ((size_t)b * KK + k) * DD;
        float wk = w[k];
        r0 = fmaf(wk, z[c0], r0);
        r1 = fmaf(wk, z[c1], r1);
    }
    float part = (r0 * regW[c0] + r1 * regW[c1]) / sm;
    red[tid] = part;
    __syncthreads();
    for (int s = 128; s > 0; s >>= 1) {
        if (tid < s) red[tid] += red[tid + s];
        __syncthreads();
    }
    if (tid == 0) out[b] = red[0] + regb[0];
}

// ------------------------- host side ------------------------------------------
static const int HG_SMEM = 2 * 40960;

extern "C" void kernel_launch(void* const* d_in, const int* in_sizes, int n_in,
                              void* d_out, int out_size)
{
    int map_[31];
    {
        int p = 0;
        for (int l = 0; l < 31; l++) {
            if (l == 5 || l == 8) {
                bool present = (n_in == 31);
                if (present && p < n_in && in_sizes[p] == 1) map_[l] = p++;
                else map_[l] = -1;
            } else map_[l] = p++;
        }
    }
    auto F = [&](int l) -> const float* { return (const float*)d_in[map_[l]]; };
    auto I = [&](int l) -> const int*   { return (const int*)d_in[map_[l]]; };

    const float* x        = F(0);
    const float* pre_x    = F(1);
    const int*   edge_ei  = I(2);
    const int*   int_ei   = I(3);
    const float* name_emb = F(6);
    const float* desc_emb = F(7);
    const int*   bkm      = I(9);
    const float* name_W = F(11), *name_b = F(12);
    const float* desc_W = F(13), *desc_b = F(14);
    const float* omic_W = F(15), *omic_b = F(16);
    const float* fus_W  = F(17), *fus_b  = F(18);
    const float* pre_W  = F(19), *pre_b  = F(20);
    const float* ienc_W = F(21), *ienc_b = F(22);
    const float* enc_W  = F(23), *enc_b  = F(24);
    const float* gate_W1 = F(25), *gate_b1 = F(26);
    const float* gate_W2 = F(27), *gate_b2 = F(28);
    const float* reg_W   = F(29), *reg_b   = F(30);
    float* out = (float*)d_out;

    const int E_full = in_sizes[map_[2]] / 2;
    const int E_int  = in_sizes[map_[3]] / 2;
    const float* W2 = fus_W + (size_t)1536 * OM_;

    __nv_bfloat16 *pA1H, *pA1L, *pA2H, *pA2L, *pCHH, *pCHL, *pE1H, *pE1L, *pE2H, *pE2L;
    __nv_bfloat16 *pWH, *pWL, *pWFH, *pWFL, *pNDPH, *pNDPL;
    float *pNDP2, *pB2, *pM, *pMP, *pZK, *pH, *pKO, *pSC;
    int *pCNT, *pOFF, *pCUR, *pSRT;
    cudaGetSymbolAddress((void**)&pA1H, g_A1H);
    cudaGetSymbolAddress((void**)&pA1L, g_A1L);
    cudaGetSymbolAddress((void**)&pA2H, g_A2H);
    cudaGetSymbolAddress((void**)&pA2L, g_A2L);
    cudaGetSymbolAddress((void**)&pCHH, g_CHH);
    cudaGetSymbolAddress((void**)&pCHL, g_CHL);
    cudaGetSymbolAddress((void**)&pE1H, g_E1H);
    cudaGetSymbolAddress((void**)&pE1L, g_E1L);
    cudaGetSymbolAddress((void**)&pE2H, g_E2H);
    cudaGetSymbolAddress((void**)&pE2L, g_E2L);
    cudaGetSymbolAddress((void**)&pWH,  g_WH);
    cudaGetSymbolAddress((void**)&pWL,  g_WL);
    cudaGetSymbolAddress((void**)&pWFH, g_WFH);
    cudaGetSymbolAddress((void**)&pWFL, g_WFL);
    cudaGetSymbolAddress((void**)&pNDPH, g_NDPH);
    cudaGetSymbolAddress((void**)&pNDPL, g_NDPL);
    cudaGetSymbolAddress((void**)&pNDP2, g_NDP2);
    cudaGetSymbolAddress((void**)&pB2,  g_B2);
    cudaGetSymbolAddress((void**)&pM,   g_M);
    cudaGetSymbolAddress((void**)&pMP,  g_MP);
    cudaGetSymbolAddress((void**)&pZK,  g_ZK);
    cudaGetSymbolAddress((void**)&pH,   g_H);
    cudaGetSymbolAddress((void**)&pKO,  g_KO);
    cudaGetSymbolAddress((void**)&pSC,  g_SC);
    cudaGetSymbolAddress((void**)&pCNT, g_CNT);
    cudaGetSymbolAddress((void**)&pOFF, g_OFF);
    cudaGetSymbolAddress((void**)&pCUR, g_CUR);
    cudaGetSymbolAddress((void**)&pSRT, g_SRT);

    cudaFuncSetAttribute(hgemm, cudaFuncAttributeMaxDynamicSharedMemorySize, HG_SMEM);

    const long OFF_NAME  = 0;        // 768x768  (name^T)
    const long OFF_DESC  = 589824;   // 768x768  (desc^T)
    const long OFF_FUS1  = 1179648;  // 512x1536 (fus[0:1536]^T)
    const long OFF_OMIC  = 1966080;  // 512x512  (omic^T)
    const long OFF_IENC2 = 2228224;  // 512x512  (ienc'^T)
    const long OFF_W2D   = 2490368;  // 512x512  (fus2 direct)
    const long OFF_PRED  = 2752512;  // 512x512  (pre_W direct)
    const long OFF_ENC2  = 3014656;  // 512x1024 ([enc^T | WPE^T])
    const long OFF_GATE  = 3538944;  // 512x512  (gate1^T)

    cudaStream_t s1, s2, s3;
    cudaStreamCreateWithFlags(&s1, cudaStreamNonBlocking);
    cudaStreamCreateWithFlags(&s2, cudaStreamNonBlocking);
    cudaStreamCreateWithFlags(&s3, cudaStreamNonBlocking);
    cudaEvent_t evStart, evW, evX, evKO, ev1, ev2, ev3;
    cudaEventCreateWithFlags(&evStart, cudaEventDisableTiming);
    cudaEventCreateWithFlags(&evW,     cudaEventDisableTiming);
    cudaEventCreateWithFlags(&evX,     cudaEventDisableTiming);
    cudaEventCreateWithFlags(&evKO,    cudaEventDisableTiming);
    cudaEventCreateWithFlags(&ev1,     cudaEventDisableTiming);
    cudaEventCreateWithFlags(&ev2,     cudaEventDisableTiming);
    cudaEventCreateWithFlags(&ev3,     cudaEventDisableTiming);

    cudaEventRecord(evStart, 0);
    cudaStreamWaitEvent(s1, evStart, 0);
    cudaStreamWaitEvent(s2, evStart, 0);

    // ---------------- s2: x split | KO | CSR | pre split | M_pre -----------
    cvt_splitA<<<(NN * 256 + 255) / 256, 256, 0, s2>>>(x, NN, OM_, OM_, 512, 512, pA1H, pA1L);
    cudaEventRecord(evX, s2);
    zero_f<<<(NN + 255) / 256, 256, 0, s2>>>(pKO, NN);
    set_ko<<<(BB * KK + 255) / 256, 256, 0, s2>>>(bkm, pKO);
    zero_i<<<(2 * NN + 255) / 256, 256, 0, s2>>>(pCNT, 2 * NN);
    csr_count2<<<(E_int + E_full + 255) / 256, 256, 0, s2>>>(int_ei, E_int, edge_ei, E_full, pCNT);
    csr_scan2<<<2, 1024, 0, s2>>>(pCNT, pOFF, pCUR, E_int);
    csr_fill2<<<(E_int + E_full + 255) / 256, 256, 0, s2>>>(int_ei, E_int, edge_ei, E_full, pCUR, pSRT);
    cudaEventRecord(evKO, s2);
    cvt_splitA<<<(NN * 256 + 255) / 256, 256, 0, s2>>>(pre_x, NN, OM_, OM_, 512, 512, pCHH, pCHL);

    // ---------------- s1: entity emb conversions (no weight dep) ----------
    cvt_splitA<<<(NE_ * 384 + 255) / 256, 256, 0, s1>>>(name_emb, NE_, TX_, TX_, TX_, TX_, pE1H, pE1L);
    cvt_splitA<<<(NE_ * 384 + 255) / 256, 256, 0, s1>>>(desc_emb, NE_, TX_, TX_, TX_, TX_,
                                                        pE1H + (size_t)NE_ * TX_,
                                                        pE1L + (size_t)NE_ * TX_);

    // ---------------- s0: weight conversion -------------------------------
    {
        WJobs jb;
        const float* Ws[9] = {name_W, desc_W, fus_W, omic_W, ienc_W, W2, pre_W, enc_W, gate_W1};
        int Ks[9]  = {TX_, TX_, 1536, OM_, OM_, OM_, DD, DD, DD};
        int Ns[9]  = {TX_, TX_, OM_, OM_, DD, OM_, DD, DD, DD};
        int ldw[9] = {TX_, TX_, OM_, OM_, DD, OM_, DD, DD, DD};
        int ldo[9] = {TX_, TX_, 1536, 512, 512, 512, 512, 1024, 512};
        int Np[9]  = {TX_, TX_, 512, 512, 512, 512, 512, 512, 512};
        int tr[9]  = {1, 1, 1, 1, 1, 0, 0, 1, 1};
        long offs[9] = {OFF_NAME, OFF_DESC, OFF_FUS1, OFF_OMIC, OFF_IENC2,
                        OFF_W2D, OFF_PRED, OFF_ENC2, OFF_GATE};
        long cum = 0;
        jb.njobs = 9;
        for (int j = 0; j < 9; j++) {
            jb.W[j] = Ws[j]; jb.K[j] = Ks[j]; jb.N[j] = Ns[j];
            jb.ldw[j] = ldw[j]; jb.ldo[j] = ldo[j]; jb.trans[j] = tr[j];
            jb.off[j] = offs[j];
            jb.cum[j] = cum; cum += (long)Np[j] * ldo[j];
        }
        jb.cum[9] = cum;
        cvt_splitW_all<<<(int)((cum + 255) / 256), 256>>>(jb, pWH, pWL);
    }
    cudaEventRecord(evW, 0);

    // ---------------- s3: WFT + WPE + fold_bias ----------------------------
    cudaStreamWaitEvent(s3, evW, 0);
    fold_bias<<<2, DD, 0, s3>>>(pre_b, pre_W, enc_W, pB2);
    hgemm<<<dim3(4, 4), 256, HG_SMEM, s3>>>(pWH + OFF_IENC2, pWL + OFF_IENC2,
        pWH + OFF_W2D, pWL + OFF_W2D,
        nullptr, nullptr, nullptr, nullptr, nullptr, nullptr, pWFH, pWFL,
        512, 512, 16, OM_, 0, 512, 512, 8 | 16);
    hgemm<<<dim3(4, 4), 256, HG_SMEM, s3>>>(pWH + OFF_ENC2, pWL + OFF_ENC2,
        pWH + OFF_PRED, pWL + OFF_PRED,
        nullptr, nullptr, nullptr, nullptr, nullptr, nullptr,
        pWH + OFF_ENC2 + 512, pWL + OFF_ENC2 + 512,
        1024, 512, 16, 512, 0, 1024, 512, 8 | 16);
    cudaEventRecord(ev3, s3);

    // ---------------- s2 (cont.): M_pre = pre_x@WPE + folds ----------------
    cudaStreamWaitEvent(s2, ev3, 0);
    hgemm<<<dim3(4, 128), 256, HG_SMEM, s2>>>(pCHH, pCHL,
        pWH + OFF_ENC2 + 512, pWL + OFF_ENC2 + 512,
        pB2, nullptr, pKO, pB2 + DD,
        nullptr, pMP, nullptr, nullptr,
        512, 1024, 16, DD, 512, 0, 0, 32);
    cudaEventRecord(ev2, s2);

    // ---------------- s1 (cont.): entity GEMM chain ------------------------
    cudaStreamWaitEvent(s1, evW, 0);
    hgemm<<<dim3(6, 8), 256, HG_SMEM, s1>>>(pE1H, pE1L, pWH + OFF_NAME, pWL + OFF_NAME,
        name_b, nullptr, nullptr, nullptr, nullptr, nullptr, pE2H, pE2L,
        TX_, TX_, 24, TX_, 0, 1536, TX_, 1 | 8 | 16);
    hgemm<<<dim3(6, 8), 256, HG_SMEM, s1>>>(pE1H + (size_t)NE_ * TX_, pE1L + (size_t)NE_ * TX_,
        pWH + OFF_DESC, pWL + OFF_DESC,
        desc_b, nullptr, nullptr, nullptr, nullptr, nullptr, pE2H + TX_, pE2L + TX_,
        TX_, TX_, 24, TX_, 0, 1536, TX_, 1 | 8 | 16);
    hgemm<<<dim3(4, 8), 256, HG_SMEM, s1>>>(pE2H, pE2L, pWH + OFF_FUS1, pWL + OFF_FUS1,
        fus_b, nullptr, nullptr, nullptr, nullptr, nullptr, pNDPH, pNDPL,
        1536, 1536, 48, OM_, 0, 512, 512, 8 | 16);
    hgemm<<<dim3(4, 8), 256, HG_SMEM, s1>>>(pNDPH, pNDPL, pWH + OFF_IENC2, pWL + OFF_IENC2,
        nullptr, nullptr, nullptr, nullptr, nullptr, pNDP2, nullptr, nullptr,
        512, 512, 16, DD, 512, 0, 0, 0);
    cudaEventRecord(ev1, s1);

    // ---------------- s0: omic + joined tail -------------------------------
    cudaStreamWaitEvent(0, evX, 0);
    hgemm<<<dim3(4, 128), 256, HG_SMEM>>>(pA1H, pA1L, pWH + OFF_OMIC, pWL + OFF_OMIC,
        omic_b, nullptr, nullptr, nullptr, nullptr, nullptr, pA2H, pA2L,
        512, 512, 16, OM_, 0, 512, 512, 1 | 8 | 16);

    cudaStreamWaitEvent(0, ev1, 0);
    cudaStreamWaitEvent(0, ev3, 0);
    cudaStreamWaitEvent(0, evKO, 0);

    // ienc message (folded): M = omic @ WFT + NDP2[r%1024] + ko⊗ienc_w511
    hgemm<<<dim3(4, 128), 256, HG_SMEM>>>(pA2H, pA2L, pWFH, pWFL,
        nullptr, pNDP2, pKO, ienc_W + (size_t)511 * DD,
        nullptr, pM, nullptr, nullptr,
        512, 512, 16, DD, 512, 0, 0, 4 | 32);

    // gconv(int) -> Zg split into A2
    gconv_int<<<NN, 128>>>(pM, ienc_b, pOFF, pCNT, pSRT, x, pKO, pA2H, pA2L);

    // enc msg: M = Zg @ Wenc + M_pre (K=512; pre half precomputed)
    cudaStreamWaitEvent(0, ev2, 0);
    hgemm<<<dim3(4, 128), 256, HG_SMEM>>>(pA2H, pA2L, pWH + OFF_ENC2, pWL + OFF_ENC2,
        nullptr, nullptr, nullptr, nullptr,
        pMP, pM, nullptr, nullptr,
        512, 1024, 16, DD, 512, 0, 0, 2);

    // gconv(full) at 1024 gathered rows only -> ZK fp32 + split for gate GEMM
    gconv_rows<<<BB * KK, 128>>>(pM, enc_b, pOFF + NN, pCNT + NN, pSRT, bkm,
                                 pZK, pA1H, pA1L);

    // gate GEMM + gated readout
    hgemm<<<dim3(4, 8), 256, HG_SMEM>>>(pA1H, pA1L, pWH + OFF_GATE, pWL + OFF_GATE,
        gate_b1, nullptr, nullptr, nullptr, nullptr, pH, nullptr, nullptr,
        512, 512, 16, DD, 512, 0, 0, 0);
    tanh_dot<<<BB * KK, 128>>>(pH, gate_W2, gate_b2, pSC);
    readout2<<<BB, 256>>>(pZK, pSC, reg_W, reg_b, out);

    cudaStreamCaptureStatus cap = cudaStreamCaptureStatusNone;
    cudaStreamIsCapturing(0, &cap);
    if (cap == cudaStreamCaptureStatusNone) {
        cudaStreamDestroy(s1);
        cudaStreamDestroy(s2);
        cudaStreamDestroy(s3);
        cudaEventDestroy(evStart);
        cudaEventDestroy(evW);
        cudaEventDestroy(evX);
        cudaEventDestroy(evKO);
        cudaEventDestroy(ev1);
        cudaEventDestroy(ev2);
        cudaEventDestroy(ev3);
    }

    (void)out_size;
    (void)n_in;
}